// round 6
// baseline (speedup 1.0000x reference)
#include <cuda_runtime.h>
#include <math.h>
#include <stdint.h>

// ---------------- problem constants ----------------
#define BB   4
#define TT   512
#define VV   576
#define LL   256
#define HH   1024
#define NHH  16
#define HDD  64
#define II   4096
#define EE   8
#define KSEL_T 80
#define KSEL_V 90
#define SELCAP 96
#define LN_EPS 1e-5f

#define BM 128
#define BKW 32          // K per tile (floats)

// ---------------- scratch ----------------
__device__ float g_ln   [BB*TT*HH];
__device__ float g_q    [BB*TT*HH];
__device__ float g_cq   [BB*TT*HH];
__device__ float g_qkv  [BB*TT*3*HH];
__device__ float g_kv   [BB*VV*2*HH];
__device__ float g_scores[BB*NHH*TT*VV];
__device__ float g_attn [BB*TT*HH];
__device__ float g_vt   [BB*NHH*HDD*VV];
__device__ float g_ht   [BB*EE*SELCAP*II];
__device__ float g_hi   [BB*EE*SELCAP*II];
__device__ float g_acc_t[BB*TT*HH];
__device__ float g_acc_i[BB*VV*HH];
__device__ float g_ctx_img[BB*HH];
__device__ float g_ctx_txt[BB*HH];
__device__ float g_gb_img[BB*EE];
__device__ float g_gb_txt[BB*EE];
__device__ float g_probs_t[BB*TT*EE];
__device__ float g_probs_i[BB*VV*EE];
__device__ int   g_sel_t[BB*EE*SELCAP];
__device__ int   g_sel_i[BB*EE*SELCAP];
__device__ int   g_cnt_t[BB*TT];
__device__ int   g_cnt_i[BB*VV];

// ---------------- helpers ----------------
__device__ __forceinline__ float gelu_f(float x) {
    float x3 = x * x * x;
    return 0.5f * x * (1.0f + tanhf(0.7978845608028654f * (x + 0.044715f * x3)));
}
__device__ __forceinline__ uint32_t f2tf32(float v) {
    uint32_t r;
    asm("cvt.rna.tf32.f32 %0, %1;" : "=r"(r) : "f"(v));
    return r;
}
__device__ __forceinline__ float roundtf(float v) {
    return __uint_as_float(f2tf32(v));
}
__device__ __forceinline__ void mma_tf32(float c[4],
    uint32_t a0, uint32_t a1, uint32_t a2, uint32_t a3,
    uint32_t b0, uint32_t b1)
{
    asm volatile(
        "mma.sync.aligned.m16n8k8.row.col.f32.tf32.tf32.f32 "
        "{%0,%1,%2,%3}, {%4,%5,%6,%7}, {%8,%9}, {%0,%1,%2,%3};"
        : "+f"(c[0]), "+f"(c[1]), "+f"(c[2]), "+f"(c[3])
        : "r"(a0), "r"(a1), "r"(a2), "r"(a3), "r"(b0), "r"(b1));
}
__device__ __forceinline__ void cpa16(float* dst, const float* src, bool valid) {
    uint32_t d = (uint32_t)__cvta_generic_to_shared(dst);
    asm volatile("cp.async.cg.shared.global [%0], [%1], 16, %2;"
                 :: "r"(d), "l"(src), "r"(valid ? 16 : 0));
}

// ---------------- tile loader ----------------
template<int BN>
__device__ __forceinline__ void load_tile(
    float* Asd, float* Bsd,
    const float* __restrict__ A, int lda, const int* rowA,
    const float* __restrict__ Bp, int ldb, const int* rowB,
    int k0, int sr, int kc)
{
#pragma unroll
    for (int p = 0; p < 4; p++)
        cpa16(Asd + (sr + p * 32) * 36 + kc,
              A + (size_t)(rowA[p] < 0 ? 0 : rowA[p]) * lda + k0 + kc,
              rowA[p] >= 0);
#pragma unroll
    for (int p = 0; p < BN / 32; p++)
        cpa16(Bsd + (sr + p * 32) * 36 + kc,
              Bp + (size_t)(rowB[p] < 0 ? 0 : rowB[p]) * ldb + k0 + kc,
              rowB[p] >= 0);
}

// ---------------- fragment loader (smem -> regs) ----------------
template<int NJ>
__device__ __forceinline__ void load_frags(
    const float* __restrict__ Ab, const float* __restrict__ Bb,
    int wm, int wn, int lane, int ks,
    uint32_t a[2][4], uint32_t b[][2])
{
    const int cc = ks * 8 + (lane & 3);
#pragma unroll
    for (int i = 0; i < 2; i++) {
        const int r = wm + i * 16 + (lane >> 2);
        a[i][0] = __float_as_uint(Ab[r * 36 + cc]);
        a[i][1] = __float_as_uint(Ab[(r + 8) * 36 + cc]);
        a[i][2] = __float_as_uint(Ab[r * 36 + cc + 4]);
        a[i][3] = __float_as_uint(Ab[(r + 8) * 36 + cc + 4]);
    }
#pragma unroll
    for (int j = 0; j < NJ; j++) {
        const int bc = wn + j * 8 + (lane >> 2);
        b[j][0] = __float_as_uint(Bb[bc * 36 + cc]);
        b[j][1] = __float_as_uint(Bb[bc * 36 + cc + 4]);
    }
}

// ---------------- tensor-core GEMM: C = alpha*A@B^T + eps -------------------
// A [M,K] row-major (optional row gather), B [N,K] row-major.
// 3-stage cp.async ring + frag double-buffering, 128xBN x32 tiles, 256 thr.
template<int BN, bool GELU_E, bool ATOMIC, bool ROUND>
__device__ __forceinline__ void mma_gemm(
    float* smem,
    const float* __restrict__ A, int lda, const int* __restrict__ arow,
    const float* __restrict__ Bp, int ldb,
    const float* __restrict__ bias, const float* __restrict__ res,
    float* __restrict__ C, int ldc, const int* __restrict__ crow,
    int M, int N, int K, float alpha)
{
    constexpr int NJ  = BN / 16;
    constexpr int STB = (BM + BN) * 36;
    float* As[3] = { smem,           smem + STB,           smem + 2 * STB };
    float* Bs[3] = { smem + BM * 36, smem + STB + BM * 36, smem + 2 * STB + BM * 36 };

    const int tid  = threadIdx.x;
    const int lane = tid & 31, warp = tid >> 5;
    const int wm = (warp & 3) * 32;
    const int wn = (warp >> 2) * (BN / 2);
    const int m0 = blockIdx.y * BM, n0 = blockIdx.x * BN;

    const int sr = tid >> 3;
    const int kc = (tid & 7) * 4;
    int rowA[4];
#pragma unroll
    for (int p = 0; p < 4; p++) {
        int gm = m0 + sr + p * 32;
        rowA[p] = (gm < M) ? (arow ? arow[gm] : gm) : -1;
    }
    int rowB[BN / 32];
#pragma unroll
    for (int p = 0; p < BN / 32; p++) {
        int gn = n0 + sr + p * 32;
        rowB[p] = (gn < N) ? gn : -1;
    }

    float c[2][NJ][4];
#pragma unroll
    for (int i = 0; i < 2; i++)
#pragma unroll
        for (int j = 0; j < NJ; j++)
#pragma unroll
            for (int q = 0; q < 4; q++) c[i][j][q] = 0.0f;

    const int KT = K / BKW;

    load_tile<BN>(As[0], Bs[0], A, lda, rowA, Bp, ldb, rowB, 0, sr, kc);
    asm volatile("cp.async.commit_group;");
    load_tile<BN>(As[1], Bs[1], A, lda, rowA, Bp, ldb, rowB, BKW, sr, kc);
    asm volatile("cp.async.commit_group;");

    for (int kt = 0; kt < KT; kt++) {
        asm volatile("cp.async.wait_group 1;");
        __syncthreads();
        const int st  = kt % 3;
        const int nst = (kt + 2) % 3;
        if (kt + 2 < KT)
            load_tile<BN>(As[nst], Bs[nst], A, lda, rowA, Bp, ldb, rowB,
                          (kt + 2) * BKW, sr, kc);
        asm volatile("cp.async.commit_group;");

        const float* Ab = As[st];
        const float* Bb = Bs[st];
        uint32_t af[2][2][4], bf[2][NJ][2];
        load_frags<NJ>(Ab, Bb, wm, wn, lane, 0, af[0], bf[0]);
#pragma unroll
        for (int ks = 0; ks < 4; ks++) {
            if (ks < 3)
                load_frags<NJ>(Ab, Bb, wm, wn, lane, ks + 1,
                               af[(ks + 1) & 1], bf[(ks + 1) & 1]);
            const int cb = ks & 1;
#pragma unroll
            for (int i = 0; i < 2; i++)
#pragma unroll
                for (int j = 0; j < NJ; j++)
                    mma_tf32(c[i][j], af[cb][i][0], af[cb][i][1],
                             af[cb][i][2], af[cb][i][3],
                             bf[cb][j][0], bf[cb][j][1]);
        }
    }

    // epilogue
#pragma unroll
    for (int i = 0; i < 2; i++) {
        int rm = m0 + wm + i * 16 + (lane >> 2);
#pragma unroll
        for (int j = 0; j < NJ; j++) {
            int cn = n0 + wn + j * 8 + 2 * (lane & 3);
#pragma unroll
            for (int rr = 0; rr < 2; rr++) {
                int gm = rm + rr * 8;
                if (gm >= M) continue;
                int orow = crow ? crow[gm] : gm;
#pragma unroll
                for (int qq = 0; qq < 2; qq++) {
                    int gn = cn + qq;
                    if (gn >= N) continue;
                    float v = c[i][j][rr * 2 + qq] * alpha;
                    if (bias) v += bias[gn];
                    if (res)  v += res[(size_t)gm * ldc + gn];
                    if (GELU_E) v = gelu_f(v);
                    if (ROUND)  v = roundtf(v);
                    if (ATOMIC) atomicAdd(&C[(size_t)orow * ldc + gn], v);
                    else        C[(size_t)orow * ldc + gn] = v;
                }
            }
        }
    }
}

// ---------------- GEMM wrappers ----------------
__global__ __launch_bounds__(256, 2) void k_gemm_r(
    const float* A, int lda, const float* W, int ldw,
    const float* bias, const float* res,
    float* C, int ldc, int M, int N, int K)
{
    extern __shared__ float sm[];
    mma_gemm<128, false, false, true>(sm, A, lda, nullptr, W, ldw, bias, res,
                                      C, ldc, nullptr, M, N, K, 1.0f);
}

__global__ __launch_bounds__(256, 2) void k_gemm_p(
    const float* A, int lda, const float* W, int ldw,
    const float* bias, const float* res,
    float* C, int ldc, int M, int N, int K)
{
    extern __shared__ float sm[];
    mma_gemm<128, false, false, false>(sm, A, lda, nullptr, W, ldw, bias, res,
                                       C, ldc, nullptr, M, N, K, 1.0f);
}

__global__ __launch_bounds__(256, 2) void k_scores(
    const float* Q, int qbs, int qld,
    const float* Kp, int kbs, int kld,
    float* S, int Tq, int Skv)
{
    extern __shared__ float sm[];
    int z = blockIdx.z; int b = z / NHH, h = z % NHH;
    mma_gemm<128, false, false, false>(sm,
        Q + (size_t)b * qbs + h * HDD, qld, nullptr,
        Kp + (size_t)b * kbs + h * HDD, kld,
        nullptr, nullptr,
        S + (size_t)z * Tq * Skv, Skv, nullptr,
        Tq, Skv, HDD, 0.125f);
}

__global__ __launch_bounds__(256, 2) void k_av(
    const float* P, const float* Vt, float* O, int Tq, int Skv)
{
    extern __shared__ float sm[];
    int z = blockIdx.z; int b = z / NHH, h = z % NHH;
    mma_gemm<64, false, false, true>(sm,
        P + (size_t)z * Tq * Skv, Skv, nullptr,
        Vt + (size_t)z * HDD * Skv, Skv,
        nullptr, nullptr,
        O + (size_t)b * Tq * HH + h * HDD, HH, nullptr,
        Tq, HDD, Skv, 1.0f);
}

// merged MoE up-projection: z<32 text, z>=32 image
__global__ __launch_bounds__(256, 2) void k_moe1_all(
    const float* Xt, const float* Xi,
    const float* w1, const float* b1,
    const int* selt, const int* seli,
    float* Ht, float* Hi)
{
    extern __shared__ float sm[];
    int z = blockIdx.z;
    bool txt = z < BB * EE;
    int g = txt ? z : z - BB * EE;
    int b = g / EE, e = g % EE;
    const float* X = txt ? Xt + (size_t)b * TT * HH : Xi + (size_t)b * VV * HH;
    const int* sel = (txt ? selt : seli) + g * SELCAP;
    float* H = (txt ? Ht : Hi) + (size_t)g * SELCAP * II;
    int ksel = txt ? KSEL_T : KSEL_V;
    mma_gemm<128, true, false, true>(sm, X, HH, sel,
        w1 + (size_t)e * II * HH, HH, b1 + (size_t)e * II, nullptr,
        H, II, nullptr, ksel, II, HH, 1.0f);
}

// merged MoE down-projection + scatter
__global__ __launch_bounds__(256, 2) void k_moe2_all(
    const float* Ht, const float* Hi,
    const float* w2, const float* b2,
    const int* selt, const int* seli,
    float* AccT, float* AccI)
{
    extern __shared__ float sm[];
    int z = blockIdx.z;
    bool txt = z < BB * EE;
    int g = txt ? z : z - BB * EE;
    int b = g / EE, e = g % EE;
    const float* H = (txt ? Ht : Hi) + (size_t)g * SELCAP * II;
    const int* sel = (txt ? selt : seli) + g * SELCAP;
    float* Acc = txt ? AccT + (size_t)b * TT * HH : AccI + (size_t)b * VV * HH;
    int ksel = txt ? KSEL_T : KSEL_V;
    mma_gemm<128, false, true, false>(sm, H, II, nullptr,
        w2 + (size_t)e * HH * II, II, b2 + (size_t)e * HH, nullptr,
        Acc, HH, sel, ksel, HH, II, 1.0f);
}

// ---------------- V transpose ----------------
__global__ void k_transp(const float* __restrict__ X, int ldx,
                         float* __restrict__ Y, int S)
{
    __shared__ float t[32][33];
    int z = blockIdx.z; int b = z >> 4, h = z & 15;
    int t0 = blockIdx.x * 32, d0 = blockIdx.y * 32;
    const float* src = X + ((size_t)b * S) * ldx + h * HDD;
#pragma unroll
    for (int k2 = 0; k2 < 4; k2++) {
        int tt = t0 + threadIdx.y + k2 * 8;
        t[threadIdx.y + k2 * 8][threadIdx.x] =
            src[(size_t)tt * ldx + d0 + threadIdx.x];
    }
    __syncthreads();
    float* dst = Y + ((size_t)z * HDD) * S;
#pragma unroll
    for (int k2 = 0; k2 < 4; k2++) {
        int d = d0 + threadIdx.y + k2 * 8;
        dst[(size_t)d * S + t0 + threadIdx.x] = t[threadIdx.x][threadIdx.y + k2 * 8];
    }
}

// ---------------- layernorm (tf32-rounded; optional acc-zero fold) ----------
__global__ void k_ln(const float* X, const float* gg, const float* bb,
                     float* Y, float* accz)
{
    int r = blockIdx.x;
    const float* x = X + (size_t)r * HH;
    float* y = Y + (size_t)r * HH;
    int tid = threadIdx.x;
    if (accz) {
        float* az = accz + (size_t)r * HH;
        for (int i = tid; i < HH; i += 256) az[i] = 0.0f;
    }
    float s = 0.0f, s2 = 0.0f;
    for (int i = tid; i < HH; i += 256) { float v = x[i]; s += v; s2 += v * v; }
    __shared__ float r1[256], r2[256];
    r1[tid] = s; r2[tid] = s2; __syncthreads();
    for (int st = 128; st; st >>= 1) {
        if (tid < st) { r1[tid] += r1[tid + st]; r2[tid] += r2[tid + st]; }
        __syncthreads();
    }
    float mean = r1[0] * (1.0f / HH);
    float var  = r2[0] * (1.0f / HH) - mean * mean;
    float rstd = rsqrtf(var + LN_EPS);
    for (int i = tid; i < HH; i += 256)
        y[i] = roundtf((x[i] - mean) * rstd * gg[i] + bb[i]);
}

// ---------------- softmax: warp per row ----------------
template<int W>
__global__ __launch_bounds__(256) void k_softmax_w(float* __restrict__ S)
{
    const int row = blockIdx.x * 8 + (threadIdx.x >> 5);
    const int lane = threadIdx.x & 31;
    float* r = S + (size_t)row * W;
    constexpr int NV = W / 32;
    float v[NV];
    float m = -3.0e38f;
#pragma unroll
    for (int j = 0; j < NV; j++) { v[j] = r[lane + (j << 5)]; m = fmaxf(m, v[j]); }
#pragma unroll
    for (int o = 16; o; o >>= 1) m = fmaxf(m, __shfl_xor_sync(0xffffffffu, m, o));
    float s = 0.0f;
#pragma unroll
    for (int j = 0; j < NV; j++) { v[j] = expf(v[j] - m); s += v[j]; }
#pragma unroll
    for (int o = 16; o; o >>= 1) s += __shfl_xor_sync(0xffffffffu, s, o);
    float inv = 1.0f / s;
#pragma unroll
    for (int j = 0; j < NV; j++) r[lane + (j << 5)] = roundtf(v[j] * inv);
}

// ---------------- gating / misc ----------------
__global__ void k_mean(const float* X, float* ctx, int S)
{
    int b = blockIdx.y;
    int c = blockIdx.x * 256 + threadIdx.x;
    float s = 0.0f;
    for (int j = 0; j < S; j++) s += X[(size_t)(b * S + j) * HH + c];
    ctx[b * HH + c] = s / (float)S;
}

__global__ void k_ctxbias(const float* ctx, const float* gw, const float* gb,
                          float* outp)
{
    int g = blockIdx.x; int b = g / EE, e = g % EE;
    int tid = threadIdx.x;
    float s = 0.0f;
    for (int c = tid; c < HH; c += 256)
        s += ctx[b * HH + c] * gw[(size_t)e * 2 * HH + HH + c];
    __shared__ float red[256];
    red[tid] = s; __syncthreads();
    for (int st = 128; st; st >>= 1) {
        if (tid < st) red[tid] += red[tid + st];
        __syncthreads();
    }
    if (tid == 0) outp[g] = red[0] + gb[e];
}

__global__ void k_gate(const float* X, const float* gw, const float* cb,
                       float* probs, int S, int* cntz, float* accz)
{
    int t = blockIdx.x; int b = t / S;
    const float* x = X + (size_t)t * HH;
    int tid = threadIdx.x;
    if (tid == 0) cntz[t] = 0;
    if (accz) {
        float* az = accz + (size_t)t * HH;
        for (int i = tid; i < HH; i += 256) az[i] = 0.0f;
    }
    float part[EE];
#pragma unroll
    for (int e = 0; e < EE; e++) part[e] = 0.0f;
    for (int c = tid; c < HH; c += 256) {
        float xv = x[c];
#pragma unroll
        for (int e = 0; e < EE; e++) part[e] += xv * gw[(size_t)e * 2 * HH + c];
    }
    __shared__ float red[256];
    __shared__ float lg[EE];
    for (int e = 0; e < EE; e++) {
        red[tid] = part[e]; __syncthreads();
        for (int st = 128; st; st >>= 1) {
            if (tid < st) red[tid] += red[tid + st];
            __syncthreads();
        }
        if (tid == 0) lg[e] = red[0] + cb[b * EE + e];
        __syncthreads();
    }
    if (tid == 0) {
        float mx = lg[0];
#pragma unroll
        for (int e = 1; e < EE; e++) mx = fmaxf(mx, lg[e]);
        float sum = 0.0f, ex[EE];
#pragma unroll
        for (int e = 0; e < EE; e++) { ex[e] = expf(lg[e] - mx); sum += ex[e]; }
        float inv = 1.0f / sum;
#pragma unroll
        for (int e = 0; e < EE; e++) probs[(size_t)t * EE + e] = ex[e] * inv;
    }
}

__global__ void k_topk(const float* probs, int S, int ksel, int* sel, int* cnt)
{
    int g = blockIdx.x; int b = g / EE, e = g % EE;
    int tid = threadIdx.x;
    __shared__ float v[VV];
    __shared__ int   sels[SELCAP];
    __shared__ float bestv[256];
    __shared__ int   besti[256];
    for (int i = tid; i < S; i += 256) v[i] = probs[(size_t)(b * S + i) * EE + e];
    __syncthreads();
    for (int it = 0; it < ksel; it++) {
        float bv = -3.0e38f; int bi = S;
        for (int i = tid; i < S; i += 256) {
            float x = v[i];
            if (x > bv || (x == bv && i < bi)) { bv = x; bi = i; }
        }
        bestv[tid] = bv; besti[tid] = bi; __syncthreads();
        for (int st = 128; st; st >>= 1) {
            if (tid < st) {
                if (bestv[tid + st] > bestv[tid] ||
                    (bestv[tid + st] == bestv[tid] && besti[tid + st] < besti[tid])) {
                    bestv[tid] = bestv[tid + st];
                    besti[tid] = besti[tid + st];
                }
            }
            __syncthreads();
        }
        if (tid == 0) {
            sels[it] = besti[0];
            sel[g * SELCAP + it] = besti[0];
            v[besti[0]] = -1.0e30f;
        }
        __syncthreads();
    }
    if (tid < ksel) atomicAdd(&cnt[b * S + sels[tid]], 1);
}

__global__ void k_combine(const float* base, const float* acc, const int* cnt,
                          float* outp, int n)
{
    int i = blockIdx.x * 256 + threadIdx.x;
    if (i < n) {
        int tok = i / HH;
        outp[i] = base[i] + acc[i] / fmaxf((float)cnt[tok], 1.0f);
    }
}

// ---------------- launch ----------------
#define SMEM128 (3 * (BM + 128) * 36 * 4)
#define SMEM64  (3 * (BM + 64) * 36 * 4)

extern "C" void kernel_launch(void* const* d_in, const int* in_sizes, int n_in,
                              void* d_out, int out_size)
{
    (void)in_sizes; (void)n_in; (void)out_size;
    const float* in_q      = (const float*)d_in[0];
    const float* in_img    = (const float*)d_in[1];
    const float* in_txt    = (const float*)d_in[2];
    const float* sa_w_in   = (const float*)d_in[3];
    const float* sa_b_in   = (const float*)d_in[4];
    const float* sa_w_out  = (const float*)d_in[5];
    const float* sa_b_out  = (const float*)d_in[6];
    const float* ca_w_in   = (const float*)d_in[7];
    const float* ca_b_in   = (const float*)d_in[8];
    const float* ca_w_out  = (const float*)d_in[9];
    const float* ca_b_out  = (const float*)d_in[10];
    const float* gate_img_w= (const float*)d_in[11];
    const float* gate_img_b= (const float*)d_in[12];
    const float* gate_txt_w= (const float*)d_in[13];
    const float* gate_txt_b= (const float*)d_in[14];
    const float* e_w1      = (const float*)d_in[15];
    const float* e_b1      = (const float*)d_in[16];
    const float* e_w2      = (const float*)d_in[17];
    const float* e_b2      = (const float*)d_in[18];
    const float* lnq_g     = (const float*)d_in[19];
    const float* lnq_b     = (const float*)d_in[20];
    const float* lnc_g     = (const float*)d_in[21];
    const float* lnc_b     = (const float*)d_in[22];
    const float* lnf_g     = (const float*)d_in[23];
    const float* lnf_b     = (const float*)d_in[24];
    float* out_q   = (float*)d_out;
    float* out_img = out_q + (size_t)BB * TT * HH;

    float *p_ln, *p_q, *p_cq, *p_qkv, *p_kv, *p_scores, *p_attn, *p_vt;
    float *p_ht, *p_hi, *p_acc_t, *p_acc_i;
    float *p_ctx_img, *p_ctx_txt, *p_gb_img, *p_gb_txt, *p_probs_t, *p_probs_i;
    int *p_sel_t, *p_sel_i, *p_cnt_t, *p_cnt_i;
    cudaGetSymbolAddress((void**)&p_ln, g_ln);
    cudaGetSymbolAddress((void**)&p_q, g_q);
    cudaGetSymbolAddress((void**)&p_cq, g_cq);
    cudaGetSymbolAddress((void**)&p_qkv, g_qkv);
    cudaGetSymbolAddress((void**)&p_kv, g_kv);
    cudaGetSymbolAddress((void**)&p_scores, g_scores);
    cudaGetSymbolAddress((void**)&p_attn, g_attn);
    cudaGetSymbolAddress((void**)&p_vt, g_vt);
    cudaGetSymbolAddress((void**)&p_ht, g_ht);
    cudaGetSymbolAddress((void**)&p_hi, g_hi);
    cudaGetSymbolAddress((void**)&p_acc_t, g_acc_t);
    cudaGetSymbolAddress((void**)&p_acc_i, g_acc_i);
    cudaGetSymbolAddress((void**)&p_ctx_img, g_ctx_img);
    cudaGetSymbolAddress((void**)&p_ctx_txt, g_ctx_txt);
    cudaGetSymbolAddress((void**)&p_gb_img, g_gb_img);
    cudaGetSymbolAddress((void**)&p_gb_txt, g_gb_txt);
    cudaGetSymbolAddress((void**)&p_probs_t, g_probs_t);
    cudaGetSymbolAddress((void**)&p_probs_i, g_probs_i);
    cudaGetSymbolAddress((void**)&p_sel_t, g_sel_t);
    cudaGetSymbolAddress((void**)&p_sel_i, g_sel_i);
    cudaGetSymbolAddress((void**)&p_cnt_t, g_cnt_t);
    cudaGetSymbolAddress((void**)&p_cnt_i, g_cnt_i);

    cudaFuncSetAttribute(k_gemm_r, cudaFuncAttributeMaxDynamicSharedMemorySize, SMEM128);
    cudaFuncSetAttribute(k_gemm_p, cudaFuncAttributeMaxDynamicSharedMemorySize, SMEM128);
    cudaFuncSetAttribute(k_scores, cudaFuncAttributeMaxDynamicSharedMemorySize, SMEM128);
    cudaFuncSetAttribute(k_av,     cudaFuncAttributeMaxDynamicSharedMemorySize, SMEM64);
    cudaFuncSetAttribute(k_moe1_all, cudaFuncAttributeMaxDynamicSharedMemorySize, SMEM128);
    cudaFuncSetAttribute(k_moe2_all, cudaFuncAttributeMaxDynamicSharedMemorySize, SMEM128);

    // ---- self attention ----
    k_ln<<<BB * TT, 256>>>(in_q, lnq_g, lnq_b, p_ln, nullptr);
    k_gemm_r<<<dim3(3 * HH / 128, BB * TT / BM), 256, SMEM128>>>(
        p_ln, HH, sa_w_in, HH, sa_b_in, nullptr, p_qkv, 3 * HH,
        BB * TT, 3 * HH, HH);
    k_transp<<<dim3(TT / 32, 2, BB * NHH), dim3(32, 8)>>>(
        p_qkv + 2 * HH, 3 * HH, p_vt, TT);
    k_scores<<<dim3(TT / 128, TT / BM, BB * NHH), 256, SMEM128>>>(
        p_qkv, TT * 3 * HH, 3 * HH, p_qkv + HH, TT * 3 * HH, 3 * HH,
        p_scores, TT, TT);
    k_softmax_w<TT><<<BB * NHH * TT / 8, 256>>>(p_scores);
    k_av<<<dim3(1, TT / BM, BB * NHH), 256, SMEM64>>>(p_scores, p_vt, p_attn, TT, TT);
    k_gemm_p<<<dim3(HH / 128, BB * TT / BM), 256, SMEM128>>>(
        p_attn, HH, sa_w_out, HH, sa_b_out, in_q, p_q, HH, BB * TT, HH, HH);

    // ---- cross attention ----
    k_ln<<<BB * TT, 256>>>(p_q, lnc_g, lnc_b, p_ln, nullptr);
    k_gemm_r<<<dim3(HH / 128, BB * TT / BM), 256, SMEM128>>>(
        p_ln, HH, ca_w_in, HH, ca_b_in, nullptr, p_cq, HH, BB * TT, HH, HH);
    k_gemm_r<<<dim3(2 * HH / 128, BB * VV / BM), 256, SMEM128>>>(
        in_img, HH, ca_w_in + (size_t)HH * HH, HH, ca_b_in + HH, nullptr,
        p_kv, 2 * HH, BB * VV, 2 * HH, HH);
    k_transp<<<dim3(VV / 32, 2, BB * NHH), dim3(32, 8)>>>(
        p_kv + HH, 2 * HH, p_vt, VV);
    k_scores<<<dim3((VV + 127) / 128, TT / BM, BB * NHH), 256, SMEM128>>>(
        p_cq, TT * HH, HH, p_kv, VV * 2 * HH, 2 * HH, p_scores, TT, VV);
    k_softmax_w<VV><<<BB * NHH * TT / 8, 256>>>(p_scores);
    k_av<<<dim3(1, TT / BM, BB * NHH), 256, SMEM64>>>(p_scores, p_vt, p_attn, TT, VV);
    k_gemm_p<<<dim3(HH / 128, BB * TT / BM), 256, SMEM128>>>(
        p_attn, HH, ca_w_out, HH, ca_b_out, p_q, p_q, HH, BB * TT, HH, HH);

    // ---- gating (also zeroes counts / image acc) ----
    k_mean<<<dim3(HH / 256, BB), 256>>>(in_img, p_ctx_img, VV);
    k_mean<<<dim3(HH / 256, BB), 256>>>(in_txt, p_ctx_txt, LL);
    k_ctxbias<<<BB * EE, 256>>>(p_ctx_txt, gate_img_w, gate_img_b, p_gb_img);
    k_ctxbias<<<BB * EE, 256>>>(p_ctx_img, gate_txt_w, gate_txt_b, p_gb_txt);
    k_gate<<<BB * VV, 256>>>(in_img, gate_img_w, p_gb_img, p_probs_i, VV,
                             p_cnt_i, p_acc_i);
    k_gate<<<BB * TT, 256>>>(p_q, gate_txt_w, p_gb_txt, p_probs_t, TT,
                             p_cnt_t, nullptr);
    k_topk<<<BB * EE, 256>>>(p_probs_t, TT, KSEL_T, p_sel_t, p_cnt_t);
    k_topk<<<BB * EE, 256>>>(p_probs_i, VV, KSEL_V, p_sel_i, p_cnt_i);

    // ---- MoE (merged text+image), ln also zeroes text acc ----
    k_ln<<<BB * TT, 256>>>(p_q, lnf_g, lnf_b, p_ln, p_acc_t);
    k_moe1_all<<<dim3(II / 128, 1, 2 * BB * EE), 256, SMEM128>>>(
        p_ln, in_img, e_w1, e_b1, p_sel_t, p_sel_i, p_ht, p_hi);
    k_moe2_all<<<dim3(HH / 128, 1, 2 * BB * EE), 256, SMEM128>>>(
        p_ht, p_hi, e_w2, e_b2, p_sel_t, p_sel_i, p_acc_t, p_acc_i);
    k_combine<<<(BB * TT * HH + 255) / 256, 256>>>(
        p_q, p_acc_t, p_cnt_t, out_q, BB * TT * HH);
    k_combine<<<(BB * VV * HH + 255) / 256, 256>>>(
        in_img, p_acc_i, p_cnt_i, out_img, BB * VV * HH);
}

// round 8
// speedup vs baseline: 1.4491x; 1.4491x over previous
#include <cuda_runtime.h>
#include <cuda_fp16.h>
#include <math.h>
#include <stdint.h>

// ---------------- problem constants ----------------
#define BB   4
#define TT   512
#define VV   576
#define LL   256
#define HH   1024
#define NHH  16
#define HDD  64
#define II   4096
#define EE   8
#define KSEL_T 80
#define KSEL_V 90
#define SELCAP 96
#define LN_EPS 1e-5f

#define BM   128
#define BKH  64      // K per tile (halves)
#define ROWH 72      // smem row stride (halves), 64 + 8 pad

// ---------------- fp32 scratch ----------------
__device__ float g_q     [BB*TT*HH];
__device__ float g_scores[BB*NHH*TT*VV];
__device__ float g_acc_t [BB*TT*HH];
__device__ float g_acc_i [BB*VV*HH];
__device__ float g_ctx_img[BB*HH];
__device__ float g_ctx_txt[BB*HH];
__device__ float g_gb_img[BB*EE];
__device__ float g_gb_txt[BB*EE];
__device__ float g_probs_t[BB*TT*EE];
__device__ float g_probs_i[BB*VV*EE];
__device__ int   g_sel_t[BB*EE*SELCAP];
__device__ int   g_sel_i[BB*EE*SELCAP];
__device__ int   g_cnt_t[BB*TT];
__device__ int   g_cnt_i[BB*VV];

// ---------------- fp16 scratch ----------------
__device__ __half h_w_sain [3*HH*HH];
__device__ __half h_w_saout[HH*HH];
__device__ __half h_w_cain [3*HH*HH];
__device__ __half h_w_caout[HH*HH];
__device__ __half h_w_e1   [EE*II*HH];
__device__ __half h_w_e2   [EE*HH*II];
__device__ __half h_img    [BB*VV*HH];
__device__ __half h_ln     [BB*TT*HH];
__device__ __half h_qkv    [BB*TT*3*HH];
__device__ __half h_cq     [BB*TT*HH];
__device__ __half h_kv     [BB*VV*2*HH];
__device__ __half h_probs  [BB*NHH*TT*VV];
__device__ __half h_vt     [BB*NHH*HDD*VV];
__device__ __half h_attn   [BB*TT*HH];
__device__ __half h_ht     [BB*EE*SELCAP*II];
__device__ __half h_hi     [BB*EE*SELCAP*II];

// ---------------- helpers ----------------
__device__ __forceinline__ float gelu_f(float x) {
    float x3 = x * x * x;
    return 0.5f * x * (1.0f + tanhf(0.7978845608028654f * (x + 0.044715f * x3)));
}
__device__ __forceinline__ void mma_f16(float c[4],
    uint32_t a0, uint32_t a1, uint32_t a2, uint32_t a3,
    uint32_t b0, uint32_t b1)
{
    asm volatile(
        "mma.sync.aligned.m16n8k16.row.col.f32.f16.f16.f32 "
        "{%0,%1,%2,%3}, {%4,%5,%6,%7}, {%8,%9}, {%0,%1,%2,%3};"
        : "+f"(c[0]), "+f"(c[1]), "+f"(c[2]), "+f"(c[3])
        : "r"(a0), "r"(a1), "r"(a2), "r"(a3), "r"(b0), "r"(b1));
}
__device__ __forceinline__ void cpa16h(__half* dst, const __half* src, bool valid) {
    uint32_t d = (uint32_t)__cvta_generic_to_shared(dst);
    asm volatile("cp.async.cg.shared.global [%0], [%1], 16, %2;"
                 :: "r"(d), "l"(src), "r"(valid ? 16 : 0));
}

// ---------------- fp16 tensor-core GEMM: C = alpha*A@B^T + eps -------------
// A [M,K] halves row-major (optional row gather), B [N,K] halves row-major.
// 128 x BN x 64 tiles, 3-stage cp.async ring, 256 threads.
template<int BN, bool GELU_E, bool ATOMIC, bool RES, bool OUT16, bool OUT32>
__device__ __forceinline__ void hgemm(
    __half* smem,
    const __half* __restrict__ A, int lda, const int* __restrict__ arow,
    const __half* __restrict__ Bp, int ldb,
    const float* __restrict__ bias, const float* __restrict__ res,
    float* __restrict__ C32, __half* __restrict__ C16,
    int ldc, const int* __restrict__ crow,
    int M, int N, int K, float alpha)
{
    constexpr int NJ  = BN / 16;
    constexpr int STH = (BM + BN) * ROWH;   // halves per stage
    __half* As[3] = { smem, smem + STH, smem + 2 * STH };
    __half* Bs[3] = { smem + BM * ROWH, smem + STH + BM * ROWH,
                      smem + 2 * STH + BM * ROWH };

    const int tid  = threadIdx.x;
    const int lane = tid & 31, warp = tid >> 5;
    const int wm = (warp & 3) * 32;
    const int wn = (warp >> 2) * (BN / 2);
    const int m0 = blockIdx.y * BM, n0 = blockIdx.x * BN;

    const int sr = tid >> 3;          // 0..31: row within pass
    const int ch = tid & 7;           // 8-half (16B) chunk within K-tile
    int rowA[4]; bool valA[4];
#pragma unroll
    for (int p = 0; p < 4; p++) {
        int gm = m0 + sr + p * 32;
        valA[p] = gm < M;
        rowA[p] = valA[p] ? (arow ? arow[gm] : gm) : 0;
    }
    int rowB[BN / 32]; bool valB[BN / 32];
#pragma unroll
    for (int p = 0; p < BN / 32; p++) {
        int gn = n0 + sr + p * 32;
        valB[p] = gn < N;
        rowB[p] = valB[p] ? gn : 0;
    }

    float c[2][NJ][4];
#pragma unroll
    for (int i = 0; i < 2; i++)
#pragma unroll
        for (int j = 0; j < NJ; j++)
#pragma unroll
            for (int q = 0; q < 4; q++) c[i][j][q] = 0.0f;

    const int KT = K / BKH;

    auto load_tile = [&](int st, int k0) {
        __half* Ad = As[st];
        __half* Bd = Bs[st];
#pragma unroll
        for (int p = 0; p < 4; p++)
            cpa16h(Ad + (sr + p * 32) * ROWH + ch * 8,
                   A + (size_t)rowA[p] * lda + k0 + ch * 8, valA[p]);
#pragma unroll
        for (int p = 0; p < BN / 32; p++)
            cpa16h(Bd + (sr + p * 32) * ROWH + ch * 8,
                   Bp + (size_t)rowB[p] * ldb + k0 + ch * 8, valB[p]);
    };

    load_tile(0, 0);
    asm volatile("cp.async.commit_group;");
    if (KT > 1) load_tile(1, BKH);
    asm volatile("cp.async.commit_group;");

    for (int kt = 0; kt < KT; kt++) {
        asm volatile("cp.async.wait_group 1;");
        __syncthreads();
        const int st = kt % 3;
        if (kt + 2 < KT) load_tile((kt + 2) % 3, (kt + 2) * BKH);
        asm volatile("cp.async.commit_group;");

        const __half* Ab = As[st];
        const __half* Bb = Bs[st];
#pragma unroll
        for (int ks = 0; ks < 4; ks++) {
            const int cc = ks * 16 + 2 * (lane & 3);
            uint32_t a[2][4];
#pragma unroll
            for (int i = 0; i < 2; i++) {
                const int r = wm + i * 16 + (lane >> 2);
                a[i][0] = *(const uint32_t*)&Ab[r * ROWH + cc];
                a[i][1] = *(const uint32_t*)&Ab[(r + 8) * ROWH + cc];
                a[i][2] = *(const uint32_t*)&Ab[r * ROWH + cc + 8];
                a[i][3] = *(const uint32_t*)&Ab[(r + 8) * ROWH + cc + 8];
            }
            uint32_t b[NJ][2];
#pragma unroll
            for (int j = 0; j < NJ; j++) {
                const int bc = wn + j * 8 + (lane >> 2);
                b[j][0] = *(const uint32_t*)&Bb[bc * ROWH + cc];
                b[j][1] = *(const uint32_t*)&Bb[bc * ROWH + cc + 8];
            }
#pragma unroll
            for (int i = 0; i < 2; i++)
#pragma unroll
                for (int j = 0; j < NJ; j++)
                    mma_f16(c[i][j], a[i][0], a[i][1], a[i][2], a[i][3],
                            b[j][0], b[j][1]);
        }
    }

    // epilogue
#pragma unroll
    for (int i = 0; i < 2; i++) {
        int rm = m0 + wm + i * 16 + (lane >> 2);
#pragma unroll
        for (int j = 0; j < NJ; j++) {
            int cn = n0 + wn + j * 8 + 2 * (lane & 3);
#pragma unroll
            for (int rr = 0; rr < 2; rr++) {
                int gm = rm + rr * 8;
                if (gm >= M) continue;
                int orow = crow ? crow[gm] : gm;
#pragma unroll
                for (int qq = 0; qq < 2; qq++) {
                    int gn = cn + qq;
                    if (gn >= N) continue;
                    float v = c[i][j][rr * 2 + qq] * alpha;
                    if (bias) v += bias[gn];
                    if (RES)  v += res[(size_t)gm * ldc + gn];
                    if (GELU_E) v = gelu_f(v);
                    if (ATOMIC) {
                        atomicAdd(&C32[(size_t)orow * ldc + gn], v);
                    } else {
                        if (OUT32) C32[(size_t)orow * ldc + gn] = v;
                        if (OUT16) C16[(size_t)orow * ldc + gn] = __float2half_rn(v);
                    }
                }
            }
        }
    }
}

// ---------------- GEMM kernel wrappers ----------------
// activation GEMM: fp16 out, bias
__global__ __launch_bounds__(256, 2) void k_hg_act(
    const __half* A, int lda, const __half* W, int ldw,
    const float* bias, __half* C16, int ldc, int M, int N, int K)
{
    extern __shared__ __half smh[];
    hgemm<128, false, false, false, true, false>(smh, A, lda, nullptr, W, ldw,
        bias, nullptr, nullptr, C16, ldc, nullptr, M, N, K, 1.0f);
}

// projection GEMM: fp32 out, bias + residual
__global__ __launch_bounds__(256, 2) void k_hg_proj(
    const __half* A, int lda, const __half* W, int ldw,
    const float* bias, const float* res, float* C32, int ldc, int M, int N, int K)
{
    extern __shared__ __half smh[];
    hgemm<128, false, false, true, false, true>(smh, A, lda, nullptr, W, ldw,
        bias, res, C32, nullptr, ldc, nullptr, M, N, K, 1.0f);
}

__global__ __launch_bounds__(256, 2) void k_hg_scores(
    const __half* Q, int qbs, int qld,
    const __half* Kp, int kbs, int kld,
    float* S, int Tq, int Skv)
{
    extern __shared__ __half smh[];
    int z = blockIdx.z; int b = z / NHH, h = z % NHH;
    hgemm<128, false, false, false, false, true>(smh,
        Q + (size_t)b * qbs + h * HDD, qld, nullptr,
        Kp + (size_t)b * kbs + h * HDD, kld,
        nullptr, nullptr,
        S + (size_t)z * Tq * Skv, nullptr, Skv, nullptr,
        Tq, Skv, HDD, 0.125f);
}

__global__ __launch_bounds__(256, 2) void k_hg_av(
    const __half* P, const __half* Vt, __half* O, int Tq, int Skv)
{
    extern __shared__ __half smh[];
    int z = blockIdx.z; int b = z / NHH, h = z % NHH;
    hgemm<64, false, false, false, true, false>(smh,
        P + (size_t)z * Tq * Skv, Skv, nullptr,
        Vt + (size_t)z * HDD * Skv, Skv,
        nullptr, nullptr,
        nullptr, O + (size_t)b * Tq * HH + h * HDD, HH, nullptr,
        Tq, HDD, Skv, 1.0f);
}

__global__ __launch_bounds__(256, 2) void k_hg_moe1(
    const __half* Xt, const __half* Xi, const __half* w1, const float* b1,
    const int* selt, const int* seli, __half* Ht, __half* Hi)
{
    extern __shared__ __half smh[];
    int z = blockIdx.z;
    bool txt = z < BB * EE;
    int g = txt ? z : z - BB * EE;
    int b = g / EE, e = g % EE;
    const __half* X = txt ? Xt + (size_t)b * TT * HH : Xi + (size_t)b * VV * HH;
    const int* sel = (txt ? selt : seli) + g * SELCAP;
    __half* H = (txt ? Ht : Hi) + (size_t)g * SELCAP * II;
    int ksel = txt ? KSEL_T : KSEL_V;
    hgemm<128, true, false, false, true, false>(smh, X, HH, sel,
        w1 + (size_t)e * II * HH, HH, b1 + (size_t)e * II, nullptr,
        nullptr, H, II, nullptr, ksel, II, HH, 1.0f);
}

__global__ __launch_bounds__(256, 2) void k_hg_moe2(
    const __half* Ht, const __half* Hi, const __half* w2, const float* b2,
    const int* selt, const int* seli, float* AccT, float* AccI)
{
    extern __shared__ __half smh[];
    int z = blockIdx.z;
    bool txt = z < BB * EE;
    int g = txt ? z : z - BB * EE;
    int b = g / EE, e = g % EE;
    const __half* H = (txt ? Ht : Hi) + (size_t)g * SELCAP * II;
    const int* sel = (txt ? selt : seli) + g * SELCAP;
    float* Acc = txt ? AccT + (size_t)b * TT * HH : AccI + (size_t)b * VV * HH;
    int ksel = txt ? KSEL_T : KSEL_V;
    hgemm<128, false, true, false, false, false>(smh, H, II, nullptr,
        w2 + (size_t)e * HH * II, II, b2 + (size_t)e * HH, nullptr,
        Acc, nullptr, HH, sel, ksel, HH, II, 1.0f);
}

// ---------------- fp32 -> fp16 conversion ----------------
__global__ void k_f2h(const float* __restrict__ x, __half* __restrict__ y, int n)
{
    int i = (blockIdx.x * 256 + threadIdx.x) * 4;
    if (i < n) {
        float4 v = *(const float4*)(x + i);
        *(__half2*)(y + i)     = __floats2half2_rn(v.x, v.y);
        *(__half2*)(y + i + 2) = __floats2half2_rn(v.z, v.w);
    }
}

// ---------------- V transpose (fp16): [S,64] head slices -> [64,S] --------
__global__ void k_transp(const __half* __restrict__ X, int ldx,
                         __half* __restrict__ Y, int S)
{
    __shared__ float t[32][33];
    int z = blockIdx.z; int b = z >> 4, h = z & 15;
    int t0 = blockIdx.x * 32, d0 = blockIdx.y * 32;
    const __half* src = X + ((size_t)b * S) * ldx + h * HDD;
#pragma unroll
    for (int k2 = 0; k2 < 4; k2++) {
        int tt = t0 + threadIdx.y + k2 * 8;
        t[threadIdx.y + k2 * 8][threadIdx.x] =
            __half2float(src[(size_t)tt * ldx + d0 + threadIdx.x]);
    }
    __syncthreads();
    __half* dst = Y + ((size_t)z * HDD) * S;
#pragma unroll
    for (int k2 = 0; k2 < 4; k2++) {
        int d = d0 + threadIdx.y + k2 * 8;
        dst[(size_t)d * S + t0 + threadIdx.x] =
            __float2half_rn(t[threadIdx.x][threadIdx.y + k2 * 8]);
    }
}

// ---------------- layernorm (fp16 out; optional acc-zero fold) -------------
__global__ void k_ln(const float* X, const float* gg, const float* bb,
                     __half* Y, float* accz)
{
    int r = blockIdx.x;
    const float* x = X + (size_t)r * HH;
    __half* y = Y + (size_t)r * HH;
    int tid = threadIdx.x;
    if (accz) {
        float* az = accz + (size_t)r * HH;
        for (int i = tid; i < HH; i += 256) az[i] = 0.0f;
    }
    float s = 0.0f, s2 = 0.0f;
    for (int i = tid; i < HH; i += 256) { float v = x[i]; s += v; s2 += v * v; }
    __shared__ float r1[256], r2[256];
    r1[tid] = s; r2[tid] = s2; __syncthreads();
    for (int st = 128; st; st >>= 1) {
        if (tid < st) { r1[tid] += r1[tid + st]; r2[tid] += r2[tid + st]; }
        __syncthreads();
    }
    float mean = r1[0] * (1.0f / HH);
    float var  = r2[0] * (1.0f / HH) - mean * mean;
    float rstd = rsqrtf(var + LN_EPS);
    for (int i = tid; i < HH; i += 256)
        y[i] = __float2half_rn((x[i] - mean) * rstd * gg[i] + bb[i]);
}

// ---------------- softmax: fp32 in, fp16 out ----------------
template<int W>
__global__ __launch_bounds__(256) void k_softmax_w(const float* __restrict__ S,
                                                   __half* __restrict__ P)
{
    const int row = blockIdx.x * 8 + (threadIdx.x >> 5);
    const int lane = threadIdx.x & 31;
    const float* r = S + (size_t)row * W;
    __half* o = P + (size_t)row * W;
    constexpr int NV = W / 32;
    float v[NV];
    float m = -3.0e38f;
#pragma unroll
    for (int j = 0; j < NV; j++) { v[j] = r[lane + (j << 5)]; m = fmaxf(m, v[j]); }
#pragma unroll
    for (int o2 = 16; o2; o2 >>= 1) m = fmaxf(m, __shfl_xor_sync(0xffffffffu, m, o2));
    float s = 0.0f;
#pragma unroll
    for (int j = 0; j < NV; j++) { v[j] = expf(v[j] - m); s += v[j]; }
#pragma unroll
    for (int o2 = 16; o2; o2 >>= 1) s += __shfl_xor_sync(0xffffffffu, s, o2);
    float inv = 1.0f / s;
#pragma unroll
    for (int j = 0; j < NV; j++) o[lane + (j << 5)] = __float2half_rn(v[j] * inv);
}

// ---------------- gating / misc (fp32) ----------------
__global__ void k_mean(const float* X, float* ctx, int S)
{
    int b = blockIdx.y;
    int c = blockIdx.x * 256 + threadIdx.x;
    float s = 0.0f;
    for (int j = 0; j < S; j++) s += X[(size_t)(b * S + j) * HH + c];
    ctx[b * HH + c] = s / (float)S;
}

__global__ void k_ctxbias(const float* ctx, const float* gw, const float* gb,
                          float* outp)
{
    int g = blockIdx.x; int b = g / EE, e = g % EE;
    int tid = threadIdx.x;
    float s = 0.0f;
    for (int c = tid; c < HH; c += 256)
        s += ctx[b * HH + c] * gw[(size_t)e * 2 * HH + HH + c];
    __shared__ float red[256];
    red[tid] = s; __syncthreads();
    for (int st = 128; st; st >>= 1) {
        if (tid < st) red[tid] += red[tid + st];
        __syncthreads();
    }
    if (tid == 0) outp[g] = red[0] + gb[e];
}

__global__ void k_gate(const float* X, const float* gw, const float* cb,
                       float* probs, int S, int* cntz, float* accz)
{
    int t = blockIdx.x; int b = t / S;
    const float* x = X + (size_t)t * HH;
    int tid = threadIdx.x;
    if (tid == 0) cntz[t] = 0;
    if (accz) {
        float* az = accz + (size_t)t * HH;
        for (int i = tid; i < HH; i += 256) az[i] = 0.0f;
    }
    float part[EE];
#pragma unroll
    for (int e = 0; e < EE; e++) part[e] = 0.0f;
    for (int c = tid; c < HH; c += 256) {
        float xv = x[c];
#pragma unroll
        for (int e = 0; e < EE; e++) part[e] += xv * gw[(size_t)e * 2 * HH + c];
    }
    __shared__ float red[256];
    __shared__ float lg[EE];
    for (int e = 0; e < EE; e++) {
        red[tid] = part[e]; __syncthreads();
        for (int st = 128; st; st >>= 1) {
            if (tid < st) red[tid] += red[tid + st];
            __syncthreads();
        }
        if (tid == 0) lg[e] = red[0] + cb[b * EE + e];
        __syncthreads();
    }
    if (tid == 0) {
        float mx = lg[0];
#pragma unroll
        for (int e = 1; e < EE; e++) mx = fmaxf(mx, lg[e]);
        float sum = 0.0f, ex[EE];
#pragma unroll
        for (int e = 0; e < EE; e++) { ex[e] = expf(lg[e] - mx); sum += ex[e]; }
        float inv = 1.0f / sum;
#pragma unroll
        for (int e = 0; e < EE; e++) probs[(size_t)t * EE + e] = ex[e] * inv;
    }
}

__global__ void k_topk(const float* probs, int S, int ksel, int* sel, int* cnt)
{
    int g = blockIdx.x; int b = g / EE, e = g % EE;
    int tid = threadIdx.x;
    __shared__ float v[VV];
    __shared__ int   sels[SELCAP];
    __shared__ float bestv[256];
    __shared__ int   besti[256];
    for (int i = tid; i < S; i += 256) v[i] = probs[(size_t)(b * S + i) * EE + e];
    __syncthreads();
    for (int it = 0; it < ksel; it++) {
        float bv = -3.0e38f; int bi = S;
        for (int i = tid; i < S; i += 256) {
            float x = v[i];
            if (x > bv || (x == bv && i < bi)) { bv = x; bi = i; }
        }
        bestv[tid] = bv; besti[tid] = bi; __syncthreads();
        for (int st = 128; st; st >>= 1) {
            if (tid < st) {
                if (bestv[tid + st] > bestv[tid] ||
                    (bestv[tid + st] == bestv[tid] && besti[tid + st] < besti[tid])) {
                    bestv[tid] = bestv[tid + st];
                    besti[tid] = besti[tid + st];
                }
            }
            __syncthreads();
        }
        if (tid == 0) {
            sels[it] = besti[0];
            sel[g * SELCAP + it] = besti[0];
            v[besti[0]] = -1.0e30f;
        }
        __syncthreads();
    }
    if (tid < ksel) atomicAdd(&cnt[b * S + sels[tid]], 1);
}

__global__ void k_combine(const float* base, const float* acc, const int* cnt,
                          float* outp, int n)
{
    int i = blockIdx.x * 256 + threadIdx.x;
    if (i < n) {
        int tok = i / HH;
        outp[i] = base[i] + acc[i] / fmaxf((float)cnt[tok], 1.0f);
    }
}

// ---------------- launch ----------------
#define SMEMH128 (3 * (BM + 128) * ROWH * 2)
#define SMEMH64  (3 * (BM + 64) * ROWH * 2)

extern "C" void kernel_launch(void* const* d_in, const int* in_sizes, int n_in,
                              void* d_out, int out_size)
{
    (void)in_sizes; (void)n_in; (void)out_size;
    const float* in_q      = (const float*)d_in[0];
    const float* in_img    = (const float*)d_in[1];
    const float* in_txt    = (const float*)d_in[2];
    const float* sa_w_in   = (const float*)d_in[3];
    const float* sa_b_in   = (const float*)d_in[4];
    const float* sa_w_out  = (const float*)d_in[5];
    const float* sa_b_out  = (const float*)d_in[6];
    const float* ca_w_in   = (const float*)d_in[7];
    const float* ca_b_in   = (const float*)d_in[8];
    const float* ca_w_out  = (const float*)d_in[9];
    const float* ca_b_out  = (const float*)d_in[10];
    const float* gate_img_w= (const float*)d_in[11];
    const float* gate_img_b= (const float*)d_in[12];
    const float* gate_txt_w= (const float*)d_in[13];
    const float* gate_txt_b= (const float*)d_in[14];
    const float* e_w1      = (const float*)d_in[15];
    const float* e_b1      = (const float*)d_in[16];
    const float* e_w2      = (const float*)d_in[17];
    const float* e_b2      = (const float*)d_in[18];
    const float* lnq_g     = (const float*)d_in[19];
    const float* lnq_b     = (const float*)d_in[20];
    const float* lnc_g     = (const float*)d_in[21];
    const float* lnc_b     = (const float*)d_in[22];
    const float* lnf_g     = (const float*)d_in[23];
    const float* lnf_b     = (const float*)d_in[24];
    float* out_q   = (float*)d_out;
    float* out_img = out_q + (size_t)BB * TT * HH;

    float *p_q, *p_scores, *p_acc_t, *p_acc_i;
    float *p_ctx_img, *p_ctx_txt, *p_gb_img, *p_gb_txt, *p_probs_t, *p_probs_i;
    int *p_sel_t, *p_sel_i, *p_cnt_t, *p_cnt_i;
    __half *ph_sain, *ph_saout, *ph_cain, *ph_caout, *ph_e1, *ph_e2;
    __half *ph_img, *ph_ln, *ph_qkv, *ph_cq, *ph_kv, *ph_probs, *ph_vt, *ph_attn;
    __half *ph_ht, *ph_hi;
    cudaGetSymbolAddress((void**)&p_q, g_q);
    cudaGetSymbolAddress((void**)&p_scores, g_scores);
    cudaGetSymbolAddress((void**)&p_acc_t, g_acc_t);
    cudaGetSymbolAddress((void**)&p_acc_i, g_acc_i);
    cudaGetSymbolAddress((void**)&p_ctx_img, g_ctx_img);
    cudaGetSymbolAddress((void**)&p_ctx_txt, g_ctx_txt);
    cudaGetSymbolAddress((void**)&p_gb_img, g_gb_img);
    cudaGetSymbolAddress((void**)&p_gb_txt, g_gb_txt);
    cudaGetSymbolAddress((void**)&p_probs_t, g_probs_t);
    cudaGetSymbolAddress((void**)&p_probs_i, g_probs_i);
    cudaGetSymbolAddress((void**)&p_sel_t, g_sel_t);
    cudaGetSymbolAddress((void**)&p_sel_i, g_sel_i);
    cudaGetSymbolAddress((void**)&p_cnt_t, g_cnt_t);
    cudaGetSymbolAddress((void**)&p_cnt_i, g_cnt_i);
    cudaGetSymbolAddress((void**)&ph_sain, h_w_sain);
    cudaGetSymbolAddress((void**)&ph_saout, h_w_saout);
    cudaGetSymbolAddress((void**)&ph_cain, h_w_cain);
    cudaGetSymbolAddress((void**)&ph_caout, h_w_caout);
    cudaGetSymbolAddress((void**)&ph_e1, h_w_e1);
    cudaGetSymbolAddress((void**)&ph_e2, h_w_e2);
    cudaGetSymbolAddress((void**)&ph_img, h_img);
    cudaGetSymbolAddress((void**)&ph_ln, h_ln);
    cudaGetSymbolAddress((void**)&ph_qkv, h_qkv);
    cudaGetSymbolAddress((void**)&ph_cq, h_cq);
    cudaGetSymbolAddress((void**)&ph_kv, h_kv);
    cudaGetSymbolAddress((void**)&ph_probs, h_probs);
    cudaGetSymbolAddress((void**)&ph_vt, h_vt);
    cudaGetSymbolAddress((void**)&ph_attn, h_attn);
    cudaGetSymbolAddress((void**)&ph_ht, h_ht);
    cudaGetSymbolAddress((void**)&ph_hi, h_hi);

    cudaFuncSetAttribute(k_hg_act,    cudaFuncAttributeMaxDynamicSharedMemorySize, SMEMH128);
    cudaFuncSetAttribute(k_hg_proj,   cudaFuncAttributeMaxDynamicSharedMemorySize, SMEMH128);
    cudaFuncSetAttribute(k_hg_scores, cudaFuncAttributeMaxDynamicSharedMemorySize, SMEMH128);
    cudaFuncSetAttribute(k_hg_av,     cudaFuncAttributeMaxDynamicSharedMemorySize, SMEMH64);
    cudaFuncSetAttribute(k_hg_moe1,   cudaFuncAttributeMaxDynamicSharedMemorySize, SMEMH128);
    cudaFuncSetAttribute(k_hg_moe2,   cudaFuncAttributeMaxDynamicSharedMemorySize, SMEMH128);

    // ---- weight / input conversions ----
    k_f2h<<<(3 * HH * HH / 4 + 255) / 256, 256>>>(sa_w_in, ph_sain, 3 * HH * HH);
    k_f2h<<<(HH * HH / 4 + 255) / 256, 256>>>(sa_w_out, ph_saout, HH * HH);
    k_f2h<<<(3 * HH * HH / 4 + 255) / 256, 256>>>(ca_w_in, ph_cain, 3 * HH * HH);
    k_f2h<<<(HH * HH / 4 + 255) / 256, 256>>>(ca_w_out, ph_caout, HH * HH);
    k_f2h<<<(EE * II * HH / 4 + 255) / 256, 256>>>(e_w1, ph_e1, EE * II * HH);
    k_f2h<<<(EE * HH * II / 4 + 255) / 256, 256>>>(e_w2, ph_e2, EE * HH * II);
    k_f2h<<<(BB * VV * HH / 4 + 255) / 256, 256>>>(in_img, ph_img, BB * VV * HH);

    // ---- self attention ----
    k_ln<<<BB * TT, 256>>>(in_q, lnq_g, lnq_b, ph_ln, nullptr);
    k_hg_act<<<dim3(3 * HH / 128, BB * TT / BM), 256, SMEMH128>>>(
        ph_ln, HH, ph_sain, HH, sa_b_in, ph_qkv, 3 * HH, BB * TT, 3 * HH, HH);
    k_transp<<<dim3(TT / 32, 2, BB * NHH), dim3(32, 8)>>>(
        ph_qkv + 2 * HH, 3 * HH, ph_vt, TT);
    k_hg_scores<<<dim3(TT / 128, TT / BM, BB * NHH), 256, SMEMH128>>>(
        ph_qkv, TT * 3 * HH, 3 * HH, ph_qkv + HH, TT * 3 * HH, 3 * HH,
        p_scores, TT, TT);
    k_softmax_w<TT><<<BB * NHH * TT / 8, 256>>>(p_scores, ph_probs);
    k_hg_av<<<dim3(1, TT / BM, BB * NHH), 256, SMEMH64>>>(
        ph_probs, ph_vt, ph_attn, TT, TT);
    k_hg_proj<<<dim3(HH / 128, BB * TT / BM), 256, SMEMH128>>>(
        ph_attn, HH, ph_saout, HH, sa_b_out, in_q, p_q, HH, BB * TT, HH, HH);

    // ---- cross attention ----
    k_ln<<<BB * TT, 256>>>(p_q, lnc_g, lnc_b, ph_ln, nullptr);
    k_hg_act<<<dim3(HH / 128, BB * TT / BM), 256, SMEMH128>>>(
        ph_ln, HH, ph_cain, HH, ca_b_in, ph_cq, HH, BB * TT, HH, HH);
    k_hg_act<<<dim3(2 * HH / 128, BB * VV / BM), 256, SMEMH128>>>(
        ph_img, HH, ph_cain + (size_t)HH * HH, HH, ca_b_in + HH,
        ph_kv, 2 * HH, BB * VV, 2 * HH, HH);
    k_transp<<<dim3(VV / 32, 2, BB * NHH), dim3(32, 8)>>>(
        ph_kv + HH, 2 * HH, ph_vt, VV);
    k_hg_scores<<<dim3((VV + 127) / 128, TT / BM, BB * NHH), 256, SMEMH128>>>(
        ph_cq, TT * HH, HH, ph_kv, VV * 2 * HH, 2 * HH, p_scores, TT, VV);
    k_softmax_w<VV><<<BB * NHH * TT / 8, 256>>>(p_scores, ph_probs);
    k_hg_av<<<dim3(1, TT / BM, BB * NHH), 256, SMEMH64>>>(
        ph_probs, ph_vt, ph_attn, TT, VV);
    k_hg_proj<<<dim3(HH / 128, BB * TT / BM), 256, SMEMH128>>>(
        ph_attn, HH, ph_caout, HH, ca_b_out, p_q, p_q, HH, BB * TT, HH, HH);

    // ---- gating (also zeroes counts / image acc) ----
    k_mean<<<dim3(HH / 256, BB), 256>>>(in_img, p_ctx_img, VV);
    k_mean<<<dim3(HH / 256, BB), 256>>>(in_txt, p_ctx_txt, LL);
    k_ctxbias<<<BB * EE, 256>>>(p_ctx_txt, gate_img_w, gate_img_b, p_gb_img);
    k_ctxbias<<<BB * EE, 256>>>(p_ctx_img, gate_txt_w, gate_txt_b, p_gb_txt);
    k_gate<<<BB * VV, 256>>>(in_img, gate_img_w, p_gb_img, p_probs_i, VV,
                             p_cnt_i, p_acc_i);
    k_gate<<<BB * TT, 256>>>(p_q, gate_txt_w, p_gb_txt, p_probs_t, TT,
                             p_cnt_t, nullptr);
    k_topk<<<BB * EE, 256>>>(p_probs_t, TT, KSEL_T, p_sel_t, p_cnt_t);
    k_topk<<<BB * EE, 256>>>(p_probs_i, VV, KSEL_V, p_sel_i, p_cnt_i);

    // ---- MoE (merged text+image) ----
    k_ln<<<BB * TT, 256>>>(p_q, lnf_g, lnf_b, ph_ln, p_acc_t);
    k_hg_moe1<<<dim3(II / 128, 1, 2 * BB * EE), 256, SMEMH128>>>(
        ph_ln, ph_img, ph_e1, e_b1, p_sel_t, p_sel_i, ph_ht, ph_hi);
    k_hg_moe2<<<dim3(HH / 128, 1, 2 * BB * EE), 256, SMEMH128>>>(
        ph_ht, ph_hi, ph_e2, e_b2, p_sel_t, p_sel_i, p_acc_t, p_acc_i);
    k_combine<<<(BB * TT * HH + 255) / 256, 256>>>(
        p_q, p_acc_t, p_cnt_t, out_q, BB * TT * HH);
    k_combine<<<(BB * VV * HH + 255) / 256, 256>>>(
        in_img, p_acc_i, p_cnt_i, out_img, BB * VV * HH);
}

// round 9
// speedup vs baseline: 1.5936x; 1.0997x over previous
#include <cuda_runtime.h>
#include <cuda_fp16.h>
#include <math.h>
#include <stdint.h>

// ---------------- problem constants ----------------
#define BB   4
#define TT   512
#define VV   576
#define LL   256
#define HH   1024
#define NHH  16
#define HDD  64
#define II   4096
#define EE   8
#define KSEL_T 80
#define KSEL_V 90
#define SELCAP 96
#define LN_EPS 1e-5f

#define BKH  64      // K per tile (halves)
#define ROWH 72      // smem row stride (halves)

// ---------------- fp32 scratch ----------------
__device__ float g_q     [BB*TT*HH];
__device__ float g_acc_t [BB*TT*HH];
__device__ float g_acc_i [BB*VV*HH];
__device__ float g_ctx_img[BB*HH];
__device__ float g_ctx_txt[BB*HH];
__device__ float g_gb_img[BB*EE];
__device__ float g_gb_txt[BB*EE];
__device__ float g_probs_t[BB*TT*EE];
__device__ float g_probs_i[BB*VV*EE];
__device__ int   g_sel_t[BB*EE*SELCAP];
__device__ int   g_sel_i[BB*EE*SELCAP];
__device__ int   g_cnt_t[BB*TT];
__device__ int   g_cnt_i[BB*VV];

// ---------------- fp16 scratch ----------------
__device__ __half h_w_sain [3*HH*HH];
__device__ __half h_w_saout[HH*HH];
__device__ __half h_w_cain [3*HH*HH];
__device__ __half h_w_caout[HH*HH];
__device__ __half h_w_e1   [EE*II*HH];
__device__ __half h_w_e2   [EE*HH*II];
__device__ __half h_img    [BB*VV*HH];
__device__ __half h_ln     [BB*TT*HH];
__device__ __half h_qkv    [BB*TT*3*HH];
__device__ __half h_cq     [BB*TT*HH];
__device__ __half h_kv     [BB*VV*2*HH];
__device__ __half h_vt     [BB*NHH*HDD*VV];
__device__ __half h_attn   [BB*TT*HH];
__device__ __half h_ht     [BB*EE*SELCAP*II];
__device__ __half h_hi     [BB*EE*SELCAP*II];

// ---------------- helpers ----------------
__device__ __forceinline__ float gelu_f(float x) {
    float x3 = x * x * x;
    return 0.5f * x * (1.0f + tanhf(0.7978845608028654f * (x + 0.044715f * x3)));
}
__device__ __forceinline__ void mma_f16(float c[4],
    uint32_t a0, uint32_t a1, uint32_t a2, uint32_t a3,
    uint32_t b0, uint32_t b1)
{
    asm volatile(
        "mma.sync.aligned.m16n8k16.row.col.f32.f16.f16.f32 "
        "{%0,%1,%2,%3}, {%4,%5,%6,%7}, {%8,%9}, {%0,%1,%2,%3};"
        : "+f"(c[0]), "+f"(c[1]), "+f"(c[2]), "+f"(c[3])
        : "r"(a0), "r"(a1), "r"(a2), "r"(a3), "r"(b0), "r"(b1));
}
__device__ __forceinline__ void cpa16h(__half* dst, const __half* src, bool valid) {
    uint32_t d = (uint32_t)__cvta_generic_to_shared(dst);
    asm volatile("cp.async.cg.shared.global [%0], [%1], 16, %2;"
                 :: "r"(d), "l"(src), "r"(valid ? 16 : 0));
}

// ---------------- fp16 GEMM: C = A@B^T + eps; BN=128 fixed -----------------
// BMT in {128 (256 thr, 4x2 warps), 96 (192 thr, 3x2 warps)}.
template<int BMT, int THREADS, bool GELU_E, bool ATOMIC, bool RES, bool OUT16, bool OUT32>
__device__ __forceinline__ void hgemm(
    __half* smem,
    const __half* __restrict__ A, int lda, const int* __restrict__ arow,
    const __half* __restrict__ Bp, int ldb,
    const float* __restrict__ bias, const float* __restrict__ res,
    float* __restrict__ C32, __half* __restrict__ C16,
    int ldc, const int* __restrict__ crow,
    int M, int N, int K)
{
    constexpr int BN  = 128;
    constexpr int NJ  = 8;
    constexpr int RP  = THREADS / 8;             // rows per load pass
    constexpr int AP  = BMT / RP;                // A passes (=4)
    constexpr int BP  = (BN + RP - 1) / RP;      // B passes
    constexpr int NWM = THREADS / 64;            // warps in M (4 or 3)
    constexpr int STH = (BMT + BN) * ROWH;
    __half* As[3] = { smem, smem + STH, smem + 2 * STH };
    __half* Bs[3] = { smem + BMT * ROWH, smem + STH + BMT * ROWH,
                      smem + 2 * STH + BMT * ROWH };

    const int tid  = threadIdx.x;
    const int lane = tid & 31, warp = tid >> 5;
    const int wm = (warp % NWM) * 32;
    const int wn = (warp / NWM) * 64;
    const int m0 = blockIdx.y * BMT, n0 = blockIdx.x * BN;

    const int sr = tid >> 3;
    const int ch = tid & 7;
    int rowA[AP]; bool valA[AP];
#pragma unroll
    for (int p = 0; p < AP; p++) {
        int gm = m0 + sr + p * RP;
        valA[p] = gm < M;
        rowA[p] = valA[p] ? (arow ? arow[gm] : gm) : 0;
    }
    int rowB[BP]; bool valB[BP];
#pragma unroll
    for (int p = 0; p < BP; p++) {
        int r = sr + p * RP;
        int gn = n0 + r;
        valB[p] = (r < BN) && (gn < N);
        rowB[p] = valB[p] ? gn : 0;
    }

    float c[2][NJ][4];
#pragma unroll
    for (int i = 0; i < 2; i++)
#pragma unroll
        for (int j = 0; j < NJ; j++)
#pragma unroll
            for (int q = 0; q < 4; q++) c[i][j][q] = 0.0f;

    const int KT = K / BKH;

    auto load_tile = [&](int st, int k0) {
        __half* Ad = As[st];
        __half* Bd = Bs[st];
#pragma unroll
        for (int p = 0; p < AP; p++)
            cpa16h(Ad + (sr + p * RP) * ROWH + ch * 8,
                   A + (size_t)rowA[p] * lda + k0 + ch * 8, valA[p]);
#pragma unroll
        for (int p = 0; p < BP; p++) {
            int r = sr + p * RP;
            if (r < BN)
                cpa16h(Bd + r * ROWH + ch * 8,
                       Bp + (size_t)rowB[p] * ldb + k0 + ch * 8, valB[p]);
        }
    };

    load_tile(0, 0);
    asm volatile("cp.async.commit_group;");
    if (KT > 1) load_tile(1, BKH);
    asm volatile("cp.async.commit_group;");

    for (int kt = 0; kt < KT; kt++) {
        asm volatile("cp.async.wait_group 1;");
        __syncthreads();
        const int st = kt % 3;
        if (kt + 2 < KT) load_tile((kt + 2) % 3, (kt + 2) * BKH);
        asm volatile("cp.async.commit_group;");

        const __half* Ab = As[st];
        const __half* Bb = Bs[st];
#pragma unroll
        for (int ks = 0; ks < 4; ks++) {
            const int cc = ks * 16 + 2 * (lane & 3);
            uint32_t a[2][4];
#pragma unroll
            for (int i = 0; i < 2; i++) {
                const int r = wm + i * 16 + (lane >> 2);
                a[i][0] = *(const uint32_t*)&Ab[r * ROWH + cc];
                a[i][1] = *(const uint32_t*)&Ab[(r + 8) * ROWH + cc];
                a[i][2] = *(const uint32_t*)&Ab[r * ROWH + cc + 8];
                a[i][3] = *(const uint32_t*)&Ab[(r + 8) * ROWH + cc + 8];
            }
            uint32_t b[NJ][2];
#pragma unroll
            for (int j = 0; j < NJ; j++) {
                const int bc = wn + j * 8 + (lane >> 2);
                b[j][0] = *(const uint32_t*)&Bb[bc * ROWH + cc];
                b[j][1] = *(const uint32_t*)&Bb[bc * ROWH + cc + 8];
            }
#pragma unroll
            for (int i = 0; i < 2; i++)
#pragma unroll
                for (int j = 0; j < NJ; j++)
                    mma_f16(c[i][j], a[i][0], a[i][1], a[i][2], a[i][3],
                            b[j][0], b[j][1]);
        }
    }

    // epilogue
#pragma unroll
    for (int i = 0; i < 2; i++) {
        int rm = m0 + wm + i * 16 + (lane >> 2);
#pragma unroll
        for (int j = 0; j < NJ; j++) {
            int cn = n0 + wn + j * 8 + 2 * (lane & 3);
#pragma unroll
            for (int rr = 0; rr < 2; rr++) {
                int gm = rm + rr * 8;
                if (gm >= M) continue;
                int orow = crow ? crow[gm] : gm;
#pragma unroll
                for (int qq = 0; qq < 2; qq++) {
                    int gn = cn + qq;
                    if (gn >= N) continue;
                    float v = c[i][j][rr * 2 + qq];
                    if (bias) v += bias[gn];
                    if (RES)  v += res[(size_t)gm * ldc + gn];
                    if (GELU_E) v = gelu_f(v);
                    if (ATOMIC) {
                        atomicAdd(&C32[(size_t)orow * ldc + gn], v);
                    } else {
                        if (OUT32) C32[(size_t)orow * ldc + gn] = v;
                        if (OUT16) C16[(size_t)orow * ldc + gn] = __float2half_rn(v);
                    }
                }
            }
        }
    }
}

// ---------------- GEMM kernel wrappers ----------------
__global__ __launch_bounds__(256, 2) void k_hg_act(
    const __half* A, int lda, const __half* W, int ldw,
    const float* bias, __half* C16, int ldc, int M, int N, int K)
{
    extern __shared__ __half smh[];
    hgemm<128, 256, false, false, false, true, false>(smh, A, lda, nullptr, W, ldw,
        bias, nullptr, nullptr, C16, ldc, nullptr, M, N, K);
}

__global__ __launch_bounds__(256, 2) void k_hg_proj(
    const __half* A, int lda, const __half* W, int ldw,
    const float* bias, const float* res, float* C32, int ldc, int M, int N, int K)
{
    extern __shared__ __half smh[];
    hgemm<128, 256, false, false, true, false, true>(smh, A, lda, nullptr, W, ldw,
        bias, res, C32, nullptr, ldc, nullptr, M, N, K);
}

__global__ __launch_bounds__(192, 2) void k_hg_moe1(
    const __half* Xt, const __half* Xi, const __half* w1, const float* b1,
    const int* selt, const int* seli, __half* Ht, __half* Hi)
{
    extern __shared__ __half smh[];
    int z = blockIdx.z;
    bool txt = z < BB * EE;
    int g = txt ? z : z - BB * EE;
    int b = g / EE, e = g % EE;
    const __half* X = txt ? Xt + (size_t)b * TT * HH : Xi + (size_t)b * VV * HH;
    const int* sel = (txt ? selt : seli) + g * SELCAP;
    __half* H = (txt ? Ht : Hi) + (size_t)g * SELCAP * II;
    int ksel = txt ? KSEL_T : KSEL_V;
    hgemm<96, 192, true, false, false, true, false>(smh, X, HH, sel,
        w1 + (size_t)e * II * HH, HH, b1 + (size_t)e * II, nullptr,
        nullptr, H, II, nullptr, ksel, II, HH);
}

__global__ __launch_bounds__(192, 2) void k_hg_moe2(
    const __half* Ht, const __half* Hi, const __half* w2, const float* b2,
    const int* selt, const int* seli, float* AccT, float* AccI)
{
    extern __shared__ __half smh[];
    int z = blockIdx.z;
    bool txt = z < BB * EE;
    int g = txt ? z : z - BB * EE;
    int b = g / EE, e = g % EE;
    const __half* H = (txt ? Ht : Hi) + (size_t)g * SELCAP * II;
    const int* sel = (txt ? selt : seli) + g * SELCAP;
    float* Acc = txt ? AccT + (size_t)b * TT * HH : AccI + (size_t)b * VV * HH;
    int ksel = txt ? KSEL_T : KSEL_V;
    hgemm<96, 192, false, true, false, false, false>(smh, H, II, nullptr,
        w2 + (size_t)e * HH * II, II, b2 + (size_t)e * HH, nullptr,
        Acc, nullptr, HH, sel, ksel, HH, II);
}

// ---------------- fused flash attention ----------------
// grid: (Tq/128, 1, B*NH), 256 threads. Q tile 128x64, KV chunks of 64.
#define FL_SMEM ((128 * ROWH + 4 * 64 * ROWH) * 2)

__global__ __launch_bounds__(256, 1) void k_flash(
    const __half* __restrict__ Qp, int qld, int qbs,
    const __half* __restrict__ Kp, int kld, int kbs,
    const __half* __restrict__ Vt,
    __half* __restrict__ O, int Tq, int Skv)
{
    extern __shared__ __half sm[];
    __half* Qs = sm;
    __half* Ks[2] = { sm + 128 * ROWH, sm + 128 * ROWH + 64 * ROWH };
    __half* Vs[2] = { sm + 128 * ROWH + 2 * 64 * ROWH,
                      sm + 128 * ROWH + 3 * 64 * ROWH };

    const int z = blockIdx.z, b = z / NHH, h = z % NHH;
    const __half* Qb = Qp + (size_t)b * qbs + h * HDD;
    const __half* Kb = Kp + (size_t)b * kbs + h * HDD;
    const __half* Vb = Vt + (size_t)z * HDD * Skv;
    __half* Ob = O + (size_t)b * Tq * HH + h * HDD;

    const int tid = threadIdx.x, lane = tid & 31, warp = tid >> 5;
    const int m0 = blockIdx.x * 128;
    const int sr = tid >> 3, ch = tid & 7;

    auto loadKV = [&](int buf, int s0) {
#pragma unroll
        for (int p = 0; p < 2; p++)
            cpa16h(Ks[buf] + (sr + p * 32) * ROWH + ch * 8,
                   Kb + (size_t)(s0 + sr + p * 32) * kld + ch * 8, true);
#pragma unroll
        for (int p = 0; p < 2; p++)
            cpa16h(Vs[buf] + (sr + p * 32) * ROWH + ch * 8,
                   Vb + (size_t)(sr + p * 32) * Skv + s0 + ch * 8, true);
    };

    // prologue: Q tile + chunk 0
#pragma unroll
    for (int p = 0; p < 4; p++)
        cpa16h(Qs + (sr + p * 32) * ROWH + ch * 8,
               Qb + (size_t)(m0 + sr + p * 32) * qld + ch * 8, true);
    loadKV(0, 0);
    asm volatile("cp.async.commit_group;");

    uint32_t qa[4][4];
    float o[8][4];
#pragma unroll
    for (int j = 0; j < 8; j++)
#pragma unroll
        for (int q = 0; q < 4; q++) o[j][q] = 0.0f;
    float m0v = -1.0e30f, m1v = -1.0e30f, l0 = 0.0f, l1 = 0.0f;

    const int nchunks = Skv / 64;
    for (int s = 0; s < nchunks; s++) {
        asm volatile("cp.async.wait_group 0;");
        __syncthreads();
        const int buf = s & 1;
        if (s == 0) {
            const int r = warp * 16 + (lane >> 2);
#pragma unroll
            for (int ks = 0; ks < 4; ks++) {
                const int cc = ks * 16 + 2 * (lane & 3);
                qa[ks][0] = *(const uint32_t*)&Qs[r * ROWH + cc];
                qa[ks][1] = *(const uint32_t*)&Qs[(r + 8) * ROWH + cc];
                qa[ks][2] = *(const uint32_t*)&Qs[r * ROWH + cc + 8];
                qa[ks][3] = *(const uint32_t*)&Qs[(r + 8) * ROWH + cc + 8];
            }
        }
        if (s + 1 < nchunks) loadKV(buf ^ 1, (s + 1) * 64);
        asm volatile("cp.async.commit_group;");

        // S = 0.125 * Q @ K^T  (16x64 per warp)
        float sc[8][4];
#pragma unroll
        for (int j = 0; j < 8; j++)
#pragma unroll
            for (int q = 0; q < 4; q++) sc[j][q] = 0.0f;
        const __half* Kc = Ks[buf];
#pragma unroll
        for (int ks = 0; ks < 4; ks++) {
            const int cc = ks * 16 + 2 * (lane & 3);
#pragma unroll
            for (int j = 0; j < 8; j++) {
                const int bc = j * 8 + (lane >> 2);
                uint32_t b0 = *(const uint32_t*)&Kc[bc * ROWH + cc];
                uint32_t b1 = *(const uint32_t*)&Kc[bc * ROWH + cc + 8];
                mma_f16(sc[j], qa[ks][0], qa[ks][1], qa[ks][2], qa[ks][3], b0, b1);
            }
        }
        // online softmax (rows: lane>>2 [q0,q1], lane>>2+8 [q2,q3])
        float rm0 = -1.0e30f, rm1 = -1.0e30f;
#pragma unroll
        for (int j = 0; j < 8; j++) {
#pragma unroll
            for (int q = 0; q < 4; q++) sc[j][q] *= 0.125f;
            rm0 = fmaxf(rm0, fmaxf(sc[j][0], sc[j][1]));
            rm1 = fmaxf(rm1, fmaxf(sc[j][2], sc[j][3]));
        }
#pragma unroll
        for (int off = 1; off <= 2; off <<= 1) {
            rm0 = fmaxf(rm0, __shfl_xor_sync(0xffffffffu, rm0, off));
            rm1 = fmaxf(rm1, __shfl_xor_sync(0xffffffffu, rm1, off));
        }
        float nm0 = fmaxf(m0v, rm0), nm1 = fmaxf(m1v, rm1);
        float cr0 = __expf(m0v - nm0), cr1 = __expf(m1v - nm1);
        m0v = nm0; m1v = nm1;
        float rs0 = 0.0f, rs1 = 0.0f;
#pragma unroll
        for (int j = 0; j < 8; j++) {
            sc[j][0] = __expf(sc[j][0] - nm0);
            sc[j][1] = __expf(sc[j][1] - nm0);
            sc[j][2] = __expf(sc[j][2] - nm1);
            sc[j][3] = __expf(sc[j][3] - nm1);
            rs0 += sc[j][0] + sc[j][1];
            rs1 += sc[j][2] + sc[j][3];
        }
#pragma unroll
        for (int off = 1; off <= 2; off <<= 1) {
            rs0 += __shfl_xor_sync(0xffffffffu, rs0, off);
            rs1 += __shfl_xor_sync(0xffffffffu, rs1, off);
        }
        l0 = l0 * cr0 + rs0;
        l1 = l1 * cr1 + rs1;
#pragma unroll
        for (int j = 0; j < 8; j++) {
            o[j][0] *= cr0; o[j][1] *= cr0;
            o[j][2] *= cr1; o[j][3] *= cr1;
        }
        // O += P @ V  (P reused as A-frags)
        const __half* Vc = Vs[buf];
#pragma unroll
        for (int ks = 0; ks < 4; ks++) {
            uint32_t a0, a1, a2, a3;
            {
                __half2 t;
                t = __floats2half2_rn(sc[2 * ks][0], sc[2 * ks][1]);     a0 = *(uint32_t*)&t;
                t = __floats2half2_rn(sc[2 * ks][2], sc[2 * ks][3]);     a1 = *(uint32_t*)&t;
                t = __floats2half2_rn(sc[2 * ks + 1][0], sc[2 * ks + 1][1]); a2 = *(uint32_t*)&t;
                t = __floats2half2_rn(sc[2 * ks + 1][2], sc[2 * ks + 1][3]); a3 = *(uint32_t*)&t;
            }
            const int cc = ks * 16 + 2 * (lane & 3);
#pragma unroll
            for (int jd = 0; jd < 8; jd++) {
                const int bc = jd * 8 + (lane >> 2);
                uint32_t b0 = *(const uint32_t*)&Vc[bc * ROWH + cc];
                uint32_t b1 = *(const uint32_t*)&Vc[bc * ROWH + cc + 8];
                mma_f16(o[jd], a0, a1, a2, a3, b0, b1);
            }
        }
    }

    // epilogue
    const float iv0 = 1.0f / l0, iv1 = 1.0f / l1;
    const int r0 = m0 + warp * 16 + (lane >> 2);
#pragma unroll
    for (int jd = 0; jd < 8; jd++) {
        const int col = jd * 8 + 2 * (lane & 3);
        Ob[(size_t)r0 * HH + col]       = __float2half_rn(o[jd][0] * iv0);
        Ob[(size_t)r0 * HH + col + 1]   = __float2half_rn(o[jd][1] * iv0);
        Ob[(size_t)(r0 + 8) * HH + col]     = __float2half_rn(o[jd][2] * iv1);
        Ob[(size_t)(r0 + 8) * HH + col + 1] = __float2half_rn(o[jd][3] * iv1);
    }
}

// ---------------- fp32 -> fp16 conversion ----------------
__global__ void k_f2h(const float* __restrict__ x, __half* __restrict__ y, int n)
{
    int i = (blockIdx.x * 256 + threadIdx.x) * 4;
    if (i < n) {
        float4 v = *(const float4*)(x + i);
        *(__half2*)(y + i)     = __floats2half2_rn(v.x, v.y);
        *(__half2*)(y + i + 2) = __floats2half2_rn(v.z, v.w);
    }
}

// ---------------- V transpose (fp16) ----------------
__global__ void k_transp(const __half* __restrict__ X, int ldx,
                         __half* __restrict__ Y, int S)
{
    __shared__ float t[32][33];
    int z = blockIdx.z; int b = z >> 4, h = z & 15;
    int t0 = blockIdx.x * 32, d0 = blockIdx.y * 32;
    const __half* src = X + ((size_t)b * S) * ldx + h * HDD;
#pragma unroll
    for (int k2 = 0; k2 < 4; k2++) {
        int tt = t0 + threadIdx.y + k2 * 8;
        t[threadIdx.y + k2 * 8][threadIdx.x] =
            __half2float(src[(size_t)tt * ldx + d0 + threadIdx.x]);
    }
    __syncthreads();
    __half* dst = Y + ((size_t)z * HDD) * S;
#pragma unroll
    for (int k2 = 0; k2 < 4; k2++) {
        int d = d0 + threadIdx.y + k2 * 8;
        dst[(size_t)d * S + t0 + threadIdx.x] =
            __float2half_rn(t[threadIdx.x][threadIdx.y + k2 * 8]);
    }
}

// ---------------- layernorm (fp16 out; optional acc-zero fold) -------------
__global__ void k_ln(const float* X, const float* gg, const float* bb,
                     __half* Y, float* accz)
{
    int r = blockIdx.x;
    const float* x = X + (size_t)r * HH;
    __half* y = Y + (size_t)r * HH;
    int tid = threadIdx.x;
    if (accz) {
        float* az = accz + (size_t)r * HH;
        for (int i = tid; i < HH; i += 256) az[i] = 0.0f;
    }
    float s = 0.0f, s2 = 0.0f;
    for (int i = tid; i < HH; i += 256) { float v = x[i]; s += v; s2 += v * v; }
    __shared__ float r1[256], r2[256];
    r1[tid] = s; r2[tid] = s2; __syncthreads();
    for (int st = 128; st; st >>= 1) {
        if (tid < st) { r1[tid] += r1[tid + st]; r2[tid] += r2[tid + st]; }
        __syncthreads();
    }
    float mean = r1[0] * (1.0f / HH);
    float var  = r2[0] * (1.0f / HH) - mean * mean;
    float rstd = rsqrtf(var + LN_EPS);
    for (int i = tid; i < HH; i += 256)
        y[i] = __float2half_rn((x[i] - mean) * rstd * gg[i] + bb[i]);
}

// ---------------- gating / misc (fp32) ----------------
__global__ void k_mean(const float* X, float* ctx, int S)
{
    int b = blockIdx.y;
    int c = blockIdx.x * 256 + threadIdx.x;
    float s = 0.0f;
    for (int j = 0; j < S; j++) s += X[(size_t)(b * S + j) * HH + c];
    ctx[b * HH + c] = s / (float)S;
}

__global__ void k_ctxbias(const float* ctx, const float* gw, const float* gb,
                          float* outp)
{
    int g = blockIdx.x; int b = g / EE, e = g % EE;
    int tid = threadIdx.x;
    float s = 0.0f;
    for (int c = tid; c < HH; c += 256)
        s += ctx[b * HH + c] * gw[(size_t)e * 2 * HH + HH + c];
    __shared__ float red[256];
    red[tid] = s; __syncthreads();
    for (int st = 128; st; st >>= 1) {
        if (tid < st) red[tid] += red[tid + st];
        __syncthreads();
    }
    if (tid == 0) outp[g] = red[0] + gb[e];
}

__global__ void k_gate(const float* X, const float* gw, const float* cb,
                       float* probs, int S, int* cntz, float* accz)
{
    int t = blockIdx.x; int b = t / S;
    const float* x = X + (size_t)t * HH;
    int tid = threadIdx.x;
    if (tid == 0) cntz[t] = 0;
    if (accz) {
        float* az = accz + (size_t)t * HH;
        for (int i = tid; i < HH; i += 256) az[i] = 0.0f;
    }
    float part[EE];
#pragma unroll
    for (int e = 0; e < EE; e++) part[e] = 0.0f;
    for (int c = tid; c < HH; c += 256) {
        float xv = x[c];
#pragma unroll
        for (int e = 0; e < EE; e++) part[e] += xv * gw[(size_t)e * 2 * HH + c];
    }
    __shared__ float red[256];
    __shared__ float lg[EE];
    for (int e = 0; e < EE; e++) {
        red[tid] = part[e]; __syncthreads();
        for (int st = 128; st; st >>= 1) {
            if (tid < st) red[tid] += red[tid + st];
            __syncthreads();
        }
        if (tid == 0) lg[e] = red[0] + cb[b * EE + e];
        __syncthreads();
    }
    if (tid == 0) {
        float mx = lg[0];
#pragma unroll
        for (int e = 1; e < EE; e++) mx = fmaxf(mx, lg[e]);
        float sum = 0.0f, ex[EE];
#pragma unroll
        for (int e = 0; e < EE; e++) { ex[e] = expf(lg[e] - mx); sum += ex[e]; }
        float inv = 1.0f / sum;
#pragma unroll
        for (int e = 0; e < EE; e++) probs[(size_t)t * EE + e] = ex[e] * inv;
    }
}

__global__ void k_topk(const float* probs, int S, int ksel, int* sel, int* cnt)
{
    int g = blockIdx.x; int b = g / EE, e = g % EE;
    int tid = threadIdx.x;
    __shared__ float v[VV];
    __shared__ int   sels[SELCAP];
    __shared__ float bestv[256];
    __shared__ int   besti[256];
    for (int i = tid; i < S; i += 256) v[i] = probs[(size_t)(b * S + i) * EE + e];
    __syncthreads();
    for (int it = 0; it < ksel; it++) {
        float bv = -3.0e38f; int bi = S;
        for (int i = tid; i < S; i += 256) {
            float x = v[i];
            if (x > bv || (x == bv && i < bi)) { bv = x; bi = i; }
        }
        bestv[tid] = bv; besti[tid] = bi; __syncthreads();
        for (int st = 128; st; st >>= 1) {
            if (tid < st) {
                if (bestv[tid + st] > bestv[tid] ||
                    (bestv[tid + st] == bestv[tid] && besti[tid + st] < besti[tid])) {
                    bestv[tid] = bestv[tid + st];
                    besti[tid] = besti[tid + st];
                }
            }
            __syncthreads();
        }
        if (tid == 0) {
            sels[it] = besti[0];
            sel[g * SELCAP + it] = besti[0];
            v[besti[0]] = -1.0e30f;
        }
        __syncthreads();
    }
    if (tid < ksel) atomicAdd(&cnt[b * S + sels[tid]], 1);
}

__global__ void k_combine(const float* base, const float* acc, const int* cnt,
                          float* outp, int n)
{
    int i = blockIdx.x * 256 + threadIdx.x;
    if (i < n) {
        int tok = i / HH;
        outp[i] = base[i] + acc[i] / fmaxf((float)cnt[tok], 1.0f);
    }
}

// ---------------- launch ----------------
#define SMEMH128 (3 * (128 + 128) * ROWH * 2)
#define SMEMH96  (3 * (96 + 128) * ROWH * 2)

extern "C" void kernel_launch(void* const* d_in, const int* in_sizes, int n_in,
                              void* d_out, int out_size)
{
    (void)in_sizes; (void)n_in; (void)out_size;
    const float* in_q      = (const float*)d_in[0];
    const float* in_img    = (const float*)d_in[1];
    const float* in_txt    = (const float*)d_in[2];
    const float* sa_w_in   = (const float*)d_in[3];
    const float* sa_b_in   = (const float*)d_in[4];
    const float* sa_w_out  = (const float*)d_in[5];
    const float* sa_b_out  = (const float*)d_in[6];
    const float* ca_w_in   = (const float*)d_in[7];
    const float* ca_b_in   = (const float*)d_in[8];
    const float* ca_w_out  = (const float*)d_in[9];
    const float* ca_b_out  = (const float*)d_in[10];
    const float* gate_img_w= (const float*)d_in[11];
    const float* gate_img_b= (const float*)d_in[12];
    const float* gate_txt_w= (const float*)d_in[13];
    const float* gate_txt_b= (const float*)d_in[14];
    const float* e_w1      = (const float*)d_in[15];
    const float* e_b1      = (const float*)d_in[16];
    const float* e_w2      = (const float*)d_in[17];
    const float* e_b2      = (const float*)d_in[18];
    const float* lnq_g     = (const float*)d_in[19];
    const float* lnq_b     = (const float*)d_in[20];
    const float* lnc_g     = (const float*)d_in[21];
    const float* lnc_b     = (const float*)d_in[22];
    const float* lnf_g     = (const float*)d_in[23];
    const float* lnf_b     = (const float*)d_in[24];
    float* out_q   = (float*)d_out;
    float* out_img = out_q + (size_t)BB * TT * HH;

    float *p_q, *p_acc_t, *p_acc_i;
    float *p_ctx_img, *p_ctx_txt, *p_gb_img, *p_gb_txt, *p_probs_t, *p_probs_i;
    int *p_sel_t, *p_sel_i, *p_cnt_t, *p_cnt_i;
    __half *ph_sain, *ph_saout, *ph_cain, *ph_caout, *ph_e1, *ph_e2;
    __half *ph_img, *ph_ln, *ph_qkv, *ph_cq, *ph_kv, *ph_vt, *ph_attn;
    __half *ph_ht, *ph_hi;
    cudaGetSymbolAddress((void**)&p_q, g_q);
    cudaGetSymbolAddress((void**)&p_acc_t, g_acc_t);
    cudaGetSymbolAddress((void**)&p_acc_i, g_acc_i);
    cudaGetSymbolAddress((void**)&p_ctx_img, g_ctx_img);
    cudaGetSymbolAddress((void**)&p_ctx_txt, g_ctx_txt);
    cudaGetSymbolAddress((void**)&p_gb_img, g_gb_img);
    cudaGetSymbolAddress((void**)&p_gb_txt, g_gb_txt);
    cudaGetSymbolAddress((void**)&p_probs_t, g_probs_t);
    cudaGetSymbolAddress((void**)&p_probs_i, g_probs_i);
    cudaGetSymbolAddress((void**)&p_sel_t, g_sel_t);
    cudaGetSymbolAddress((void**)&p_sel_i, g_sel_i);
    cudaGetSymbolAddress((void**)&p_cnt_t, g_cnt_t);
    cudaGetSymbolAddress((void**)&p_cnt_i, g_cnt_i);
    cudaGetSymbolAddress((void**)&ph_sain, h_w_sain);
    cudaGetSymbolAddress((void**)&ph_saout, h_w_saout);
    cudaGetSymbolAddress((void**)&ph_cain, h_w_cain);
    cudaGetSymbolAddress((void**)&ph_caout, h_w_caout);
    cudaGetSymbolAddress((void**)&ph_e1, h_w_e1);
    cudaGetSymbolAddress((void**)&ph_e2, h_w_e2);
    cudaGetSymbolAddress((void**)&ph_img, h_img);
    cudaGetSymbolAddress((void**)&ph_ln, h_ln);
    cudaGetSymbolAddress((void**)&ph_qkv, h_qkv);
    cudaGetSymbolAddress((void**)&ph_cq, h_cq);
    cudaGetSymbolAddress((void**)&ph_kv, h_kv);
    cudaGetSymbolAddress((void**)&ph_vt, h_vt);
    cudaGetSymbolAddress((void**)&ph_attn, h_attn);
    cudaGetSymbolAddress((void**)&ph_ht, h_ht);
    cudaGetSymbolAddress((void**)&ph_hi, h_hi);

    cudaFuncSetAttribute(k_hg_act,  cudaFuncAttributeMaxDynamicSharedMemorySize, SMEMH128);
    cudaFuncSetAttribute(k_hg_proj, cudaFuncAttributeMaxDynamicSharedMemorySize, SMEMH128);
    cudaFuncSetAttribute(k_hg_moe1, cudaFuncAttributeMaxDynamicSharedMemorySize, SMEMH96);
    cudaFuncSetAttribute(k_hg_moe2, cudaFuncAttributeMaxDynamicSharedMemorySize, SMEMH96);
    cudaFuncSetAttribute(k_flash,   cudaFuncAttributeMaxDynamicSharedMemorySize, FL_SMEM);

    // ---- weight / input conversions ----
    k_f2h<<<(3 * HH * HH / 4 + 255) / 256, 256>>>(sa_w_in, ph_sain, 3 * HH * HH);
    k_f2h<<<(HH * HH / 4 + 255) / 256, 256>>>(sa_w_out, ph_saout, HH * HH);
    k_f2h<<<(3 * HH * HH / 4 + 255) / 256, 256>>>(ca_w_in, ph_cain, 3 * HH * HH);
    k_f2h<<<(HH * HH / 4 + 255) / 256, 256>>>(ca_w_out, ph_caout, HH * HH);
    k_f2h<<<(EE * II * HH / 4 + 255) / 256, 256>>>(e_w1, ph_e1, EE * II * HH);
    k_f2h<<<(EE * HH * II / 4 + 255) / 256, 256>>>(e_w2, ph_e2, EE * HH * II);
    k_f2h<<<(BB * VV * HH / 4 + 255) / 256, 256>>>(in_img, ph_img, BB * VV * HH);

    // ---- self attention ----
    k_ln<<<BB * TT, 256>>>(in_q, lnq_g, lnq_b, ph_ln, nullptr);
    k_hg_act<<<dim3(3 * HH / 128, BB * TT / 128), 256, SMEMH128>>>(
        ph_ln, HH, ph_sain, HH, sa_b_in, ph_qkv, 3 * HH, BB * TT, 3 * HH, HH);
    k_transp<<<dim3(TT / 32, 2, BB * NHH), dim3(32, 8)>>>(
        ph_qkv + 2 * HH, 3 * HH, ph_vt, TT);
    k_flash<<<dim3(TT / 128, 1, BB * NHH), 256, FL_SMEM>>>(
        ph_qkv, 3 * HH, TT * 3 * HH, ph_qkv + HH, 3 * HH, TT * 3 * HH,
        ph_vt, ph_attn, TT, TT);
    k_hg_proj<<<dim3(HH / 128, BB * TT / 128), 256, SMEMH128>>>(
        ph_attn, HH, ph_saout, HH, sa_b_out, in_q, p_q, HH, BB * TT, HH, HH);

    // ---- cross attention ----
    k_ln<<<BB * TT, 256>>>(p_q, lnc_g, lnc_b, ph_ln, nullptr);
    k_hg_act<<<dim3(HH / 128, BB * TT / 128), 256, SMEMH128>>>(
        ph_ln, HH, ph_cain, HH, ca_b_in, ph_cq, HH, BB * TT, HH, HH);
    k_hg_act<<<dim3(2 * HH / 128, BB * VV / 128), 256, SMEMH128>>>(
        ph_img, HH, ph_cain + (size_t)HH * HH, HH, ca_b_in + HH,
        ph_kv, 2 * HH, BB * VV, 2 * HH, HH);
    k_transp<<<dim3(VV / 32, 2, BB * NHH), dim3(32, 8)>>>(
        ph_kv + HH, 2 * HH, ph_vt, VV);
    k_flash<<<dim3(TT / 128, 1, BB * NHH), 256, FL_SMEM>>>(
        ph_cq, HH, TT * HH, ph_kv, 2 * HH, VV * 2 * HH,
        ph_vt, ph_attn, TT, VV);
    k_hg_proj<<<dim3(HH / 128, BB * TT / 128), 256, SMEMH128>>>(
        ph_attn, HH, ph_caout, HH, ca_b_out, p_q, p_q, HH, BB * TT, HH, HH);

    // ---- gating (also zeroes counts / image acc) ----
    k_mean<<<dim3(HH / 256, BB), 256>>>(in_img, p_ctx_img, VV);
    k_mean<<<dim3(HH / 256, BB), 256>>>(in_txt, p_ctx_txt, LL);
    k_ctxbias<<<BB * EE, 256>>>(p_ctx_txt, gate_img_w, gate_img_b, p_gb_img);
    k_ctxbias<<<BB * EE, 256>>>(p_ctx_img, gate_txt_w, gate_txt_b, p_gb_txt);
    k_gate<<<BB * VV, 256>>>(in_img, gate_img_w, p_gb_img, p_probs_i, VV,
                             p_cnt_i, p_acc_i);
    k_gate<<<BB * TT, 256>>>(p_q, gate_txt_w, p_gb_txt, p_probs_t, TT,
                             p_cnt_t, nullptr);
    k_topk<<<BB * EE, 256>>>(p_probs_t, TT, KSEL_T, p_sel_t, p_cnt_t);
    k_topk<<<BB * EE, 256>>>(p_probs_i, VV, KSEL_V, p_sel_i, p_cnt_i);

    // ---- MoE (merged text+image; BM=96 tiles) ----
    k_ln<<<BB * TT, 256>>>(p_q, lnf_g, lnf_b, ph_ln, p_acc_t);
    k_hg_moe1<<<dim3(II / 128, 1, 2 * BB * EE), 192, SMEMH96>>>(
        ph_ln, ph_img, ph_e1, e_b1, p_sel_t, p_sel_i, ph_ht, ph_hi);
    k_hg_moe2<<<dim3(HH / 128, 1, 2 * BB * EE), 192, SMEMH96>>>(
        ph_ht, ph_hi, ph_e2, e_b2, p_sel_t, p_sel_i, p_acc_t, p_acc_i);
    k_combine<<<(BB * TT * HH + 255) / 256, 256>>>(
        p_q, p_acc_t, p_cnt_t, out_q, BB * TT * HH);
    k_combine<<<(BB * VV * HH + 255) / 256, 256>>>(
        in_img, p_acc_i, p_cnt_i, out_img, BB * VV * HH);
}

// round 10
// speedup vs baseline: 1.9068x; 1.1965x over previous
#include <cuda_runtime.h>
#include <cuda_fp16.h>
#include <math.h>
#include <stdint.h>

// ---------------- problem constants ----------------
#define BB   4
#define TT   512
#define VV   576
#define LL   256
#define HH   1024
#define NHH  16
#define HDD  64
#define II   4096
#define EE   8
#define KSEL_T 80
#define KSEL_V 90
#define SELCAP 96
#define LN_EPS 1e-5f

#define BKH  64
#define ROWH 72

// ---------------- fp32 scratch ----------------
__device__ float g_q     [BB*TT*HH];
__device__ float g_acc_t [BB*TT*HH];
__device__ float g_acc_i [BB*VV*HH];
__device__ float g_ctx_img[BB*HH];
__device__ float g_ctx_txt[BB*HH];
__device__ float g_gb_img[BB*EE];
__device__ float g_gb_txt[BB*EE];
__device__ float g_probs_t[BB*TT*EE];
__device__ float g_probs_i[BB*VV*EE];
__device__ int   g_sel_t[BB*EE*SELCAP];
__device__ int   g_sel_i[BB*EE*SELCAP];
__device__ int   g_cnt_t[BB*TT];
__device__ int   g_cnt_i[BB*VV];

// ---------------- fp16 scratch ----------------
__device__ __half h_w_sain [3*HH*HH];
__device__ __half h_w_saout[HH*HH];
__device__ __half h_w_cain [3*HH*HH];
__device__ __half h_w_caout[HH*HH];
__device__ __half h_w_e1   [EE*II*HH];
__device__ __half h_w_e2   [EE*HH*II];
__device__ __half h_img    [BB*VV*HH];
__device__ __half h_ln     [BB*TT*HH];
__device__ __half h_qkv    [BB*TT*3*HH];
__device__ __half h_cq     [BB*TT*HH];
__device__ __half h_kv     [BB*VV*2*HH];
__device__ __half h_vt     [BB*NHH*HDD*VV];
__device__ __half h_attn   [BB*TT*HH];
__device__ __half h_ht     [BB*EE*SELCAP*II];
__device__ __half h_hi     [BB*EE*SELCAP*II];

// ---------------- helpers ----------------
__device__ __forceinline__ float gelu_f(float x) {
    float x3 = x * x * x;
    return 0.5f * x * (1.0f + tanhf(0.7978845608028654f * (x + 0.044715f * x3)));
}
__device__ __forceinline__ void mma_f16(float c[4],
    uint32_t a0, uint32_t a1, uint32_t a2, uint32_t a3,
    uint32_t b0, uint32_t b1)
{
    asm volatile(
        "mma.sync.aligned.m16n8k16.row.col.f32.f16.f16.f32 "
        "{%0,%1,%2,%3}, {%4,%5,%6,%7}, {%8,%9}, {%0,%1,%2,%3};"
        : "+f"(c[0]), "+f"(c[1]), "+f"(c[2]), "+f"(c[3])
        : "r"(a0), "r"(a1), "r"(a2), "r"(a3), "r"(b0), "r"(b1));
}
__device__ __forceinline__ void cpa16h(__half* dst, const __half* src, bool valid) {
    uint32_t d = (uint32_t)__cvta_generic_to_shared(dst);
    asm volatile("cp.async.cg.shared.global [%0], [%1], 16, %2;"
                 :: "r"(d), "l"(src), "r"(valid ? 16 : 0));
}

// ---------------- fp16 GEMM (unchanged core) ----------------
template<int BMT, int THREADS, bool GELU_E, bool ATOMIC, bool RES, bool OUT16, bool OUT32>
__device__ __forceinline__ void hgemm(
    __half* smem,
    const __half* __restrict__ A, int lda, const int* __restrict__ arow,
    const __half* __restrict__ Bp, int ldb,
    const float* __restrict__ bias, const float* __restrict__ res,
    float* __restrict__ C32, __half* __restrict__ C16,
    int ldc, const int* __restrict__ crow,
    int M, int N, int K)
{
    constexpr int BN  = 128;
    constexpr int NJ  = 8;
    constexpr int RP  = THREADS / 8;
    constexpr int AP  = BMT / RP;
    constexpr int BP  = (BN + RP - 1) / RP;
    constexpr int NWM = THREADS / 64;
    constexpr int STH = (BMT + BN) * ROWH;
    __half* As[3] = { smem, smem + STH, smem + 2 * STH };
    __half* Bs[3] = { smem + BMT * ROWH, smem + STH + BMT * ROWH,
                      smem + 2 * STH + BMT * ROWH };

    const int tid  = threadIdx.x;
    const int lane = tid & 31, warp = tid >> 5;
    const int wm = (warp % NWM) * 32;
    const int wn = (warp / NWM) * 64;
    const int m0 = blockIdx.y * BMT, n0 = blockIdx.x * BN;

    const int sr = tid >> 3;
    const int ch = tid & 7;
    int rowA[AP]; bool valA[AP];
#pragma unroll
    for (int p = 0; p < AP; p++) {
        int gm = m0 + sr + p * RP;
        valA[p] = gm < M;
        rowA[p] = valA[p] ? (arow ? arow[gm] : gm) : 0;
    }
    int rowB[BP]; bool valB[BP];
#pragma unroll
    for (int p = 0; p < BP; p++) {
        int r = sr + p * RP;
        int gn = n0 + r;
        valB[p] = (r < BN) && (gn < N);
        rowB[p] = valB[p] ? gn : 0;
    }

    float c[2][NJ][4];
#pragma unroll
    for (int i = 0; i < 2; i++)
#pragma unroll
        for (int j = 0; j < NJ; j++)
#pragma unroll
            for (int q = 0; q < 4; q++) c[i][j][q] = 0.0f;

    const int KT = K / BKH;

    auto load_tile = [&](int st, int k0) {
        __half* Ad = As[st];
        __half* Bd = Bs[st];
#pragma unroll
        for (int p = 0; p < AP; p++)
            cpa16h(Ad + (sr + p * RP) * ROWH + ch * 8,
                   A + (size_t)rowA[p] * lda + k0 + ch * 8, valA[p]);
#pragma unroll
        for (int p = 0; p < BP; p++) {
            int r = sr + p * RP;
            if (r < BN)
                cpa16h(Bd + r * ROWH + ch * 8,
                       Bp + (size_t)rowB[p] * ldb + k0 + ch * 8, valB[p]);
        }
    };

    load_tile(0, 0);
    asm volatile("cp.async.commit_group;");
    if (KT > 1) load_tile(1, BKH);
    asm volatile("cp.async.commit_group;");

    for (int kt = 0; kt < KT; kt++) {
        asm volatile("cp.async.wait_group 1;");
        __syncthreads();
        const int st = kt % 3;
        if (kt + 2 < KT) load_tile((kt + 2) % 3, (kt + 2) * BKH);
        asm volatile("cp.async.commit_group;");

        const __half* Ab = As[st];
        const __half* Bb = Bs[st];
#pragma unroll
        for (int ks = 0; ks < 4; ks++) {
            const int cc = ks * 16 + 2 * (lane & 3);
            uint32_t a[2][4];
#pragma unroll
            for (int i = 0; i < 2; i++) {
                const int r = wm + i * 16 + (lane >> 2);
                a[i][0] = *(const uint32_t*)&Ab[r * ROWH + cc];
                a[i][1] = *(const uint32_t*)&Ab[(r + 8) * ROWH + cc];
                a[i][2] = *(const uint32_t*)&Ab[r * ROWH + cc + 8];
                a[i][3] = *(const uint32_t*)&Ab[(r + 8) * ROWH + cc + 8];
            }
            uint32_t b[NJ][2];
#pragma unroll
            for (int j = 0; j < NJ; j++) {
                const int bc = wn + j * 8 + (lane >> 2);
                b[j][0] = *(const uint32_t*)&Bb[bc * ROWH + cc];
                b[j][1] = *(const uint32_t*)&Bb[bc * ROWH + cc + 8];
            }
#pragma unroll
            for (int i = 0; i < 2; i++)
#pragma unroll
                for (int j = 0; j < NJ; j++)
                    mma_f16(c[i][j], a[i][0], a[i][1], a[i][2], a[i][3],
                            b[j][0], b[j][1]);
        }
    }

#pragma unroll
    for (int i = 0; i < 2; i++) {
        int rm = m0 + wm + i * 16 + (lane >> 2);
#pragma unroll
        for (int j = 0; j < NJ; j++) {
            int cn = n0 + wn + j * 8 + 2 * (lane & 3);
#pragma unroll
            for (int rr = 0; rr < 2; rr++) {
                int gm = rm + rr * 8;
                if (gm >= M) continue;
                int orow = crow ? crow[gm] : gm;
#pragma unroll
                for (int qq = 0; qq < 2; qq++) {
                    int gn = cn + qq;
                    if (gn >= N) continue;
                    float v = c[i][j][rr * 2 + qq];
                    if (bias) v += bias[gn];
                    if (RES)  v += res[(size_t)gm * ldc + gn];
                    if (GELU_E) v = gelu_f(v);
                    if (ATOMIC) {
                        atomicAdd(&C32[(size_t)orow * ldc + gn], v);
                    } else {
                        if (OUT32) C32[(size_t)orow * ldc + gn] = v;
                        if (OUT16) C16[(size_t)orow * ldc + gn] = __float2half_rn(v);
                    }
                }
            }
        }
    }
}

__global__ __launch_bounds__(256, 2) void k_hg_act(
    const __half* A, int lda, const __half* W, int ldw,
    const float* bias, __half* C16, int ldc, int M, int N, int K)
{
    extern __shared__ __half smh[];
    hgemm<128, 256, false, false, false, true, false>(smh, A, lda, nullptr, W, ldw,
        bias, nullptr, nullptr, C16, ldc, nullptr, M, N, K);
}

__global__ __launch_bounds__(256, 2) void k_hg_proj(
    const __half* A, int lda, const __half* W, int ldw,
    const float* bias, const float* res, float* C32, int ldc, int M, int N, int K)
{
    extern __shared__ __half smh[];
    hgemm<128, 256, false, false, true, false, true>(smh, A, lda, nullptr, W, ldw,
        bias, res, C32, nullptr, ldc, nullptr, M, N, K);
}

__global__ __launch_bounds__(192, 2) void k_hg_moe1(
    const __half* Xt, const __half* Xi, const __half* w1, const float* b1,
    const int* selt, const int* seli, __half* Ht, __half* Hi)
{
    extern __shared__ __half smh[];
    int z = blockIdx.z;
    bool txt = z < BB * EE;
    int g = txt ? z : z - BB * EE;
    int b = g / EE, e = g % EE;
    const __half* X = txt ? Xt + (size_t)b * TT * HH : Xi + (size_t)b * VV * HH;
    const int* sel = (txt ? selt : seli) + g * SELCAP;
    __half* H = (txt ? Ht : Hi) + (size_t)g * SELCAP * II;
    int ksel = txt ? KSEL_T : KSEL_V;
    hgemm<96, 192, true, false, false, true, false>(smh, X, HH, sel,
        w1 + (size_t)e * II * HH, HH, b1 + (size_t)e * II, nullptr,
        nullptr, H, II, nullptr, ksel, II, HH);
}

__global__ __launch_bounds__(192, 2) void k_hg_moe2(
    const __half* Ht, const __half* Hi, const __half* w2, const float* b2,
    const int* selt, const int* seli, float* AccT, float* AccI)
{
    extern __shared__ __half smh[];
    int z = blockIdx.z;
    bool txt = z < BB * EE;
    int g = txt ? z : z - BB * EE;
    int b = g / EE, e = g % EE;
    const __half* H = (txt ? Ht : Hi) + (size_t)g * SELCAP * II;
    const int* sel = (txt ? selt : seli) + g * SELCAP;
    float* Acc = txt ? AccT + (size_t)b * TT * HH : AccI + (size_t)b * VV * HH;
    int ksel = txt ? KSEL_T : KSEL_V;
    hgemm<96, 192, false, true, false, false, false>(smh, H, II, nullptr,
        w2 + (size_t)e * HH * II, II, b2 + (size_t)e * HH, nullptr,
        Acc, nullptr, HH, sel, ksel, HH, II);
}

// ---------------- fused flash attention (unchanged) ----------------
#define FL_SMEM ((128 * ROWH + 4 * 64 * ROWH) * 2)

__global__ __launch_bounds__(256, 1) void k_flash(
    const __half* __restrict__ Qp, int qld, int qbs,
    const __half* __restrict__ Kp, int kld, int kbs,
    const __half* __restrict__ Vt,
    __half* __restrict__ O, int Tq, int Skv)
{
    extern __shared__ __half sm[];
    __half* Qs = sm;
    __half* Ks[2] = { sm + 128 * ROWH, sm + 128 * ROWH + 64 * ROWH };
    __half* Vs[2] = { sm + 128 * ROWH + 2 * 64 * ROWH,
                      sm + 128 * ROWH + 3 * 64 * ROWH };

    const int z = blockIdx.z, b = z / NHH, h = z % NHH;
    const __half* Qb = Qp + (size_t)b * qbs + h * HDD;
    const __half* Kb = Kp + (size_t)b * kbs + h * HDD;
    const __half* Vb = Vt + (size_t)z * HDD * Skv;
    __half* Ob = O + (size_t)b * Tq * HH + h * HDD;

    const int tid = threadIdx.x, lane = tid & 31, warp = tid >> 5;
    const int m0 = blockIdx.x * 128;
    const int sr = tid >> 3, ch = tid & 7;

    auto loadKV = [&](int buf, int s0) {
#pragma unroll
        for (int p = 0; p < 2; p++)
            cpa16h(Ks[buf] + (sr + p * 32) * ROWH + ch * 8,
                   Kb + (size_t)(s0 + sr + p * 32) * kld + ch * 8, true);
#pragma unroll
        for (int p = 0; p < 2; p++)
            cpa16h(Vs[buf] + (sr + p * 32) * ROWH + ch * 8,
                   Vb + (size_t)(sr + p * 32) * Skv + s0 + ch * 8, true);
    };

#pragma unroll
    for (int p = 0; p < 4; p++)
        cpa16h(Qs + (sr + p * 32) * ROWH + ch * 8,
               Qb + (size_t)(m0 + sr + p * 32) * qld + ch * 8, true);
    loadKV(0, 0);
    asm volatile("cp.async.commit_group;");

    uint32_t qa[4][4];
    float o[8][4];
#pragma unroll
    for (int j = 0; j < 8; j++)
#pragma unroll
        for (int q = 0; q < 4; q++) o[j][q] = 0.0f;
    float m0v = -1.0e30f, m1v = -1.0e30f, l0 = 0.0f, l1 = 0.0f;

    const int nchunks = Skv / 64;
    for (int s = 0; s < nchunks; s++) {
        asm volatile("cp.async.wait_group 0;");
        __syncthreads();
        const int buf = s & 1;
        if (s == 0) {
            const int r = warp * 16 + (lane >> 2);
#pragma unroll
            for (int ks = 0; ks < 4; ks++) {
                const int cc = ks * 16 + 2 * (lane & 3);
                qa[ks][0] = *(const uint32_t*)&Qs[r * ROWH + cc];
                qa[ks][1] = *(const uint32_t*)&Qs[(r + 8) * ROWH + cc];
                qa[ks][2] = *(const uint32_t*)&Qs[r * ROWH + cc + 8];
                qa[ks][3] = *(const uint32_t*)&Qs[(r + 8) * ROWH + cc + 8];
            }
        }
        if (s + 1 < nchunks) loadKV(buf ^ 1, (s + 1) * 64);
        asm volatile("cp.async.commit_group;");

        float sc[8][4];
#pragma unroll
        for (int j = 0; j < 8; j++)
#pragma unroll
            for (int q = 0; q < 4; q++) sc[j][q] = 0.0f;
        const __half* Kc = Ks[buf];
#pragma unroll
        for (int ks = 0; ks < 4; ks++) {
            const int cc = ks * 16 + 2 * (lane & 3);
#pragma unroll
            for (int j = 0; j < 8; j++) {
                const int bc = j * 8 + (lane >> 2);
                uint32_t b0 = *(const uint32_t*)&Kc[bc * ROWH + cc];
                uint32_t b1 = *(const uint32_t*)&Kc[bc * ROWH + cc + 8];
                mma_f16(sc[j], qa[ks][0], qa[ks][1], qa[ks][2], qa[ks][3], b0, b1);
            }
        }
        float rm0 = -1.0e30f, rm1 = -1.0e30f;
#pragma unroll
        for (int j = 0; j < 8; j++) {
#pragma unroll
            for (int q = 0; q < 4; q++) sc[j][q] *= 0.125f;
            rm0 = fmaxf(rm0, fmaxf(sc[j][0], sc[j][1]));
            rm1 = fmaxf(rm1, fmaxf(sc[j][2], sc[j][3]));
        }
#pragma unroll
        for (int off = 1; off <= 2; off <<= 1) {
            rm0 = fmaxf(rm0, __shfl_xor_sync(0xffffffffu, rm0, off));
            rm1 = fmaxf(rm1, __shfl_xor_sync(0xffffffffu, rm1, off));
        }
        float nm0 = fmaxf(m0v, rm0), nm1 = fmaxf(m1v, rm1);
        float cr0 = __expf(m0v - nm0), cr1 = __expf(m1v - nm1);
        m0v = nm0; m1v = nm1;
        float rs0 = 0.0f, rs1 = 0.0f;
#pragma unroll
        for (int j = 0; j < 8; j++) {
            sc[j][0] = __expf(sc[j][0] - nm0);
            sc[j][1] = __expf(sc[j][1] - nm0);
            sc[j][2] = __expf(sc[j][2] - nm1);
            sc[j][3] = __expf(sc[j][3] - nm1);
            rs0 += sc[j][0] + sc[j][1];
            rs1 += sc[j][2] + sc[j][3];
        }
#pragma unroll
        for (int off = 1; off <= 2; off <<= 1) {
            rs0 += __shfl_xor_sync(0xffffffffu, rs0, off);
            rs1 += __shfl_xor_sync(0xffffffffu, rs1, off);
        }
        l0 = l0 * cr0 + rs0;
        l1 = l1 * cr1 + rs1;
#pragma unroll
        for (int j = 0; j < 8; j++) {
            o[j][0] *= cr0; o[j][1] *= cr0;
            o[j][2] *= cr1; o[j][3] *= cr1;
        }
        const __half* Vc = Vs[buf];
#pragma unroll
        for (int ks = 0; ks < 4; ks++) {
            uint32_t a0, a1, a2, a3;
            {
                __half2 t;
                t = __floats2half2_rn(sc[2 * ks][0], sc[2 * ks][1]);     a0 = *(uint32_t*)&t;
                t = __floats2half2_rn(sc[2 * ks][2], sc[2 * ks][3]);     a1 = *(uint32_t*)&t;
                t = __floats2half2_rn(sc[2 * ks + 1][0], sc[2 * ks + 1][1]); a2 = *(uint32_t*)&t;
                t = __floats2half2_rn(sc[2 * ks + 1][2], sc[2 * ks + 1][3]); a3 = *(uint32_t*)&t;
            }
            const int cc = ks * 16 + 2 * (lane & 3);
#pragma unroll
            for (int jd = 0; jd < 8; jd++) {
                const int bc = jd * 8 + (lane >> 2);
                uint32_t b0 = *(const uint32_t*)&Vc[bc * ROWH + cc];
                uint32_t b1 = *(const uint32_t*)&Vc[bc * ROWH + cc + 8];
                mma_f16(o[jd], a0, a1, a2, a3, b0, b1);
            }
        }
    }

    const float iv0 = 1.0f / l0, iv1 = 1.0f / l1;
    const int r0 = m0 + warp * 16 + (lane >> 2);
#pragma unroll
    for (int jd = 0; jd < 8; jd++) {
        const int col = jd * 8 + 2 * (lane & 3);
        Ob[(size_t)r0 * HH + col]       = __float2half_rn(o[jd][0] * iv0);
        Ob[(size_t)r0 * HH + col + 1]   = __float2half_rn(o[jd][1] * iv0);
        Ob[(size_t)(r0 + 8) * HH + col]     = __float2half_rn(o[jd][2] * iv1);
        Ob[(size_t)(r0 + 8) * HH + col + 1] = __float2half_rn(o[jd][3] * iv1);
    }
}

// ---------------- merged fp32->fp16 conversion (all 7 segments) ------------
#define SEG0 (3*HH*HH)
#define SEG1 (HH*HH)
#define SEG2 (3*HH*HH)
#define SEG3 (HH*HH)
#define SEG4 (EE*II*HH)
#define SEG5 (EE*HH*II)
#define SEG6 (BB*VV*HH)
#define F2H_TOTAL (SEG0+SEG1+SEG2+SEG3+SEG4+SEG5+SEG6)

__global__ void k_f2h_all(
    const float* s0, const float* s1, const float* s2, const float* s3,
    const float* s4, const float* s5, const float* s6,
    __half* d0, __half* d1, __half* d2, __half* d3,
    __half* d4, __half* d5, __half* d6)
{
    int i = (blockIdx.x * 256 + threadIdx.x) * 4;
    if (i >= F2H_TOTAL) return;
    const float* src; __half* dst; int off;
    if      (i < SEG0)                       { src = s0; dst = d0; off = i; }
    else if (i < SEG0+SEG1)                  { src = s1; dst = d1; off = i - SEG0; }
    else if (i < SEG0+SEG1+SEG2)             { src = s2; dst = d2; off = i - SEG0-SEG1; }
    else if (i < SEG0+SEG1+SEG2+SEG3)        { src = s3; dst = d3; off = i - SEG0-SEG1-SEG2; }
    else if (i < SEG0+SEG1+SEG2+SEG3+SEG4)   { src = s4; dst = d4; off = i - SEG0-SEG1-SEG2-SEG3; }
    else if (i < SEG0+SEG1+SEG2+SEG3+SEG4+SEG5)
                                             { src = s5; dst = d5; off = i - SEG0-SEG1-SEG2-SEG3-SEG4; }
    else                                     { src = s6; dst = d6; off = i - SEG0-SEG1-SEG2-SEG3-SEG4-SEG5; }
    float4 v = *(const float4*)(src + off);
    *(__half2*)(dst + off)     = __floats2half2_rn(v.x, v.y);
    *(__half2*)(dst + off + 2) = __floats2half2_rn(v.z, v.w);
}

// ---------------- V transpose (fp16) ----------------
__global__ void k_transp(const __half* __restrict__ X, int ldx,
                         __half* __restrict__ Y, int S)
{
    __shared__ float t[32][33];
    int z = blockIdx.z; int b = z >> 4, h = z & 15;
    int t0 = blockIdx.x * 32, d0 = blockIdx.y * 32;
    const __half* src = X + ((size_t)b * S) * ldx + h * HDD;
#pragma unroll
    for (int k2 = 0; k2 < 4; k2++) {
        int tt = t0 + threadIdx.y + k2 * 8;
        t[threadIdx.y + k2 * 8][threadIdx.x] =
            __half2float(src[(size_t)tt * ldx + d0 + threadIdx.x]);
    }
    __syncthreads();
    __half* dst = Y + ((size_t)z * HDD) * S;
#pragma unroll
    for (int k2 = 0; k2 < 4; k2++) {
        int d = d0 + threadIdx.y + k2 * 8;
        dst[(size_t)d * S + t0 + threadIdx.x] =
            __float2half_rn(t[threadIdx.x][threadIdx.y + k2 * 8]);
    }
}

// ---------------- layernorm ----------------
__global__ void k_ln(const float* X, const float* gg, const float* bb,
                     __half* Y, float* accz)
{
    int r = blockIdx.x;
    const float* x = X + (size_t)r * HH;
    __half* y = Y + (size_t)r * HH;
    int tid = threadIdx.x;
    if (accz) {
        float* az = accz + (size_t)r * HH;
        for (int i = tid; i < HH; i += 256) az[i] = 0.0f;
    }
    float s = 0.0f, s2 = 0.0f;
    for (int i = tid; i < HH; i += 256) { float v = x[i]; s += v; s2 += v * v; }
    __shared__ float r1[256], r2[256];
    r1[tid] = s; r2[tid] = s2; __syncthreads();
    for (int st = 128; st; st >>= 1) {
        if (tid < st) { r1[tid] += r1[tid + st]; r2[tid] += r2[tid + st]; }
        __syncthreads();
    }
    float mean = r1[0] * (1.0f / HH);
    float var  = r2[0] * (1.0f / HH) - mean * mean;
    float rstd = rsqrtf(var + LN_EPS);
    for (int i = tid; i < HH; i += 256)
        y[i] = __float2half_rn((x[i] - mean) * rstd * gg[i] + bb[i]);
}

// ---------------- merged means + ctxbias ----------------
__global__ void k_mean2(const float* Xi, const float* Xt,
                        float* ctx_i, float* ctx_t)
{
    int b = blockIdx.y;
    int c = blockIdx.x * 256 + threadIdx.x;
    if (blockIdx.z == 0) {
        float s = 0.0f;
        for (int j = 0; j < VV; j++) s += Xi[(size_t)(b * VV + j) * HH + c];
        ctx_i[b * HH + c] = s / (float)VV;
    } else {
        float s = 0.0f;
        for (int j = 0; j < LL; j++) s += Xt[(size_t)(b * LL + j) * HH + c];
        ctx_t[b * HH + c] = s / (float)LL;
    }
}

__global__ void k_ctxbias2(const float* ctx_t, const float* ctx_i,
                           const float* gw_i, const float* gb_i,
                           const float* gw_t, const float* gb_t,
                           float* out_i, float* out_t)
{
    // one warp per (stream, b, e): 64 warps total
    int w = blockIdx.x * 8 + (threadIdx.x >> 5);
    int lane = threadIdx.x & 31;
    if (w >= 2 * BB * EE) return;
    bool first = w < BB * EE;                 // first: img gate uses text ctx
    int g = first ? w : w - BB * EE;
    int b = g / EE, e = g % EE;
    const float* ctx = first ? ctx_t : ctx_i;
    const float* gw  = first ? gw_i : gw_t;
    const float* gb  = first ? gb_i : gb_t;
    float* outp      = first ? out_i : out_t;
    float s = 0.0f;
    for (int c = lane; c < HH; c += 32)
        s += ctx[b * HH + c] * gw[(size_t)e * 2 * HH + HH + c];
#pragma unroll
    for (int o = 16; o; o >>= 1) s += __shfl_xor_sync(0xffffffffu, s, o);
    if (lane == 0) outp[g] = s + gb[e];
}

// ---------------- warp-per-token gate (both streams) ----------------
__global__ __launch_bounds__(256) void k_gate_all(
    const float* __restrict__ Xi, const float* __restrict__ Xt,
    const float* __restrict__ gw_i, const float* __restrict__ gw_t,
    const float* __restrict__ cb_i, const float* __restrict__ cb_t,
    float* __restrict__ probs_i, float* __restrict__ probs_t,
    int* __restrict__ cnt_i, int* __restrict__ cnt_t,
    float* __restrict__ acc_i)
{
    const int NTI = BB * VV;                  // image tokens first
    int w = blockIdx.x * 8 + (threadIdx.x >> 5);
    int lane = threadIdx.x & 31;
    if (w >= NTI + BB * TT) return;
    bool img = w < NTI;
    int t = img ? w : w - NTI;
    int S = img ? VV : TT;
    int b = t / S;
    const float* x = (img ? Xi : Xt) + (size_t)t * HH;
    const float* gw = img ? gw_i : gw_t;
    const float* cb = img ? cb_i : cb_t;
    float* probs = img ? probs_i : probs_t;
    int* cnt = img ? cnt_i : cnt_t;
    if (lane == 0) cnt[t] = 0;
    if (img) {
        float* az = acc_i + (size_t)t * HH;
        for (int i = lane; i < HH; i += 32) az[i] = 0.0f;
    }
    float acc[EE];
#pragma unroll
    for (int e = 0; e < EE; e++) acc[e] = 0.0f;
    for (int c = lane; c < HH; c += 32) {
        float xv = x[c];
#pragma unroll
        for (int e = 0; e < EE; e++) acc[e] += xv * gw[(size_t)e * 2 * HH + c];
    }
#pragma unroll
    for (int e = 0; e < EE; e++) {
#pragma unroll
        for (int o = 16; o; o >>= 1)
            acc[e] += __shfl_xor_sync(0xffffffffu, acc[e], o);
    }
    if (lane == 0) {
        float lg[EE];
#pragma unroll
        for (int e = 0; e < EE; e++) lg[e] = acc[e] + cb[b * EE + e];
        float mx = lg[0];
#pragma unroll
        for (int e = 1; e < EE; e++) mx = fmaxf(mx, lg[e]);
        float sum = 0.0f, ex[EE];
#pragma unroll
        for (int e = 0; e < EE; e++) { ex[e] = expf(lg[e] - mx); sum += ex[e]; }
        float inv = 1.0f / sum;
#pragma unroll
        for (int e = 0; e < EE; e++) probs[(size_t)t * EE + e] = ex[e] * inv;
    }
}

// ---------------- warp-per-group top-k (both streams) ----------------
#define NVMAX 18
__global__ __launch_bounds__(256) void k_topk_all(
    const float* __restrict__ probs_t, const float* __restrict__ probs_i,
    int* __restrict__ sel_t, int* __restrict__ sel_i,
    int* __restrict__ cnt_t, int* __restrict__ cnt_i)
{
    __shared__ int sels[8][SELCAP];
    int w = blockIdx.x * 8 + (threadIdx.x >> 5);   // 0..63
    int wl = threadIdx.x >> 5;
    int lane = threadIdx.x & 31;
    bool txt = w < BB * EE;
    int g = txt ? w : w - BB * EE;
    int b = g / EE, e = g % EE;
    int S = txt ? TT : VV;
    int ksel = txt ? KSEL_T : KSEL_V;
    const float* probs = txt ? probs_t : probs_i;
    int* sel = (txt ? sel_t : sel_i) + g * SELCAP;
    int* cnt = (txt ? cnt_t : cnt_i) + b * S;

    float v[NVMAX];
    const int NV = (S + 31) / 32;
#pragma unroll
    for (int j = 0; j < NVMAX; j++) {
        int idx = lane + j * 32;
        v[j] = (j < NV && idx < S)
             ? probs[(size_t)(b * S + idx) * EE + e] : -1.0e30f;
    }
    for (int it = 0; it < ksel; it++) {
        float bv = -2.0e30f; int bj = 0;
#pragma unroll
        for (int j = 0; j < NVMAX; j++)
            if (j < NV && v[j] > bv) { bv = v[j]; bj = j; }
        int bi = lane + bj * 32;
#pragma unroll
        for (int o = 16; o; o >>= 1) {
            float ov = __shfl_xor_sync(0xffffffffu, bv, o);
            int   oi = __shfl_xor_sync(0xffffffffu, bi, o);
            if (ov > bv || (ov == bv && oi < bi)) { bv = ov; bi = oi; }
        }
        if (lane == (bi & 31)) v[bi >> 5] = -1.0e30f;
        if (lane == 0) sels[wl][it] = bi;
    }
    __syncwarp();
    for (int i = lane; i < ksel; i += 32) {
        int tok = sels[wl][i];
        sel[i] = tok;
        atomicAdd(&cnt[tok], 1);
    }
}

// ---------------- merged combine ----------------
__global__ void k_combine2(
    const float* baseT, const float* accT, const int* cntT, float* outT,
    const float* baseI, const float* accI, const int* cntI, float* outI)
{
    const int NT = BB * TT * HH;
    int i = blockIdx.x * 256 + threadIdx.x;
    if (i < NT) {
        int tok = i / HH;
        outT[i] = baseT[i] + accT[i] / fmaxf((float)cntT[tok], 1.0f);
    } else {
        int k = i - NT;
        if (k < BB * VV * HH) {
            int tok = k / HH;
            outI[k] = baseI[k] + accI[k] / fmaxf((float)cntI[tok], 1.0f);
        }
    }
}

// ---------------- launch ----------------
#define SMEMH128 (3 * (128 + 128) * ROWH * 2)
#define SMEMH96  (3 * (96 + 128) * ROWH * 2)

extern "C" void kernel_launch(void* const* d_in, const int* in_sizes, int n_in,
                              void* d_out, int out_size)
{
    (void)in_sizes; (void)n_in; (void)out_size;
    const float* in_q      = (const float*)d_in[0];
    const float* in_img    = (const float*)d_in[1];
    const float* in_txt    = (const float*)d_in[2];
    const float* sa_w_in   = (const float*)d_in[3];
    const float* sa_b_in   = (const float*)d_in[4];
    const float* sa_w_out  = (const float*)d_in[5];
    const float* sa_b_out  = (const float*)d_in[6];
    const float* ca_w_in   = (const float*)d_in[7];
    const float* ca_b_in   = (const float*)d_in[8];
    const float* ca_w_out  = (const float*)d_in[9];
    const float* ca_b_out  = (const float*)d_in[10];
    const float* gate_img_w= (const float*)d_in[11];
    const float* gate_img_b= (const float*)d_in[12];
    const float* gate_txt_w= (const float*)d_in[13];
    const float* gate_txt_b= (const float*)d_in[14];
    const float* e_w1      = (const float*)d_in[15];
    const float* e_b1      = (const float*)d_in[16];
    const float* e_w2      = (const float*)d_in[17];
    const float* e_b2      = (const float*)d_in[18];
    const float* lnq_g     = (const float*)d_in[19];
    const float* lnq_b     = (const float*)d_in[20];
    const float* lnc_g     = (const float*)d_in[21];
    const float* lnc_b     = (const float*)d_in[22];
    const float* lnf_g     = (const float*)d_in[23];
    const float* lnf_b     = (const float*)d_in[24];
    float* out_q   = (float*)d_out;
    float* out_img = out_q + (size_t)BB * TT * HH;

    float *p_q, *p_acc_t, *p_acc_i;
    float *p_ctx_img, *p_ctx_txt, *p_gb_img, *p_gb_txt, *p_probs_t, *p_probs_i;
    int *p_sel_t, *p_sel_i, *p_cnt_t, *p_cnt_i;
    __half *ph_sain, *ph_saout, *ph_cain, *ph_caout, *ph_e1, *ph_e2;
    __half *ph_img, *ph_ln, *ph_qkv, *ph_cq, *ph_kv, *ph_vt, *ph_attn;
    __half *ph_ht, *ph_hi;
    cudaGetSymbolAddress((void**)&p_q, g_q);
    cudaGetSymbolAddress((void**)&p_acc_t, g_acc_t);
    cudaGetSymbolAddress((void**)&p_acc_i, g_acc_i);
    cudaGetSymbolAddress((void**)&p_ctx_img, g_ctx_img);
    cudaGetSymbolAddress((void**)&p_ctx_txt, g_ctx_txt);
    cudaGetSymbolAddress((void**)&p_gb_img, g_gb_img);
    cudaGetSymbolAddress((void**)&p_gb_txt, g_gb_txt);
    cudaGetSymbolAddress((void**)&p_probs_t, g_probs_t);
    cudaGetSymbolAddress((void**)&p_probs_i, g_probs_i);
    cudaGetSymbolAddress((void**)&p_sel_t, g_sel_t);
    cudaGetSymbolAddress((void**)&p_sel_i, g_sel_i);
    cudaGetSymbolAddress((void**)&p_cnt_t, g_cnt_t);
    cudaGetSymbolAddress((void**)&p_cnt_i, g_cnt_i);
    cudaGetSymbolAddress((void**)&ph_sain, h_w_sain);
    cudaGetSymbolAddress((void**)&ph_saout, h_w_saout);
    cudaGetSymbolAddress((void**)&ph_cain, h_w_cain);
    cudaGetSymbolAddress((void**)&ph_caout, h_w_caout);
    cudaGetSymbolAddress((void**)&ph_e1, h_w_e1);
    cudaGetSymbolAddress((void**)&ph_e2, h_w_e2);
    cudaGetSymbolAddress((void**)&ph_img, h_img);
    cudaGetSymbolAddress((void**)&ph_ln, h_ln);
    cudaGetSymbolAddress((void**)&ph_qkv, h_qkv);
    cudaGetSymbolAddress((void**)&ph_cq, h_cq);
    cudaGetSymbolAddress((void**)&ph_kv, h_kv);
    cudaGetSymbolAddress((void**)&ph_vt, h_vt);
    cudaGetSymbolAddress((void**)&ph_attn, h_attn);
    cudaGetSymbolAddress((void**)&ph_ht, h_ht);
    cudaGetSymbolAddress((void**)&ph_hi, h_hi);

    cudaFuncSetAttribute(k_hg_act,  cudaFuncAttributeMaxDynamicSharedMemorySize, SMEMH128);
    cudaFuncSetAttribute(k_hg_proj, cudaFuncAttributeMaxDynamicSharedMemorySize, SMEMH128);
    cudaFuncSetAttribute(k_hg_moe1, cudaFuncAttributeMaxDynamicSharedMemorySize, SMEMH96);
    cudaFuncSetAttribute(k_hg_moe2, cudaFuncAttributeMaxDynamicSharedMemorySize, SMEMH96);
    cudaFuncSetAttribute(k_flash,   cudaFuncAttributeMaxDynamicSharedMemorySize, FL_SMEM);

    // ---- all conversions in one launch ----
    k_f2h_all<<<(F2H_TOTAL / 4 + 255) / 256, 256>>>(
        sa_w_in, sa_w_out, ca_w_in, ca_w_out, e_w1, e_w2, in_img,
        ph_sain, ph_saout, ph_cain, ph_caout, ph_e1, ph_e2, ph_img);

    // ---- self attention ----
    k_ln<<<BB * TT, 256>>>(in_q, lnq_g, lnq_b, ph_ln, nullptr);
    k_hg_act<<<dim3(3 * HH / 128, BB * TT / 128), 256, SMEMH128>>>(
        ph_ln, HH, ph_sain, HH, sa_b_in, ph_qkv, 3 * HH, BB * TT, 3 * HH, HH);
    k_transp<<<dim3(TT / 32, 2, BB * NHH), dim3(32, 8)>>>(
        ph_qkv + 2 * HH, 3 * HH, ph_vt, TT);
    k_flash<<<dim3(TT / 128, 1, BB * NHH), 256, FL_SMEM>>>(
        ph_qkv, 3 * HH, TT * 3 * HH, ph_qkv + HH, 3 * HH, TT * 3 * HH,
        ph_vt, ph_attn, TT, TT);
    k_hg_proj<<<dim3(HH / 128, BB * TT / 128), 256, SMEMH128>>>(
        ph_attn, HH, ph_saout, HH, sa_b_out, in_q, p_q, HH, BB * TT, HH, HH);

    // ---- cross attention ----
    k_ln<<<BB * TT, 256>>>(p_q, lnc_g, lnc_b, ph_ln, nullptr);
    k_hg_act<<<dim3(HH / 128, BB * TT / 128), 256, SMEMH128>>>(
        ph_ln, HH, ph_cain, HH, ca_b_in, ph_cq, HH, BB * TT, HH, HH);
    k_hg_act<<<dim3(2 * HH / 128, BB * VV / 128), 256, SMEMH128>>>(
        ph_img, HH, ph_cain + (size_t)HH * HH, HH, ca_b_in + HH,
        ph_kv, 2 * HH, BB * VV, 2 * HH, HH);
    k_transp<<<dim3(VV / 32, 2, BB * NHH), dim3(32, 8)>>>(
        ph_kv + HH, 2 * HH, ph_vt, VV);
    k_flash<<<dim3(TT / 128, 1, BB * NHH), 256, FL_SMEM>>>(
        ph_cq, HH, TT * HH, ph_kv, 2 * HH, VV * 2 * HH,
        ph_vt, ph_attn, TT, VV);
    k_hg_proj<<<dim3(HH / 128, BB * TT / 128), 256, SMEMH128>>>(
        ph_attn, HH, ph_caout, HH, ca_b_out, p_q, p_q, HH, BB * TT, HH, HH);

    // ---- gating ----
    k_mean2<<<dim3(HH / 256, BB, 2), 256>>>(in_img, in_txt, p_ctx_img, p_ctx_txt);
    k_ctxbias2<<<(2 * BB * EE + 7) / 8, 256>>>(
        p_ctx_txt, p_ctx_img, gate_img_w, gate_img_b, gate_txt_w, gate_txt_b,
        p_gb_img, p_gb_txt);
    k_gate_all<<<(BB * VV + BB * TT + 7) / 8, 256>>>(
        in_img, p_q, gate_img_w, gate_txt_w, p_gb_img, p_gb_txt,
        p_probs_i, p_probs_t, p_cnt_i, p_cnt_t, p_acc_i);
    k_topk_all<<<(2 * BB * EE + 7) / 8, 256>>>(
        p_probs_t, p_probs_i, p_sel_t, p_sel_i, p_cnt_t, p_cnt_i);

    // ---- MoE ----
    k_ln<<<BB * TT, 256>>>(p_q, lnf_g, lnf_b, ph_ln, p_acc_t);
    k_hg_moe1<<<dim3(II / 128, 1, 2 * BB * EE), 192, SMEMH96>>>(
        ph_ln, ph_img, ph_e1, e_b1, p_sel_t, p_sel_i, ph_ht, ph_hi);
    k_hg_moe2<<<dim3(HH / 128, 1, 2 * BB * EE), 192, SMEMH96>>>(
        ph_ht, ph_hi, ph_e2, e_b2, p_sel_t, p_sel_i, p_acc_t, p_acc_i);
    k_combine2<<<((BB * TT + BB * VV) * HH + 255) / 256, 256>>>(
        p_q, p_acc_t, p_cnt_t, out_q, in_img, p_acc_i, p_cnt_i, out_img);
}

// round 12
// speedup vs baseline: 1.9782x; 1.0375x over previous
#include <cuda_runtime.h>
#include <cuda_fp16.h>
#include <math.h>
#include <stdint.h>

// ---------------- problem constants ----------------
#define BB   4
#define TT   512
#define VV   576
#define LL   256
#define HH   1024
#define NHH  16
#define HDD  64
#define II   4096
#define EE   8
#define KSEL_T 80
#define KSEL_V 90
#define SELCAP 96
#define LN_EPS 1e-5f

#define BKH  64
#define ROWH 72

// ---------------- fp32 scratch ----------------
__device__ float g_q     [BB*TT*HH];
__device__ float g_acc_t [BB*TT*HH];
__device__ float g_acc_i [BB*VV*HH];
__device__ float g_ctx_img[BB*HH];
__device__ float g_ctx_txt[BB*HH];
__device__ float g_gb_img[BB*EE];
__device__ float g_gb_txt[BB*EE];
__device__ float g_probs_t[BB*TT*EE];
__device__ float g_probs_i[BB*VV*EE];
__device__ int   g_sel_t[BB*EE*SELCAP];
__device__ int   g_sel_i[BB*EE*SELCAP];
__device__ int   g_cnt_t[BB*TT];
__device__ int   g_cnt_i[BB*VV];

// ---------------- fp16 scratch ----------------
__device__ __half h_w_sain [3*HH*HH];
__device__ __half h_w_saout[HH*HH];
__device__ __half h_w_cain [3*HH*HH];
__device__ __half h_w_caout[HH*HH];
__device__ __half h_w_e1   [EE*II*HH];
__device__ __half h_w_e2   [EE*HH*II];
__device__ __half h_img    [BB*VV*HH];
__device__ __half h_ln     [BB*TT*HH];
__device__ __half h_qkv    [BB*TT*3*HH];
__device__ __half h_cq     [BB*TT*HH];
__device__ __half h_kv     [BB*VV*2*HH];
__device__ __half h_vt     [BB*NHH*HDD*VV];
__device__ __half h_vt2    [BB*NHH*HDD*VV];
__device__ __half h_attn   [BB*TT*HH];
__device__ __half h_ht     [BB*EE*SELCAP*II];
__device__ __half h_hi     [BB*EE*SELCAP*II];

// ---------------- helpers ----------------
__device__ __forceinline__ float gelu_f(float x) {
    float x3 = x * x * x;
    return 0.5f * x * (1.0f + tanhf(0.7978845608028654f * (x + 0.044715f * x3)));
}
__device__ __forceinline__ void mma_f16(float c[4],
    uint32_t a0, uint32_t a1, uint32_t a2, uint32_t a3,
    uint32_t b0, uint32_t b1)
{
    asm volatile(
        "mma.sync.aligned.m16n8k16.row.col.f32.f16.f16.f32 "
        "{%0,%1,%2,%3}, {%4,%5,%6,%7}, {%8,%9}, {%0,%1,%2,%3};"
        : "+f"(c[0]), "+f"(c[1]), "+f"(c[2]), "+f"(c[3])
        : "r"(a0), "r"(a1), "r"(a2), "r"(a3), "r"(b0), "r"(b1));
}
__device__ __forceinline__ void cpa16h(__half* dst, const __half* src, bool valid) {
    uint32_t d = (uint32_t)__cvta_generic_to_shared(dst);
    asm volatile("cp.async.cg.shared.global [%0], [%1], 16, %2;"
                 :: "r"(d), "l"(src), "r"(valid ? 16 : 0));
}

// ---------------- fp16 GEMM (unchanged core) ----------------
template<int BMT, int THREADS, bool GELU_E, bool ATOMIC, bool RES, bool OUT16, bool OUT32>
__device__ __forceinline__ void hgemm(
    __half* smem,
    const __half* __restrict__ A, int lda, const int* __restrict__ arow,
    const __half* __restrict__ Bp, int ldb,
    const float* __restrict__ bias, const float* __restrict__ res,
    float* __restrict__ C32, __half* __restrict__ C16,
    int ldc, const int* __restrict__ crow,
    int M, int N, int K)
{
    constexpr int BN  = 128;
    constexpr int NJ  = 8;
    constexpr int RP  = THREADS / 8;
    constexpr int AP  = BMT / RP;
    constexpr int BP  = (BN + RP - 1) / RP;
    constexpr int NWM = THREADS / 64;
    constexpr int STH = (BMT + BN) * ROWH;
    __half* As[3] = { smem, smem + STH, smem + 2 * STH };
    __half* Bs[3] = { smem + BMT * ROWH, smem + STH + BMT * ROWH,
                      smem + 2 * STH + BMT * ROWH };

    const int tid  = threadIdx.x;
    const int lane = tid & 31, warp = tid >> 5;
    const int wm = (warp % NWM) * 32;
    const int wn = (warp / NWM) * 64;
    const int m0 = blockIdx.y * BMT, n0 = blockIdx.x * BN;

    const int sr = tid >> 3;
    const int ch = tid & 7;
    int rowA[AP]; bool valA[AP];
#pragma unroll
    for (int p = 0; p < AP; p++) {
        int gm = m0 + sr + p * RP;
        valA[p] = gm < M;
        rowA[p] = valA[p] ? (arow ? arow[gm] : gm) : 0;
    }
    int rowB[BP]; bool valB[BP];
#pragma unroll
    for (int p = 0; p < BP; p++) {
        int r = sr + p * RP;
        int gn = n0 + r;
        valB[p] = (r < BN) && (gn < N);
        rowB[p] = valB[p] ? gn : 0;
    }

    float c[2][NJ][4];
#pragma unroll
    for (int i = 0; i < 2; i++)
#pragma unroll
        for (int j = 0; j < NJ; j++)
#pragma unroll
            for (int q = 0; q < 4; q++) c[i][j][q] = 0.0f;

    const int KT = K / BKH;

    auto load_tile = [&](int st, int k0) {
        __half* Ad = As[st];
        __half* Bd = Bs[st];
#pragma unroll
        for (int p = 0; p < AP; p++)
            cpa16h(Ad + (sr + p * RP) * ROWH + ch * 8,
                   A + (size_t)rowA[p] * lda + k0 + ch * 8, valA[p]);
#pragma unroll
        for (int p = 0; p < BP; p++) {
            int r = sr + p * RP;
            if (r < BN)
                cpa16h(Bd + r * ROWH + ch * 8,
                       Bp + (size_t)rowB[p] * ldb + k0 + ch * 8, valB[p]);
        }
    };

    load_tile(0, 0);
    asm volatile("cp.async.commit_group;");
    if (KT > 1) load_tile(1, BKH);
    asm volatile("cp.async.commit_group;");

    for (int kt = 0; kt < KT; kt++) {
        asm volatile("cp.async.wait_group 1;");
        __syncthreads();
        const int st = kt % 3;
        if (kt + 2 < KT) load_tile((kt + 2) % 3, (kt + 2) * BKH);
        asm volatile("cp.async.commit_group;");

        const __half* Ab = As[st];
        const __half* Bb = Bs[st];
#pragma unroll
        for (int ks = 0; ks < 4; ks++) {
            const int cc = ks * 16 + 2 * (lane & 3);
            uint32_t a[2][4];
#pragma unroll
            for (int i = 0; i < 2; i++) {
                const int r = wm + i * 16 + (lane >> 2);
                a[i][0] = *(const uint32_t*)&Ab[r * ROWH + cc];
                a[i][1] = *(const uint32_t*)&Ab[(r + 8) * ROWH + cc];
                a[i][2] = *(const uint32_t*)&Ab[r * ROWH + cc + 8];
                a[i][3] = *(const uint32_t*)&Ab[(r + 8) * ROWH + cc + 8];
            }
            uint32_t b[NJ][2];
#pragma unroll
            for (int j = 0; j < NJ; j++) {
                const int bc = wn + j * 8 + (lane >> 2);
                b[j][0] = *(const uint32_t*)&Bb[bc * ROWH + cc];
                b[j][1] = *(const uint32_t*)&Bb[bc * ROWH + cc + 8];
            }
#pragma unroll
            for (int i = 0; i < 2; i++)
#pragma unroll
                for (int j = 0; j < NJ; j++)
                    mma_f16(c[i][j], a[i][0], a[i][1], a[i][2], a[i][3],
                            b[j][0], b[j][1]);
        }
    }

#pragma unroll
    for (int i = 0; i < 2; i++) {
        int rm = m0 + wm + i * 16 + (lane >> 2);
#pragma unroll
        for (int j = 0; j < NJ; j++) {
            int cn = n0 + wn + j * 8 + 2 * (lane & 3);
#pragma unroll
            for (int rr = 0; rr < 2; rr++) {
                int gm = rm + rr * 8;
                if (gm >= M) continue;
                int orow = crow ? crow[gm] : gm;
#pragma unroll
                for (int qq = 0; qq < 2; qq++) {
                    int gn = cn + qq;
                    if (gn >= N) continue;
                    float v = c[i][j][rr * 2 + qq];
                    if (bias) v += bias[gn];
                    if (RES)  v += res[(size_t)gm * ldc + gn];
                    if (GELU_E) v = gelu_f(v);
                    if (ATOMIC) {
                        atomicAdd(&C32[(size_t)orow * ldc + gn], v);
                    } else {
                        if (OUT32) C32[(size_t)orow * ldc + gn] = v;
                        if (OUT16) C16[(size_t)orow * ldc + gn] = __float2half_rn(v);
                    }
                }
            }
        }
    }
}

__global__ __launch_bounds__(256, 2) void k_hg_act(
    const __half* A, int lda, const __half* W, int ldw,
    const float* bias, __half* C16, int ldc, int M, int N, int K)
{
    extern __shared__ __half smh[];
    hgemm<128, 256, false, false, false, true, false>(smh, A, lda, nullptr, W, ldw,
        bias, nullptr, nullptr, C16, ldc, nullptr, M, N, K);
}

__global__ __launch_bounds__(256, 2) void k_hg_proj(
    const __half* A, int lda, const __half* W, int ldw,
    const float* bias, const float* res, float* C32, int ldc, int M, int N, int K)
{
    extern __shared__ __half smh[];
    hgemm<128, 256, false, false, true, false, true>(smh, A, lda, nullptr, W, ldw,
        bias, res, C32, nullptr, ldc, nullptr, M, N, K);
}

// per-stream MoE kernels (txt flag selects data set)
__global__ __launch_bounds__(192, 2) void k_hg_moe1s(
    const __half* X0, const __half* w1, const float* b1,
    const int* sel0, __half* H0, int S, int ksel)
{
    extern __shared__ __half smh[];
    int g = blockIdx.z;
    int b = g / EE, e = g % EE;
    const __half* X = X0 + (size_t)b * S * HH;
    const int* sel = sel0 + g * SELCAP;
    __half* H = H0 + (size_t)g * SELCAP * II;
    hgemm<96, 192, true, false, false, true, false>(smh, X, HH, sel,
        w1 + (size_t)e * II * HH, HH, b1 + (size_t)e * II, nullptr,
        nullptr, H, II, nullptr, ksel, II, HH);
}

__global__ __launch_bounds__(192, 2) void k_hg_moe2s(
    const __half* H0, const __half* w2, const float* b2,
    const int* sel0, float* Acc0, int S, int ksel)
{
    extern __shared__ __half smh[];
    int g = blockIdx.z;
    int b = g / EE, e = g % EE;
    const __half* H = H0 + (size_t)g * SELCAP * II;
    const int* sel = sel0 + g * SELCAP;
    float* Acc = Acc0 + (size_t)b * S * HH;
    hgemm<96, 192, false, true, false, false, false>(smh, H, II, nullptr,
        w2 + (size_t)e * HH * II, II, b2 + (size_t)e * HH, nullptr,
        Acc, nullptr, HH, sel, ksel, HH, II);
}

// ---------------- fused flash attention (unchanged) ----------------
#define FL_SMEM ((128 * ROWH + 4 * 64 * ROWH) * 2)

__global__ __launch_bounds__(256, 1) void k_flash(
    const __half* __restrict__ Qp, int qld, int qbs,
    const __half* __restrict__ Kp, int kld, int kbs,
    const __half* __restrict__ Vt,
    __half* __restrict__ O, int Tq, int Skv)
{
    extern __shared__ __half sm[];
    __half* Qs = sm;
    __half* Ks[2] = { sm + 128 * ROWH, sm + 128 * ROWH + 64 * ROWH };
    __half* Vs[2] = { sm + 128 * ROWH + 2 * 64 * ROWH,
                      sm + 128 * ROWH + 3 * 64 * ROWH };

    const int z = blockIdx.z, b = z / NHH, h = z % NHH;
    const __half* Qb = Qp + (size_t)b * qbs + h * HDD;
    const __half* Kb = Kp + (size_t)b * kbs + h * HDD;
    const __half* Vb = Vt + (size_t)z * HDD * Skv;
    __half* Ob = O + (size_t)b * Tq * HH + h * HDD;

    const int tid = threadIdx.x, lane = tid & 31, warp = tid >> 5;
    const int m0 = blockIdx.x * 128;
    const int sr = tid >> 3, ch = tid & 7;

    auto loadKV = [&](int buf, int s0) {
#pragma unroll
        for (int p = 0; p < 2; p++)
            cpa16h(Ks[buf] + (sr + p * 32) * ROWH + ch * 8,
                   Kb + (size_t)(s0 + sr + p * 32) * kld + ch * 8, true);
#pragma unroll
        for (int p = 0; p < 2; p++)
            cpa16h(Vs[buf] + (sr + p * 32) * ROWH + ch * 8,
                   Vb + (size_t)(sr + p * 32) * Skv + s0 + ch * 8, true);
    };

#pragma unroll
    for (int p = 0; p < 4; p++)
        cpa16h(Qs + (sr + p * 32) * ROWH + ch * 8,
               Qb + (size_t)(m0 + sr + p * 32) * qld + ch * 8, true);
    loadKV(0, 0);
    asm volatile("cp.async.commit_group;");

    uint32_t qa[4][4];
    float o[8][4];
#pragma unroll
    for (int j = 0; j < 8; j++)
#pragma unroll
        for (int q = 0; q < 4; q++) o[j][q] = 0.0f;
    float m0v = -1.0e30f, m1v = -1.0e30f, l0 = 0.0f, l1 = 0.0f;

    const int nchunks = Skv / 64;
    for (int s = 0; s < nchunks; s++) {
        asm volatile("cp.async.wait_group 0;");
        __syncthreads();
        const int buf = s & 1;
        if (s == 0) {
            const int r = warp * 16 + (lane >> 2);
#pragma unroll
            for (int ks = 0; ks < 4; ks++) {
                const int cc = ks * 16 + 2 * (lane & 3);
                qa[ks][0] = *(const uint32_t*)&Qs[r * ROWH + cc];
                qa[ks][1] = *(const uint32_t*)&Qs[(r + 8) * ROWH + cc];
                qa[ks][2] = *(const uint32_t*)&Qs[r * ROWH + cc + 8];
                qa[ks][3] = *(const uint32_t*)&Qs[(r + 8) * ROWH + cc + 8];
            }
        }
        if (s + 1 < nchunks) loadKV(buf ^ 1, (s + 1) * 64);
        asm volatile("cp.async.commit_group;");

        float sc[8][4];
#pragma unroll
        for (int j = 0; j < 8; j++)
#pragma unroll
            for (int q = 0; q < 4; q++) sc[j][q] = 0.0f;
        const __half* Kc = Ks[buf];
#pragma unroll
        for (int ks = 0; ks < 4; ks++) {
            const int cc = ks * 16 + 2 * (lane & 3);
#pragma unroll
            for (int j = 0; j < 8; j++) {
                const int bc = j * 8 + (lane >> 2);
                uint32_t b0 = *(const uint32_t*)&Kc[bc * ROWH + cc];
                uint32_t b1 = *(const uint32_t*)&Kc[bc * ROWH + cc + 8];
                mma_f16(sc[j], qa[ks][0], qa[ks][1], qa[ks][2], qa[ks][3], b0, b1);
            }
        }
        float rm0 = -1.0e30f, rm1 = -1.0e30f;
#pragma unroll
        for (int j = 0; j < 8; j++) {
#pragma unroll
            for (int q = 0; q < 4; q++) sc[j][q] *= 0.125f;
            rm0 = fmaxf(rm0, fmaxf(sc[j][0], sc[j][1]));
            rm1 = fmaxf(rm1, fmaxf(sc[j][2], sc[j][3]));
        }
#pragma unroll
        for (int off = 1; off <= 2; off <<= 1) {
            rm0 = fmaxf(rm0, __shfl_xor_sync(0xffffffffu, rm0, off));
            rm1 = fmaxf(rm1, __shfl_xor_sync(0xffffffffu, rm1, off));
        }
        float nm0 = fmaxf(m0v, rm0), nm1 = fmaxf(m1v, rm1);
        float cr0 = __expf(m0v - nm0), cr1 = __expf(m1v - nm1);
        m0v = nm0; m1v = nm1;
        float rs0 = 0.0f, rs1 = 0.0f;
#pragma unroll
        for (int j = 0; j < 8; j++) {
            sc[j][0] = __expf(sc[j][0] - nm0);
            sc[j][1] = __expf(sc[j][1] - nm0);
            sc[j][2] = __expf(sc[j][2] - nm1);
            sc[j][3] = __expf(sc[j][3] - nm1);
            rs0 += sc[j][0] + sc[j][1];
            rs1 += sc[j][2] + sc[j][3];
        }
#pragma unroll
        for (int off = 1; off <= 2; off <<= 1) {
            rs0 += __shfl_xor_sync(0xffffffffu, rs0, off);
            rs1 += __shfl_xor_sync(0xffffffffu, rs1, off);
        }
        l0 = l0 * cr0 + rs0;
        l1 = l1 * cr1 + rs1;
#pragma unroll
        for (int j = 0; j < 8; j++) {
            o[j][0] *= cr0; o[j][1] *= cr0;
            o[j][2] *= cr1; o[j][3] *= cr1;
        }
        const __half* Vc = Vs[buf];
#pragma unroll
        for (int ks = 0; ks < 4; ks++) {
            uint32_t a0, a1, a2, a3;
            {
                __half2 t;
                t = __floats2half2_rn(sc[2 * ks][0], sc[2 * ks][1]);     a0 = *(uint32_t*)&t;
                t = __floats2half2_rn(sc[2 * ks][2], sc[2 * ks][3]);     a1 = *(uint32_t*)&t;
                t = __floats2half2_rn(sc[2 * ks + 1][0], sc[2 * ks + 1][1]); a2 = *(uint32_t*)&t;
                t = __floats2half2_rn(sc[2 * ks + 1][2], sc[2 * ks + 1][3]); a3 = *(uint32_t*)&t;
            }
            const int cc = ks * 16 + 2 * (lane & 3);
#pragma unroll
            for (int jd = 0; jd < 8; jd++) {
                const int bc = jd * 8 + (lane >> 2);
                uint32_t b0 = *(const uint32_t*)&Vc[bc * ROWH + cc];
                uint32_t b1 = *(const uint32_t*)&Vc[bc * ROWH + cc + 8];
                mma_f16(o[jd], a0, a1, a2, a3, b0, b1);
            }
        }
    }

    const float iv0 = 1.0f / l0, iv1 = 1.0f / l1;
    const int r0 = m0 + warp * 16 + (lane >> 2);
#pragma unroll
    for (int jd = 0; jd < 8; jd++) {
        const int col = jd * 8 + 2 * (lane & 3);
        Ob[(size_t)r0 * HH + col]       = __float2half_rn(o[jd][0] * iv0);
        Ob[(size_t)r0 * HH + col + 1]   = __float2half_rn(o[jd][1] * iv0);
        Ob[(size_t)(r0 + 8) * HH + col]     = __float2half_rn(o[jd][2] * iv1);
        Ob[(size_t)(r0 + 8) * HH + col + 1] = __float2half_rn(o[jd][3] * iv1);
    }
}

// ---------------- split fp32->fp16 conversions ----------------
// A-side: sain, saout, caout
#define A0 (3*HH*HH)
#define A1 (HH*HH)
#define A2 (HH*HH)
#define F2HA_TOTAL (A0+A1+A2)
__global__ void k_f2h_a(const float* s0, const float* s1, const float* s2,
                        __half* d0, __half* d1, __half* d2)
{
    int i = (blockIdx.x * 256 + threadIdx.x) * 4;
    if (i >= F2HA_TOTAL) return;
    const float* src; __half* dst; int off;
    if      (i < A0)      { src = s0; dst = d0; off = i; }
    else if (i < A0+A1)   { src = s1; dst = d1; off = i - A0; }
    else                  { src = s2; dst = d2; off = i - A0 - A1; }
    float4 v = *(const float4*)(src + off);
    *(__half2*)(dst + off)     = __floats2half2_rn(v.x, v.y);
    *(__half2*)(dst + off + 2) = __floats2half2_rn(v.z, v.w);
}

// B-side: cain, img, e_w1, e_w2
#define B0 (3*HH*HH)
#define B1 (BB*VV*HH)
#define B2 (EE*II*HH)
#define B3 (EE*HH*II)
#define F2HB_TOTAL (B0+B1+B2+B3)
__global__ void k_f2h_b(const float* s0, const float* s1, const float* s2,
                        const float* s3,
                        __half* d0, __half* d1, __half* d2, __half* d3)
{
    int i = (blockIdx.x * 256 + threadIdx.x) * 4;
    if (i >= F2HB_TOTAL) return;
    const float* src; __half* dst; int off;
    if      (i < B0)          { src = s0; dst = d0; off = i; }
    else if (i < B0+B1)       { src = s1; dst = d1; off = i - B0; }
    else if (i < B0+B1+B2)    { src = s2; dst = d2; off = i - B0 - B1; }
    else                      { src = s3; dst = d3; off = i - B0 - B1 - B2; }
    float4 v = *(const float4*)(src + off);
    *(__half2*)(dst + off)     = __floats2half2_rn(v.x, v.y);
    *(__half2*)(dst + off + 2) = __floats2half2_rn(v.z, v.w);
}

// ---------------- V transpose (fp16) ----------------
__global__ void k_transp(const __half* __restrict__ X, int ldx,
                         __half* __restrict__ Y, int S)
{
    __shared__ float t[32][33];
    int z = blockIdx.z; int b = z >> 4, h = z & 15;
    int t0 = blockIdx.x * 32, d0 = blockIdx.y * 32;
    const __half* src = X + ((size_t)b * S) * ldx + h * HDD;
#pragma unroll
    for (int k2 = 0; k2 < 4; k2++) {
        int tt = t0 + threadIdx.y + k2 * 8;
        t[threadIdx.y + k2 * 8][threadIdx.x] =
            __half2float(src[(size_t)tt * ldx + d0 + threadIdx.x]);
    }
    __syncthreads();
    __half* dst = Y + ((size_t)z * HDD) * S;
#pragma unroll
    for (int k2 = 0; k2 < 4; k2++) {
        int d = d0 + threadIdx.y + k2 * 8;
        dst[(size_t)d * S + t0 + threadIdx.x] =
            __float2half_rn(t[threadIdx.x][threadIdx.y + k2 * 8]);
    }
}

// ---------------- layernorm ----------------
__global__ void k_ln(const float* X, const float* gg, const float* bb,
                     __half* Y, float* accz)
{
    int r = blockIdx.x;
    const float* x = X + (size_t)r * HH;
    __half* y = Y + (size_t)r * HH;
    int tid = threadIdx.x;
    if (accz) {
        float* az = accz + (size_t)r * HH;
        for (int i = tid; i < HH; i += 256) az[i] = 0.0f;
    }
    float s = 0.0f, s2 = 0.0f;
    for (int i = tid; i < HH; i += 256) { float v = x[i]; s += v; s2 += v * v; }
    __shared__ float r1[256], r2[256];
    r1[tid] = s; r2[tid] = s2; __syncthreads();
    for (int st = 128; st; st >>= 1) {
        if (tid < st) { r1[tid] += r1[tid + st]; r2[tid] += r2[tid + st]; }
        __syncthreads();
    }
    float mean = r1[0] * (1.0f / HH);
    float var  = r2[0] * (1.0f / HH) - mean * mean;
    float rstd = rsqrtf(var + LN_EPS);
    for (int i = tid; i < HH; i += 256)
        y[i] = __float2half_rn((x[i] - mean) * rstd * gg[i] + bb[i]);
}

// ---------------- means + ctxbias ----------------
__global__ void k_mean2(const float* Xi, const float* Xt,
                        float* ctx_i, float* ctx_t)
{
    int b = blockIdx.y;
    int c = blockIdx.x * 256 + threadIdx.x;
    if (blockIdx.z == 0) {
        float s = 0.0f;
        for (int j = 0; j < VV; j++) s += Xi[(size_t)(b * VV + j) * HH + c];
        ctx_i[b * HH + c] = s / (float)VV;
    } else {
        float s = 0.0f;
        for (int j = 0; j < LL; j++) s += Xt[(size_t)(b * LL + j) * HH + c];
        ctx_t[b * HH + c] = s / (float)LL;
    }
}

__global__ void k_ctxbias2(const float* ctx_t, const float* ctx_i,
                           const float* gw_i, const float* gb_i,
                           const float* gw_t, const float* gb_t,
                           float* out_i, float* out_t)
{
    int w = blockIdx.x * 8 + (threadIdx.x >> 5);
    int lane = threadIdx.x & 31;
    if (w >= 2 * BB * EE) return;
    bool first = w < BB * EE;
    int g = first ? w : w - BB * EE;
    int b = g / EE, e = g % EE;
    const float* ctx = first ? ctx_t : ctx_i;
    const float* gw  = first ? gw_i : gw_t;
    const float* gb  = first ? gb_i : gb_t;
    float* outp      = first ? out_i : out_t;
    float s = 0.0f;
    for (int c = lane; c < HH; c += 32)
        s += ctx[b * HH + c] * gw[(size_t)e * 2 * HH + HH + c];
#pragma unroll
    for (int o = 16; o; o >>= 1) s += __shfl_xor_sync(0xffffffffu, s, o);
    if (lane == 0) outp[g] = s + gb[e];
}

// ---------------- warp-per-token gate (single stream) ----------------
__global__ __launch_bounds__(256) void k_gate_s(
    const float* __restrict__ X,
    const float* __restrict__ gw, const float* __restrict__ cb,
    float* __restrict__ probs, int* __restrict__ cnt,
    float* __restrict__ accz, int S, int ntok)
{
    int w = blockIdx.x * 8 + (threadIdx.x >> 5);
    int lane = threadIdx.x & 31;
    if (w >= ntok) return;
    int t = w;
    int b = t / S;
    const float* x = X + (size_t)t * HH;
    if (lane == 0) cnt[t] = 0;
    if (accz) {
        float* az = accz + (size_t)t * HH;
        for (int i = lane; i < HH; i += 32) az[i] = 0.0f;
    }
    float acc[EE];
#pragma unroll
    for (int e = 0; e < EE; e++) acc[e] = 0.0f;
    for (int c = lane; c < HH; c += 32) {
        float xv = x[c];
#pragma unroll
        for (int e = 0; e < EE; e++) acc[e] += xv * gw[(size_t)e * 2 * HH + c];
    }
#pragma unroll
    for (int e = 0; e < EE; e++) {
#pragma unroll
        for (int o = 16; o; o >>= 1)
            acc[e] += __shfl_xor_sync(0xffffffffu, acc[e], o);
    }
    if (lane == 0) {
        float lg[EE];
#pragma unroll
        for (int e = 0; e < EE; e++) lg[e] = acc[e] + cb[b * EE + e];
        float mx = lg[0];
#pragma unroll
        for (int e = 1; e < EE; e++) mx = fmaxf(mx, lg[e]);
        float sum = 0.0f, ex[EE];
#pragma unroll
        for (int e = 0; e < EE; e++) { ex[e] = expf(lg[e] - mx); sum += ex[e]; }
        float inv = 1.0f / sum;
#pragma unroll
        for (int e = 0; e < EE; e++) probs[(size_t)t * EE + e] = ex[e] * inv;
    }
}

// ---------------- warp-per-group top-k (single stream) ----------------
#define NVMAX 18
__global__ __launch_bounds__(256) void k_topk_s(
    const float* __restrict__ probs, int* __restrict__ sel0,
    int* __restrict__ cnt0, int S, int ksel)
{
    __shared__ int sels[8][SELCAP];
    int w = blockIdx.x * 8 + (threadIdx.x >> 5);
    int wl = threadIdx.x >> 5;
    int lane = threadIdx.x & 31;
    if (w >= BB * EE) return;
    int g = w;
    int b = g / EE, e = g % EE;
    int* sel = sel0 + g * SELCAP;
    int* cnt = cnt0 + b * S;

    float v[NVMAX];
    const int NV = (S + 31) / 32;
#pragma unroll
    for (int j = 0; j < NVMAX; j++) {
        int idx = lane + j * 32;
        v[j] = (j < NV && idx < S)
             ? probs[(size_t)(b * S + idx) * EE + e] : -1.0e30f;
    }
    for (int it = 0; it < ksel; it++) {
        float bv = -2.0e30f; int bj = 0;
#pragma unroll
        for (int j = 0; j < NVMAX; j++)
            if (j < NV && v[j] > bv) { bv = v[j]; bj = j; }
        int bi = lane + bj * 32;
#pragma unroll
        for (int o = 16; o; o >>= 1) {
            float ov = __shfl_xor_sync(0xffffffffu, bv, o);
            int   oi = __shfl_xor_sync(0xffffffffu, bi, o);
            if (ov > bv || (ov == bv && oi < bi)) { bv = ov; bi = oi; }
        }
        if (lane == (bi & 31)) v[bi >> 5] = -1.0e30f;
        if (lane == 0) sels[wl][it] = bi;
    }
    __syncwarp();
    for (int i = lane; i < ksel; i += 32) {
        int tok = sels[wl][i];
        sel[i] = tok;
        atomicAdd(&cnt[tok], 1);
    }
}

// ---------------- per-stream combine ----------------
__global__ void k_combine_s(
    const float* base, const float* acc, const int* cnt, float* outp, int n)
{
    int i = blockIdx.x * 256 + threadIdx.x;
    if (i < n) {
        int tok = i / HH;
        outp[i] = base[i] + acc[i] / fmaxf((float)cnt[tok], 1.0f);
    }
}

// ---------------- launch ----------------
#define SMEMH128 (3 * (128 + 128) * ROWH * 2)
#define SMEMH96  (3 * (96 + 128) * ROWH * 2)

extern "C" void kernel_launch(void* const* d_in, const int* in_sizes, int n_in,
                              void* d_out, int out_size)
{
    (void)in_sizes; (void)n_in; (void)out_size;
    const float* in_q      = (const float*)d_in[0];
    const float* in_img    = (const float*)d_in[1];
    const float* in_txt    = (const float*)d_in[2];
    const float* sa_w_in   = (const float*)d_in[3];
    const float* sa_b_in   = (const float*)d_in[4];
    const float* sa_w_out  = (const float*)d_in[5];
    const float* sa_b_out  = (const float*)d_in[6];
    const float* ca_w_in   = (const float*)d_in[7];
    const float* ca_b_in   = (const float*)d_in[8];
    const float* ca_w_out  = (const float*)d_in[9];
    const float* ca_b_out  = (const float*)d_in[10];
    const float* gate_img_w= (const float*)d_in[11];
    const float* gate_img_b= (const float*)d_in[12];
    const float* gate_txt_w= (const float*)d_in[13];
    const float* gate_txt_b= (const float*)d_in[14];
    const float* e_w1      = (const float*)d_in[15];
    const float* e_b1      = (const float*)d_in[16];
    const float* e_w2      = (const float*)d_in[17];
    const float* e_b2      = (const float*)d_in[18];
    const float* lnq_g     = (const float*)d_in[19];
    const float* lnq_b     = (const float*)d_in[20];
    const float* lnc_g     = (const float*)d_in[21];
    const float* lnc_b     = (const float*)d_in[22];
    const float* lnf_g     = (const float*)d_in[23];
    const float* lnf_b     = (const float*)d_in[24];
    float* out_q   = (float*)d_out;
    float* out_img = out_q + (size_t)BB * TT * HH;

    float *p_q, *p_acc_t, *p_acc_i;
    float *p_ctx_img, *p_ctx_txt, *p_gb_img, *p_gb_txt, *p_probs_t, *p_probs_i;
    int *p_sel_t, *p_sel_i, *p_cnt_t, *p_cnt_i;
    __half *ph_sain, *ph_saout, *ph_cain, *ph_caout, *ph_e1, *ph_e2;
    __half *ph_img, *ph_ln, *ph_qkv, *ph_cq, *ph_kv, *ph_vt, *ph_vt2, *ph_attn;
    __half *ph_ht, *ph_hi;
    cudaGetSymbolAddress((void**)&p_q, g_q);
    cudaGetSymbolAddress((void**)&p_acc_t, g_acc_t);
    cudaGetSymbolAddress((void**)&p_acc_i, g_acc_i);
    cudaGetSymbolAddress((void**)&p_ctx_img, g_ctx_img);
    cudaGetSymbolAddress((void**)&p_ctx_txt, g_ctx_txt);
    cudaGetSymbolAddress((void**)&p_gb_img, g_gb_img);
    cudaGetSymbolAddress((void**)&p_gb_txt, g_gb_txt);
    cudaGetSymbolAddress((void**)&p_probs_t, g_probs_t);
    cudaGetSymbolAddress((void**)&p_probs_i, g_probs_i);
    cudaGetSymbolAddress((void**)&p_sel_t, g_sel_t);
    cudaGetSymbolAddress((void**)&p_sel_i, g_sel_i);
    cudaGetSymbolAddress((void**)&p_cnt_t, g_cnt_t);
    cudaGetSymbolAddress((void**)&p_cnt_i, g_cnt_i);
    cudaGetSymbolAddress((void**)&ph_sain, h_w_sain);
    cudaGetSymbolAddress((void**)&ph_saout, h_w_saout);
    cudaGetSymbolAddress((void**)&ph_cain, h_w_cain);
    cudaGetSymbolAddress((void**)&ph_caout, h_w_caout);
    cudaGetSymbolAddress((void**)&ph_e1, h_w_e1);
    cudaGetSymbolAddress((void**)&ph_e2, h_w_e2);
    cudaGetSymbolAddress((void**)&ph_img, h_img);
    cudaGetSymbolAddress((void**)&ph_ln, h_ln);
    cudaGetSymbolAddress((void**)&ph_qkv, h_qkv);
    cudaGetSymbolAddress((void**)&ph_cq, h_cq);
    cudaGetSymbolAddress((void**)&ph_kv, h_kv);
    cudaGetSymbolAddress((void**)&ph_vt, h_vt);
    cudaGetSymbolAddress((void**)&ph_vt2, h_vt2);
    cudaGetSymbolAddress((void**)&ph_attn, h_attn);
    cudaGetSymbolAddress((void**)&ph_ht, h_ht);
    cudaGetSymbolAddress((void**)&ph_hi, h_hi);

    cudaFuncSetAttribute(k_hg_act,   cudaFuncAttributeMaxDynamicSharedMemorySize, SMEMH128);
    cudaFuncSetAttribute(k_hg_proj,  cudaFuncAttributeMaxDynamicSharedMemorySize, SMEMH128);
    cudaFuncSetAttribute(k_hg_moe1s, cudaFuncAttributeMaxDynamicSharedMemorySize, SMEMH96);
    cudaFuncSetAttribute(k_hg_moe2s, cudaFuncAttributeMaxDynamicSharedMemorySize, SMEMH96);
    cudaFuncSetAttribute(k_flash,    cudaFuncAttributeMaxDynamicSharedMemorySize, FL_SMEM);

    // ---- fork stream B off the (captured) default stream ----
    cudaStream_t sB;
    cudaStreamCreateWithFlags(&sB, cudaStreamNonBlocking);
    cudaEvent_t ev0, evKV, evG, evEnd;
    cudaEventCreateWithFlags(&ev0,   cudaEventDisableTiming);
    cudaEventCreateWithFlags(&evKV,  cudaEventDisableTiming);
    cudaEventCreateWithFlags(&evG,   cudaEventDisableTiming);
    cudaEventCreateWithFlags(&evEnd, cudaEventDisableTiming);

    cudaEventRecord(ev0, 0);
    cudaStreamWaitEvent(sB, ev0, 0);

    // ======== stream B: image branch ========
    k_f2h_b<<<(F2HB_TOTAL / 4 + 255) / 256, 256, 0, sB>>>(
        ca_w_in, in_img, e_w1, e_w2, ph_cain, ph_img, ph_e1, ph_e2);
    k_hg_act<<<dim3(2 * HH / 128, BB * VV / 128), 256, SMEMH128, sB>>>(
        ph_img, HH, ph_cain + (size_t)HH * HH, HH, ca_b_in + HH,
        ph_kv, 2 * HH, BB * VV, 2 * HH, HH);
    k_transp<<<dim3(VV / 32, 2, BB * NHH), dim3(32, 8), 0, sB>>>(
        ph_kv + HH, 2 * HH, ph_vt2, VV);
    cudaEventRecord(evKV, sB);

    k_mean2<<<dim3(HH / 256, BB, 2), 256, 0, sB>>>(in_img, in_txt,
                                                   p_ctx_img, p_ctx_txt);
    k_ctxbias2<<<(2 * BB * EE + 7) / 8, 256, 0, sB>>>(
        p_ctx_txt, p_ctx_img, gate_img_w, gate_img_b, gate_txt_w, gate_txt_b,
        p_gb_img, p_gb_txt);
    cudaEventRecord(evG, sB);

    k_gate_s<<<(BB * VV + 7) / 8, 256, 0, sB>>>(
        in_img, gate_img_w, p_gb_img, p_probs_i, p_cnt_i, p_acc_i, VV, BB * VV);
    k_topk_s<<<(BB * EE + 7) / 8, 256, 0, sB>>>(
        p_probs_i, p_sel_i, p_cnt_i, VV, KSEL_V);
    k_hg_moe1s<<<dim3(II / 128, 1, BB * EE), 192, SMEMH96, sB>>>(
        ph_img, ph_e1, e_b1, p_sel_i, ph_hi, VV, KSEL_V);
    k_hg_moe2s<<<dim3(HH / 128, 1, BB * EE), 192, SMEMH96, sB>>>(
        ph_hi, ph_e2, e_b2, p_sel_i, p_acc_i, VV, KSEL_V);
    k_combine_s<<<(BB * VV * HH + 255) / 256, 256, 0, sB>>>(
        in_img, p_acc_i, p_cnt_i, out_img, BB * VV * HH);
    cudaEventRecord(evEnd, sB);

    // ======== stream A (default): text chain ========
    k_f2h_a<<<(F2HA_TOTAL / 4 + 255) / 256, 256>>>(
        sa_w_in, sa_w_out, ca_w_out, ph_sain, ph_saout, ph_caout);
    k_ln<<<BB * TT, 256>>>(in_q, lnq_g, lnq_b, ph_ln, nullptr);
    k_hg_act<<<dim3(3 * HH / 128, BB * TT / 128), 256, SMEMH128>>>(
        ph_ln, HH, ph_sain, HH, sa_b_in, ph_qkv, 3 * HH, BB * TT, 3 * HH, HH);
    k_transp<<<dim3(TT / 32, 2, BB * NHH), dim3(32, 8)>>>(
        ph_qkv + 2 * HH, 3 * HH, ph_vt, TT);
    k_flash<<<dim3(TT / 128, 1, BB * NHH), 256, FL_SMEM>>>(
        ph_qkv, 3 * HH, TT * 3 * HH, ph_qkv + HH, 3 * HH, TT * 3 * HH,
        ph_vt, ph_attn, TT, TT);
    k_hg_proj<<<dim3(HH / 128, BB * TT / 128), 256, SMEMH128>>>(
        ph_attn, HH, ph_saout, HH, sa_b_out, in_q, p_q, HH, BB * TT, HH, HH);

    k_ln<<<BB * TT, 256>>>(p_q, lnc_g, lnc_b, ph_ln, nullptr);
    cudaStreamWaitEvent(0, evKV, 0);
    k_hg_act<<<dim3(HH / 128, BB * TT / 128), 256, SMEMH128>>>(
        ph_ln, HH, ph_cain, HH, ca_b_in, ph_cq, HH, BB * TT, HH, HH);
    k_flash<<<dim3(TT / 128, 1, BB * NHH), 256, FL_SMEM>>>(
        ph_cq, HH, TT * HH, ph_kv, 2 * HH, VV * 2 * HH,
        ph_vt2, ph_attn, TT, VV);
    k_hg_proj<<<dim3(HH / 128, BB * TT / 128), 256, SMEMH128>>>(
        ph_attn, HH, ph_caout, HH, ca_b_out, p_q, p_q, HH, BB * TT, HH, HH);

    cudaStreamWaitEvent(0, evG, 0);
    k_gate_s<<<(BB * TT + 7) / 8, 256>>>(
        p_q, gate_txt_w, p_gb_txt, p_probs_t, p_cnt_t, nullptr, TT, BB * TT);
    k_topk_s<<<(BB * EE + 7) / 8, 256>>>(
        p_probs_t, p_sel_t, p_cnt_t, TT, KSEL_T);
    k_ln<<<BB * TT, 256>>>(p_q, lnf_g, lnf_b, ph_ln, p_acc_t);
    k_hg_moe1s<<<dim3(II / 128, 1, BB * EE), 192, SMEMH96>>>(
        ph_ln, ph_e1, e_b1, p_sel_t, ph_ht, TT, KSEL_T);
    k_hg_moe2s<<<dim3(HH / 128, 1, BB * EE), 192, SMEMH96>>>(
        ph_ht, ph_e2, e_b2, p_sel_t, p_acc_t, TT, KSEL_T);
    k_combine_s<<<(BB * TT * HH + 255) / 256, 256>>>(
        p_q, p_acc_t, p_cnt_t, out_q, BB * TT * HH);

    // ---- join ----
    cudaStreamWaitEvent(0, evEnd, 0);
}

// round 13
// speedup vs baseline: 2.0050x; 1.0135x over previous
#include <cuda_runtime.h>
#include <cuda_fp16.h>
#include <math.h>
#include <stdint.h>

// ---------------- problem constants ----------------
#define BB   4
#define TT   512
#define VV   576
#define LL   256
#define HH   1024
#define NHH  16
#define HDD  64
#define II   4096
#define EE   8
#define KSEL_T 80
#define KSEL_V 90
#define SELCAP 96
#define LN_EPS 1e-5f

#define BKH  64
#define ROWH 72

// ---------------- fp32 scratch ----------------
__device__ float g_q     [BB*TT*HH];
__device__ float g_acc_t [BB*TT*HH];
__device__ float g_acc_i [BB*VV*HH];
__device__ float g_ctx_img[BB*HH];
__device__ float g_ctx_txt[BB*HH];
__device__ float g_gb_img[BB*EE];
__device__ float g_gb_txt[BB*EE];
__device__ float g_probs_t[BB*TT*EE];
__device__ float g_probs_i[BB*VV*EE];
__device__ int   g_sel_t[BB*EE*SELCAP];
__device__ int   g_sel_i[BB*EE*SELCAP];
__device__ int   g_cnt_t[BB*TT];
__device__ int   g_cnt_i[BB*VV];

// ---------------- fp16 scratch ----------------
__device__ __half h_w_sain [3*HH*HH];
__device__ __half h_w_saout[HH*HH];
__device__ __half h_w_cain [3*HH*HH];
__device__ __half h_w_caout[HH*HH];
__device__ __half h_w_e1   [EE*II*HH];
__device__ __half h_w_e2   [EE*HH*II];
__device__ __half h_img    [BB*VV*HH];
__device__ __half h_ln     [BB*TT*HH];
__device__ __half h_qkv    [BB*TT*3*HH];
__device__ __half h_cq     [BB*TT*HH];
__device__ __half h_kv     [BB*VV*2*HH];
__device__ __half h_vt     [BB*NHH*HDD*VV];
__device__ __half h_vt2    [BB*NHH*HDD*VV];
__device__ __half h_attn   [BB*TT*HH];
__device__ __half h_ht     [BB*EE*SELCAP*II];
__device__ __half h_hi     [BB*EE*SELCAP*II];

// ---------------- helpers ----------------
__device__ __forceinline__ float gelu_f(float x) {
    float x3 = x * x * x;
    return 0.5f * x * (1.0f + tanhf(0.7978845608028654f * (x + 0.044715f * x3)));
}
__device__ __forceinline__ void mma_f16(float c[4],
    uint32_t a0, uint32_t a1, uint32_t a2, uint32_t a3,
    uint32_t b0, uint32_t b1)
{
    asm volatile(
        "mma.sync.aligned.m16n8k16.row.col.f32.f16.f16.f32 "
        "{%0,%1,%2,%3}, {%4,%5,%6,%7}, {%8,%9}, {%0,%1,%2,%3};"
        : "+f"(c[0]), "+f"(c[1]), "+f"(c[2]), "+f"(c[3])
        : "r"(a0), "r"(a1), "r"(a2), "r"(a3), "r"(b0), "r"(b1));
}
__device__ __forceinline__ void cpa16h(__half* dst, const __half* src, bool valid) {
    uint32_t d = (uint32_t)__cvta_generic_to_shared(dst);
    asm volatile("cp.async.cg.shared.global [%0], [%1], 16, %2;"
                 :: "r"(d), "l"(src), "r"(valid ? 16 : 0));
}

// ---------------- fp16 GEMM (unchanged core) ----------------
template<int BMT, int THREADS, bool GELU_E, bool ATOMIC, bool RES, bool OUT16, bool OUT32>
__device__ __forceinline__ void hgemm(
    __half* smem,
    const __half* __restrict__ A, int lda, const int* __restrict__ arow,
    const __half* __restrict__ Bp, int ldb,
    const float* __restrict__ bias, const float* __restrict__ res,
    float* __restrict__ C32, __half* __restrict__ C16,
    int ldc, const int* __restrict__ crow,
    int M, int N, int K)
{
    constexpr int BN  = 128;
    constexpr int NJ  = 8;
    constexpr int RP  = THREADS / 8;
    constexpr int AP  = BMT / RP;
    constexpr int BP  = (BN + RP - 1) / RP;
    constexpr int NWM = THREADS / 64;
    constexpr int STH = (BMT + BN) * ROWH;
    __half* As[3] = { smem, smem + STH, smem + 2 * STH };
    __half* Bs[3] = { smem + BMT * ROWH, smem + STH + BMT * ROWH,
                      smem + 2 * STH + BMT * ROWH };

    const int tid  = threadIdx.x;
    const int lane = tid & 31, warp = tid >> 5;
    const int wm = (warp % NWM) * 32;
    const int wn = (warp / NWM) * 64;
    const int m0 = blockIdx.y * BMT, n0 = blockIdx.x * BN;

    const int sr = tid >> 3;
    const int ch = tid & 7;
    int rowA[AP]; bool valA[AP];
#pragma unroll
    for (int p = 0; p < AP; p++) {
        int gm = m0 + sr + p * RP;
        valA[p] = gm < M;
        rowA[p] = valA[p] ? (arow ? arow[gm] : gm) : 0;
    }
    int rowB[BP]; bool valB[BP];
#pragma unroll
    for (int p = 0; p < BP; p++) {
        int r = sr + p * RP;
        int gn = n0 + r;
        valB[p] = (r < BN) && (gn < N);
        rowB[p] = valB[p] ? gn : 0;
    }

    float c[2][NJ][4];
#pragma unroll
    for (int i = 0; i < 2; i++)
#pragma unroll
        for (int j = 0; j < NJ; j++)
#pragma unroll
            for (int q = 0; q < 4; q++) c[i][j][q] = 0.0f;

    const int KT = K / BKH;

    auto load_tile = [&](int st, int k0) {
        __half* Ad = As[st];
        __half* Bd = Bs[st];
#pragma unroll
        for (int p = 0; p < AP; p++)
            cpa16h(Ad + (sr + p * RP) * ROWH + ch * 8,
                   A + (size_t)rowA[p] * lda + k0 + ch * 8, valA[p]);
#pragma unroll
        for (int p = 0; p < BP; p++) {
            int r = sr + p * RP;
            if (r < BN)
                cpa16h(Bd + r * ROWH + ch * 8,
                       Bp + (size_t)rowB[p] * ldb + k0 + ch * 8, valB[p]);
        }
    };

    load_tile(0, 0);
    asm volatile("cp.async.commit_group;");
    if (KT > 1) load_tile(1, BKH);
    asm volatile("cp.async.commit_group;");

    for (int kt = 0; kt < KT; kt++) {
        asm volatile("cp.async.wait_group 1;");
        __syncthreads();
        const int st = kt % 3;
        if (kt + 2 < KT) load_tile((kt + 2) % 3, (kt + 2) * BKH);
        asm volatile("cp.async.commit_group;");

        const __half* Ab = As[st];
        const __half* Bb = Bs[st];
#pragma unroll
        for (int ks = 0; ks < 4; ks++) {
            const int cc = ks * 16 + 2 * (lane & 3);
            uint32_t a[2][4];
#pragma unroll
            for (int i = 0; i < 2; i++) {
                const int r = wm + i * 16 + (lane >> 2);
                a[i][0] = *(const uint32_t*)&Ab[r * ROWH + cc];
                a[i][1] = *(const uint32_t*)&Ab[(r + 8) * ROWH + cc];
                a[i][2] = *(const uint32_t*)&Ab[r * ROWH + cc + 8];
                a[i][3] = *(const uint32_t*)&Ab[(r + 8) * ROWH + cc + 8];
            }
            uint32_t b[NJ][2];
#pragma unroll
            for (int j = 0; j < NJ; j++) {
                const int bc = wn + j * 8 + (lane >> 2);
                b[j][0] = *(const uint32_t*)&Bb[bc * ROWH + cc];
                b[j][1] = *(const uint32_t*)&Bb[bc * ROWH + cc + 8];
            }
#pragma unroll
            for (int i = 0; i < 2; i++)
#pragma unroll
                for (int j = 0; j < NJ; j++)
                    mma_f16(c[i][j], a[i][0], a[i][1], a[i][2], a[i][3],
                            b[j][0], b[j][1]);
        }
    }

#pragma unroll
    for (int i = 0; i < 2; i++) {
        int rm = m0 + wm + i * 16 + (lane >> 2);
#pragma unroll
        for (int j = 0; j < NJ; j++) {
            int cn = n0 + wn + j * 8 + 2 * (lane & 3);
#pragma unroll
            for (int rr = 0; rr < 2; rr++) {
                int gm = rm + rr * 8;
                if (gm >= M) continue;
                int orow = crow ? crow[gm] : gm;
#pragma unroll
                for (int qq = 0; qq < 2; qq++) {
                    int gn = cn + qq;
                    if (gn >= N) continue;
                    float v = c[i][j][rr * 2 + qq];
                    if (bias) v += bias[gn];
                    if (RES)  v += res[(size_t)gm * ldc + gn];
                    if (GELU_E) v = gelu_f(v);
                    if (ATOMIC) {
                        atomicAdd(&C32[(size_t)orow * ldc + gn], v);
                    } else {
                        if (OUT32) C32[(size_t)orow * ldc + gn] = v;
                        if (OUT16) C16[(size_t)orow * ldc + gn] = __float2half_rn(v);
                    }
                }
            }
        }
    }
}

__global__ __launch_bounds__(256, 2) void k_hg_act(
    const __half* A, int lda, const __half* W, int ldw,
    const float* bias, __half* C16, int ldc, int M, int N, int K)
{
    extern __shared__ __half smh[];
    hgemm<128, 256, false, false, false, true, false>(smh, A, lda, nullptr, W, ldw,
        bias, nullptr, nullptr, C16, ldc, nullptr, M, N, K);
}

__global__ __launch_bounds__(256, 2) void k_hg_proj(
    const __half* A, int lda, const __half* W, int ldw,
    const float* bias, const float* res, float* C32, int ldc, int M, int N, int K)
{
    extern __shared__ __half smh[];
    hgemm<128, 256, false, false, true, false, true>(smh, A, lda, nullptr, W, ldw,
        bias, res, C32, nullptr, ldc, nullptr, M, N, K);
}

__global__ __launch_bounds__(192, 2) void k_hg_moe1s(
    const __half* X0, const __half* w1, const float* b1,
    const int* sel0, __half* H0, int S, int ksel)
{
    extern __shared__ __half smh[];
    int g = blockIdx.z;
    int b = g / EE, e = g % EE;
    const __half* X = X0 + (size_t)b * S * HH;
    const int* sel = sel0 + g * SELCAP;
    __half* H = H0 + (size_t)g * SELCAP * II;
    hgemm<96, 192, true, false, false, true, false>(smh, X, HH, sel,
        w1 + (size_t)e * II * HH, HH, b1 + (size_t)e * II, nullptr,
        nullptr, H, II, nullptr, ksel, II, HH);
}

__global__ __launch_bounds__(192, 2) void k_hg_moe2s(
    const __half* H0, const __half* w2, const float* b2,
    const int* sel0, float* Acc0, int S, int ksel)
{
    extern __shared__ __half smh[];
    int g = blockIdx.z;
    int b = g / EE, e = g % EE;
    const __half* H = H0 + (size_t)g * SELCAP * II;
    const int* sel = sel0 + g * SELCAP;
    float* Acc = Acc0 + (size_t)b * S * HH;
    hgemm<96, 192, false, true, false, false, false>(smh, H, II, nullptr,
        w2 + (size_t)e * HH * II, II, b2 + (size_t)e * HH, nullptr,
        Acc, nullptr, HH, sel, ksel, HH, II);
}

// ---------------- fused flash attention (now 2 CTAs/SM) ----------------
#define FL_SMEM ((128 * ROWH + 4 * 64 * ROWH) * 2)

__global__ __launch_bounds__(256, 2) void k_flash(
    const __half* __restrict__ Qp, int qld, int qbs,
    const __half* __restrict__ Kp, int kld, int kbs,
    const __half* __restrict__ Vt,
    __half* __restrict__ O, int Tq, int Skv)
{
    extern __shared__ __half sm[];
    __half* Qs = sm;
    __half* Ks[2] = { sm + 128 * ROWH, sm + 128 * ROWH + 64 * ROWH };
    __half* Vs[2] = { sm + 128 * ROWH + 2 * 64 * ROWH,
                      sm + 128 * ROWH + 3 * 64 * ROWH };

    const int z = blockIdx.z, b = z / NHH, h = z % NHH;
    const __half* Qb = Qp + (size_t)b * qbs + h * HDD;
    const __half* Kb = Kp + (size_t)b * kbs + h * HDD;
    const __half* Vb = Vt + (size_t)z * HDD * Skv;
    __half* Ob = O + (size_t)b * Tq * HH + h * HDD;

    const int tid = threadIdx.x, lane = tid & 31, warp = tid >> 5;
    const int m0 = blockIdx.x * 128;
    const int sr = tid >> 3, ch = tid & 7;

    auto loadKV = [&](int buf, int s0) {
#pragma unroll
        for (int p = 0; p < 2; p++)
            cpa16h(Ks[buf] + (sr + p * 32) * ROWH + ch * 8,
                   Kb + (size_t)(s0 + sr + p * 32) * kld + ch * 8, true);
#pragma unroll
        for (int p = 0; p < 2; p++)
            cpa16h(Vs[buf] + (sr + p * 32) * ROWH + ch * 8,
                   Vb + (size_t)(sr + p * 32) * Skv + s0 + ch * 8, true);
    };

#pragma unroll
    for (int p = 0; p < 4; p++)
        cpa16h(Qs + (sr + p * 32) * ROWH + ch * 8,
               Qb + (size_t)(m0 + sr + p * 32) * qld + ch * 8, true);
    loadKV(0, 0);
    asm volatile("cp.async.commit_group;");

    uint32_t qa[4][4];
    float o[8][4];
#pragma unroll
    for (int j = 0; j < 8; j++)
#pragma unroll
        for (int q = 0; q < 4; q++) o[j][q] = 0.0f;
    float m0v = -1.0e30f, m1v = -1.0e30f, l0 = 0.0f, l1 = 0.0f;

    const int nchunks = Skv / 64;
    for (int s = 0; s < nchunks; s++) {
        asm volatile("cp.async.wait_group 0;");
        __syncthreads();
        const int buf = s & 1;
        if (s == 0) {
            const int r = warp * 16 + (lane >> 2);
#pragma unroll
            for (int ks = 0; ks < 4; ks++) {
                const int cc = ks * 16 + 2 * (lane & 3);
                qa[ks][0] = *(const uint32_t*)&Qs[r * ROWH + cc];
                qa[ks][1] = *(const uint32_t*)&Qs[(r + 8) * ROWH + cc];
                qa[ks][2] = *(const uint32_t*)&Qs[r * ROWH + cc + 8];
                qa[ks][3] = *(const uint32_t*)&Qs[(r + 8) * ROWH + cc + 8];
            }
        }
        if (s + 1 < nchunks) loadKV(buf ^ 1, (s + 1) * 64);
        asm volatile("cp.async.commit_group;");

        float sc[8][4];
#pragma unroll
        for (int j = 0; j < 8; j++)
#pragma unroll
            for (int q = 0; q < 4; q++) sc[j][q] = 0.0f;
        const __half* Kc = Ks[buf];
#pragma unroll
        for (int ks = 0; ks < 4; ks++) {
            const int cc = ks * 16 + 2 * (lane & 3);
#pragma unroll
            for (int j = 0; j < 8; j++) {
                const int bc = j * 8 + (lane >> 2);
                uint32_t b0 = *(const uint32_t*)&Kc[bc * ROWH + cc];
                uint32_t b1 = *(const uint32_t*)&Kc[bc * ROWH + cc + 8];
                mma_f16(sc[j], qa[ks][0], qa[ks][1], qa[ks][2], qa[ks][3], b0, b1);
            }
        }
        float rm0 = -1.0e30f, rm1 = -1.0e30f;
#pragma unroll
        for (int j = 0; j < 8; j++) {
#pragma unroll
            for (int q = 0; q < 4; q++) sc[j][q] *= 0.125f;
            rm0 = fmaxf(rm0, fmaxf(sc[j][0], sc[j][1]));
            rm1 = fmaxf(rm1, fmaxf(sc[j][2], sc[j][3]));
        }
#pragma unroll
        for (int off = 1; off <= 2; off <<= 1) {
            rm0 = fmaxf(rm0, __shfl_xor_sync(0xffffffffu, rm0, off));
            rm1 = fmaxf(rm1, __shfl_xor_sync(0xffffffffu, rm1, off));
        }
        float nm0 = fmaxf(m0v, rm0), nm1 = fmaxf(m1v, rm1);
        float cr0 = __expf(m0v - nm0), cr1 = __expf(m1v - nm1);
        m0v = nm0; m1v = nm1;
        float rs0 = 0.0f, rs1 = 0.0f;
#pragma unroll
        for (int j = 0; j < 8; j++) {
            sc[j][0] = __expf(sc[j][0] - nm0);
            sc[j][1] = __expf(sc[j][1] - nm0);
            sc[j][2] = __expf(sc[j][2] - nm1);
            sc[j][3] = __expf(sc[j][3] - nm1);
            rs0 += sc[j][0] + sc[j][1];
            rs1 += sc[j][2] + sc[j][3];
        }
#pragma unroll
        for (int off = 1; off <= 2; off <<= 1) {
            rs0 += __shfl_xor_sync(0xffffffffu, rs0, off);
            rs1 += __shfl_xor_sync(0xffffffffu, rs1, off);
        }
        l0 = l0 * cr0 + rs0;
        l1 = l1 * cr1 + rs1;
#pragma unroll
        for (int j = 0; j < 8; j++) {
            o[j][0] *= cr0; o[j][1] *= cr0;
            o[j][2] *= cr1; o[j][3] *= cr1;
        }
        const __half* Vc = Vs[buf];
#pragma unroll
        for (int ks = 0; ks < 4; ks++) {
            uint32_t a0, a1, a2, a3;
            {
                __half2 t;
                t = __floats2half2_rn(sc[2 * ks][0], sc[2 * ks][1]);     a0 = *(uint32_t*)&t;
                t = __floats2half2_rn(sc[2 * ks][2], sc[2 * ks][3]);     a1 = *(uint32_t*)&t;
                t = __floats2half2_rn(sc[2 * ks + 1][0], sc[2 * ks + 1][1]); a2 = *(uint32_t*)&t;
                t = __floats2half2_rn(sc[2 * ks + 1][2], sc[2 * ks + 1][3]); a3 = *(uint32_t*)&t;
            }
            const int cc = ks * 16 + 2 * (lane & 3);
#pragma unroll
            for (int jd = 0; jd < 8; jd++) {
                const int bc = jd * 8 + (lane >> 2);
                uint32_t b0 = *(const uint32_t*)&Vc[bc * ROWH + cc];
                uint32_t b1 = *(const uint32_t*)&Vc[bc * ROWH + cc + 8];
                mma_f16(o[jd], a0, a1, a2, a3, b0, b1);
            }
        }
    }

    const float iv0 = 1.0f / l0, iv1 = 1.0f / l1;
    const int r0 = m0 + warp * 16 + (lane >> 2);
#pragma unroll
    for (int jd = 0; jd < 8; jd++) {
        const int col = jd * 8 + 2 * (lane & 3);
        Ob[(size_t)r0 * HH + col]       = __float2half_rn(o[jd][0] * iv0);
        Ob[(size_t)r0 * HH + col + 1]   = __float2half_rn(o[jd][1] * iv0);
        Ob[(size_t)(r0 + 8) * HH + col]     = __float2half_rn(o[jd][2] * iv1);
        Ob[(size_t)(r0 + 8) * HH + col + 1] = __float2half_rn(o[jd][3] * iv1);
    }
}

// ---------------- split fp32->fp16 conversions ----------------
#define A0 (3*HH*HH)
#define A1 (HH*HH)
#define A2 (HH*HH)
#define F2HA_TOTAL (A0+A1+A2)
__global__ void k_f2h_a(const float* s0, const float* s1, const float* s2,
                        __half* d0, __half* d1, __half* d2)
{
    int i = (blockIdx.x * 256 + threadIdx.x) * 4;
    if (i >= F2HA_TOTAL) return;
    const float* src; __half* dst; int off;
    if      (i < A0)      { src = s0; dst = d0; off = i; }
    else if (i < A0+A1)   { src = s1; dst = d1; off = i - A0; }
    else                  { src = s2; dst = d2; off = i - A0 - A1; }
    float4 v = *(const float4*)(src + off);
    *(__half2*)(dst + off)     = __floats2half2_rn(v.x, v.y);
    *(__half2*)(dst + off + 2) = __floats2half2_rn(v.z, v.w);
}

#define B0 (3*HH*HH)
#define B1 (BB*VV*HH)
#define B2 (EE*II*HH)
#define B3 (EE*HH*II)
#define F2HB_TOTAL (B0+B1+B2+B3)
__global__ void k_f2h_b(const float* s0, const float* s1, const float* s2,
                        const float* s3,
                        __half* d0, __half* d1, __half* d2, __half* d3)
{
    int i = (blockIdx.x * 256 + threadIdx.x) * 4;
    if (i >= F2HB_TOTAL) return;
    const float* src; __half* dst; int off;
    if      (i < B0)          { src = s0; dst = d0; off = i; }
    else if (i < B0+B1)       { src = s1; dst = d1; off = i - B0; }
    else if (i < B0+B1+B2)    { src = s2; dst = d2; off = i - B0 - B1; }
    else                      { src = s3; dst = d3; off = i - B0 - B1 - B2; }
    float4 v = *(const float4*)(src + off);
    *(__half2*)(dst + off)     = __floats2half2_rn(v.x, v.y);
    *(__half2*)(dst + off + 2) = __floats2half2_rn(v.z, v.w);
}

// ---------------- V transpose (fp16) ----------------
__global__ void k_transp(const __half* __restrict__ X, int ldx,
                         __half* __restrict__ Y, int S)
{
    __shared__ float t[32][33];
    int z = blockIdx.z; int b = z >> 4, h = z & 15;
    int t0 = blockIdx.x * 32, d0 = blockIdx.y * 32;
    const __half* src = X + ((size_t)b * S) * ldx + h * HDD;
#pragma unroll
    for (int k2 = 0; k2 < 4; k2++) {
        int tt = t0 + threadIdx.y + k2 * 8;
        t[threadIdx.y + k2 * 8][threadIdx.x] =
            __half2float(src[(size_t)tt * ldx + d0 + threadIdx.x]);
    }
    __syncthreads();
    __half* dst = Y + ((size_t)z * HDD) * S;
#pragma unroll
    for (int k2 = 0; k2 < 4; k2++) {
        int d = d0 + threadIdx.y + k2 * 8;
        dst[(size_t)d * S + t0 + threadIdx.x] =
            __float2half_rn(t[threadIdx.x][threadIdx.y + k2 * 8]);
    }
}

// ---------------- layernorm ----------------
__global__ void k_ln(const float* X, const float* gg, const float* bb,
                     __half* Y, float* accz)
{
    int r = blockIdx.x;
    const float* x = X + (size_t)r * HH;
    __half* y = Y + (size_t)r * HH;
    int tid = threadIdx.x;
    if (accz) {
        float* az = accz + (size_t)r * HH;
        for (int i = tid; i < HH; i += 256) az[i] = 0.0f;
    }
    float s = 0.0f, s2 = 0.0f;
    for (int i = tid; i < HH; i += 256) { float v = x[i]; s += v; s2 += v * v; }
    __shared__ float r1[256], r2[256];
    r1[tid] = s; r2[tid] = s2; __syncthreads();
    for (int st = 128; st; st >>= 1) {
        if (tid < st) { r1[tid] += r1[tid + st]; r2[tid] += r2[tid + st]; }
        __syncthreads();
    }
    float mean = r1[0] * (1.0f / HH);
    float var  = r2[0] * (1.0f / HH) - mean * mean;
    float rstd = rsqrtf(var + LN_EPS);
    for (int i = tid; i < HH; i += 256)
        y[i] = __float2half_rn((x[i] - mean) * rstd * gg[i] + bb[i]);
}

// ---------------- means (unrolled, MLP=4) + ctxbias ----------------
__global__ void k_mean2(const float* Xi, const float* Xt,
                        float* ctx_i, float* ctx_t)
{
    int b = blockIdx.y;
    int c = blockIdx.x * 256 + threadIdx.x;
    if (blockIdx.z == 0) {
        const float* base = Xi + (size_t)b * VV * HH + c;
        float s0 = 0.0f, s1 = 0.0f, s2 = 0.0f, s3 = 0.0f;
        for (int j = 0; j < VV; j += 4) {
            s0 += base[(size_t)j * HH];
            s1 += base[(size_t)(j + 1) * HH];
            s2 += base[(size_t)(j + 2) * HH];
            s3 += base[(size_t)(j + 3) * HH];
        }
        ctx_i[b * HH + c] = (s0 + s1 + s2 + s3) / (float)VV;
    } else {
        const float* base = Xt + (size_t)b * LL * HH + c;
        float s0 = 0.0f, s1 = 0.0f, s2 = 0.0f, s3 = 0.0f;
        for (int j = 0; j < LL; j += 4) {
            s0 += base[(size_t)j * HH];
            s1 += base[(size_t)(j + 1) * HH];
            s2 += base[(size_t)(j + 2) * HH];
            s3 += base[(size_t)(j + 3) * HH];
        }
        ctx_t[b * HH + c] = (s0 + s1 + s2 + s3) / (float)LL;
    }
}

__global__ void k_ctxbias2(const float* ctx_t, const float* ctx_i,
                           const float* gw_i, const float* gb_i,
                           const float* gw_t, const float* gb_t,
                           float* out_i, float* out_t)
{
    int w = blockIdx.x * 8 + (threadIdx.x >> 5);
    int lane = threadIdx.x & 31;
    if (w >= 2 * BB * EE) return;
    bool first = w < BB * EE;
    int g = first ? w : w - BB * EE;
    int b = g / EE, e = g % EE;
    const float* ctx = first ? ctx_t : ctx_i;
    const float* gw  = first ? gw_i : gw_t;
    const float* gb  = first ? gb_i : gb_t;
    float* outp      = first ? out_i : out_t;
    float s = 0.0f;
    for (int c = lane; c < HH; c += 32)
        s += ctx[b * HH + c] * gw[(size_t)e * 2 * HH + HH + c];
#pragma unroll
    for (int o = 16; o; o >>= 1) s += __shfl_xor_sync(0xffffffffu, s, o);
    if (lane == 0) outp[g] = s + gb[e];
}

// ---------------- warp-per-token gate ----------------
__global__ __launch_bounds__(256) void k_gate_s(
    const float* __restrict__ X,
    const float* __restrict__ gw, const float* __restrict__ cb,
    float* __restrict__ probs, int* __restrict__ cnt,
    float* __restrict__ accz, int S, int ntok)
{
    int w = blockIdx.x * 8 + (threadIdx.x >> 5);
    int lane = threadIdx.x & 31;
    if (w >= ntok) return;
    int t = w;
    int b = t / S;
    const float* x = X + (size_t)t * HH;
    if (lane == 0) cnt[t] = 0;
    if (accz) {
        float* az = accz + (size_t)t * HH;
        for (int i = lane; i < HH; i += 32) az[i] = 0.0f;
    }
    float acc[EE];
#pragma unroll
    for (int e = 0; e < EE; e++) acc[e] = 0.0f;
    for (int c = lane; c < HH; c += 32) {
        float xv = x[c];
#pragma unroll
        for (int e = 0; e < EE; e++) acc[e] += xv * gw[(size_t)e * 2 * HH + c];
    }
#pragma unroll
    for (int e = 0; e < EE; e++) {
#pragma unroll
        for (int o = 16; o; o >>= 1)
            acc[e] += __shfl_xor_sync(0xffffffffu, acc[e], o);
    }
    if (lane == 0) {
        float lg[EE];
#pragma unroll
        for (int e = 0; e < EE; e++) lg[e] = acc[e] + cb[b * EE + e];
        float mx = lg[0];
#pragma unroll
        for (int e = 1; e < EE; e++) mx = fmaxf(mx, lg[e]);
        float sum = 0.0f, ex[EE];
#pragma unroll
        for (int e = 0; e < EE; e++) { ex[e] = expf(lg[e] - mx); sum += ex[e]; }
        float inv = 1.0f / sum;
#pragma unroll
        for (int e = 0; e < EE; e++) probs[(size_t)t * EE + e] = ex[e] * inv;
    }
}

// ---------------- warp-per-group top-k ----------------
#define NVMAX 18
__global__ __launch_bounds__(256) void k_topk_s(
    const float* __restrict__ probs, int* __restrict__ sel0,
    int* __restrict__ cnt0, int S, int ksel)
{
    __shared__ int sels[8][SELCAP];
    int w = blockIdx.x * 8 + (threadIdx.x >> 5);
    int wl = threadIdx.x >> 5;
    int lane = threadIdx.x & 31;
    if (w >= BB * EE) return;
    int g = w;
    int b = g / EE, e = g % EE;
    int* sel = sel0 + g * SELCAP;
    int* cnt = cnt0 + b * S;

    float v[NVMAX];
    const int NV = (S + 31) / 32;
#pragma unroll
    for (int j = 0; j < NVMAX; j++) {
        int idx = lane + j * 32;
        v[j] = (j < NV && idx < S)
             ? probs[(size_t)(b * S + idx) * EE + e] : -1.0e30f;
    }
    for (int it = 0; it < ksel; it++) {
        float bv = -2.0e30f; int bj = 0;
#pragma unroll
        for (int j = 0; j < NVMAX; j++)
            if (j < NV && v[j] > bv) { bv = v[j]; bj = j; }
        int bi = lane + bj * 32;
#pragma unroll
        for (int o = 16; o; o >>= 1) {
            float ov = __shfl_xor_sync(0xffffffffu, bv, o);
            int   oi = __shfl_xor_sync(0xffffffffu, bi, o);
            if (ov > bv || (ov == bv && oi < bi)) { bv = ov; bi = oi; }
        }
        if (lane == (bi & 31)) v[bi >> 5] = -1.0e30f;
        if (lane == 0) sels[wl][it] = bi;
    }
    __syncwarp();
    for (int i = lane; i < ksel; i += 32) {
        int tok = sels[wl][i];
        sel[i] = tok;
        atomicAdd(&cnt[tok], 1);
    }
}

// ---------------- per-stream combine ----------------
__global__ void k_combine_s(
    const float* base, const float* acc, const int* cnt, float* outp, int n)
{
    int i = blockIdx.x * 256 + threadIdx.x;
    if (i < n) {
        int tok = i / HH;
        outp[i] = base[i] + acc[i] / fmaxf((float)cnt[tok], 1.0f);
    }
}

// ---------------- launch ----------------
#define SMEMH128 (3 * (128 + 128) * ROWH * 2)
#define SMEMH96  (3 * (96 + 128) * ROWH * 2)

extern "C" void kernel_launch(void* const* d_in, const int* in_sizes, int n_in,
                              void* d_out, int out_size)
{
    (void)in_sizes; (void)n_in; (void)out_size;
    const float* in_q      = (const float*)d_in[0];
    const float* in_img    = (const float*)d_in[1];
    const float* in_txt    = (const float*)d_in[2];
    const float* sa_w_in   = (const float*)d_in[3];
    const float* sa_b_in   = (const float*)d_in[4];
    const float* sa_w_out  = (const float*)d_in[5];
    const float* sa_b_out  = (const float*)d_in[6];
    const float* ca_w_in   = (const float*)d_in[7];
    const float* ca_b_in   = (const float*)d_in[8];
    const float* ca_w_out  = (const float*)d_in[9];
    const float* ca_b_out  = (const float*)d_in[10];
    const float* gate_img_w= (const float*)d_in[11];
    const float* gate_img_b= (const float*)d_in[12];
    const float* gate_txt_w= (const float*)d_in[13];
    const float* gate_txt_b= (const float*)d_in[14];
    const float* e_w1      = (const float*)d_in[15];
    const float* e_b1      = (const float*)d_in[16];
    const float* e_w2      = (const float*)d_in[17];
    const float* e_b2      = (const float*)d_in[18];
    const float* lnq_g     = (const float*)d_in[19];
    const float* lnq_b     = (const float*)d_in[20];
    const float* lnc_g     = (const float*)d_in[21];
    const float* lnc_b     = (const float*)d_in[22];
    const float* lnf_g     = (const float*)d_in[23];
    const float* lnf_b     = (const float*)d_in[24];
    float* out_q   = (float*)d_out;
    float* out_img = out_q + (size_t)BB * TT * HH;

    float *p_q, *p_acc_t, *p_acc_i;
    float *p_ctx_img, *p_ctx_txt, *p_gb_img, *p_gb_txt, *p_probs_t, *p_probs_i;
    int *p_sel_t, *p_sel_i, *p_cnt_t, *p_cnt_i;
    __half *ph_sain, *ph_saout, *ph_cain, *ph_caout, *ph_e1, *ph_e2;
    __half *ph_img, *ph_ln, *ph_qkv, *ph_cq, *ph_kv, *ph_vt, *ph_vt2, *ph_attn;
    __half *ph_ht, *ph_hi;
    cudaGetSymbolAddress((void**)&p_q, g_q);
    cudaGetSymbolAddress((void**)&p_acc_t, g_acc_t);
    cudaGetSymbolAddress((void**)&p_acc_i, g_acc_i);
    cudaGetSymbolAddress((void**)&p_ctx_img, g_ctx_img);
    cudaGetSymbolAddress((void**)&p_ctx_txt, g_ctx_txt);
    cudaGetSymbolAddress((void**)&p_gb_img, g_gb_img);
    cudaGetSymbolAddress((void**)&p_gb_txt, g_gb_txt);
    cudaGetSymbolAddress((void**)&p_probs_t, g_probs_t);
    cudaGetSymbolAddress((void**)&p_probs_i, g_probs_i);
    cudaGetSymbolAddress((void**)&p_sel_t, g_sel_t);
    cudaGetSymbolAddress((void**)&p_sel_i, g_sel_i);
    cudaGetSymbolAddress((void**)&p_cnt_t, g_cnt_t);
    cudaGetSymbolAddress((void**)&p_cnt_i, g_cnt_i);
    cudaGetSymbolAddress((void**)&ph_sain, h_w_sain);
    cudaGetSymbolAddress((void**)&ph_saout, h_w_saout);
    cudaGetSymbolAddress((void**)&ph_cain, h_w_cain);
    cudaGetSymbolAddress((void**)&ph_caout, h_w_caout);
    cudaGetSymbolAddress((void**)&ph_e1, h_w_e1);
    cudaGetSymbolAddress((void**)&ph_e2, h_w_e2);
    cudaGetSymbolAddress((void**)&ph_img, h_img);
    cudaGetSymbolAddress((void**)&ph_ln, h_ln);
    cudaGetSymbolAddress((void**)&ph_qkv, h_qkv);
    cudaGetSymbolAddress((void**)&ph_cq, h_cq);
    cudaGetSymbolAddress((void**)&ph_kv, h_kv);
    cudaGetSymbolAddress((void**)&ph_vt, h_vt);
    cudaGetSymbolAddress((void**)&ph_vt2, h_vt2);
    cudaGetSymbolAddress((void**)&ph_attn, h_attn);
    cudaGetSymbolAddress((void**)&ph_ht, h_ht);
    cudaGetSymbolAddress((void**)&ph_hi, h_hi);

    cudaFuncSetAttribute(k_hg_act,   cudaFuncAttributeMaxDynamicSharedMemorySize, SMEMH128);
    cudaFuncSetAttribute(k_hg_proj,  cudaFuncAttributeMaxDynamicSharedMemorySize, SMEMH128);
    cudaFuncSetAttribute(k_hg_moe1s, cudaFuncAttributeMaxDynamicSharedMemorySize, SMEMH96);
    cudaFuncSetAttribute(k_hg_moe2s, cudaFuncAttributeMaxDynamicSharedMemorySize, SMEMH96);
    cudaFuncSetAttribute(k_flash,    cudaFuncAttributeMaxDynamicSharedMemorySize, FL_SMEM);

    // ---- fork stream B off the (captured) default stream ----
    cudaStream_t sB;
    cudaStreamCreateWithFlags(&sB, cudaStreamNonBlocking);
    cudaEvent_t ev0, evKV, evG, evEnd;
    cudaEventCreateWithFlags(&ev0,   cudaEventDisableTiming);
    cudaEventCreateWithFlags(&evKV,  cudaEventDisableTiming);
    cudaEventCreateWithFlags(&evG,   cudaEventDisableTiming);
    cudaEventCreateWithFlags(&evEnd, cudaEventDisableTiming);

    cudaEventRecord(ev0, 0);
    cudaStreamWaitEvent(sB, ev0, 0);

    // ======== stream B: image branch ========
    // gating contexts first (input-only deps) so evG fires early
    k_mean2<<<dim3(HH / 256, BB, 2), 256, 0, sB>>>(in_img, in_txt,
                                                   p_ctx_img, p_ctx_txt);
    k_ctxbias2<<<(2 * BB * EE + 7) / 8, 256, 0, sB>>>(
        p_ctx_txt, p_ctx_img, gate_img_w, gate_img_b, gate_txt_w, gate_txt_b,
        p_gb_img, p_gb_txt);
    cudaEventRecord(evG, sB);

    k_gate_s<<<(BB * VV + 7) / 8, 256, 0, sB>>>(
        in_img, gate_img_w, p_gb_img, p_probs_i, p_cnt_i, p_acc_i, VV, BB * VV);
    k_topk_s<<<(BB * EE + 7) / 8, 256, 0, sB>>>(
        p_probs_i, p_sel_i, p_cnt_i, VV, KSEL_V);

    k_f2h_b<<<(F2HB_TOTAL / 4 + 255) / 256, 256, 0, sB>>>(
        ca_w_in, in_img, e_w1, e_w2, ph_cain, ph_img, ph_e1, ph_e2);
    k_hg_act<<<dim3(2 * HH / 128, BB * VV / 128), 256, SMEMH128, sB>>>(
        ph_img, HH, ph_cain + (size_t)HH * HH, HH, ca_b_in + HH,
        ph_kv, 2 * HH, BB * VV, 2 * HH, HH);
    k_transp<<<dim3(VV / 32, 2, BB * NHH), dim3(32, 8), 0, sB>>>(
        ph_kv + HH, 2 * HH, ph_vt2, VV);
    cudaEventRecord(evKV, sB);

    k_hg_moe1s<<<dim3(II / 128, 1, BB * EE), 192, SMEMH96, sB>>>(
        ph_img, ph_e1, e_b1, p_sel_i, ph_hi, VV, KSEL_V);
    k_hg_moe2s<<<dim3(HH / 128, 1, BB * EE), 192, SMEMH96, sB>>>(
        ph_hi, ph_e2, e_b2, p_sel_i, p_acc_i, VV, KSEL_V);
    k_combine_s<<<(BB * VV * HH + 255) / 256, 256, 0, sB>>>(
        in_img, p_acc_i, p_cnt_i, out_img, BB * VV * HH);
    cudaEventRecord(evEnd, sB);

    // ======== stream A (default): text chain ========
    k_f2h_a<<<(F2HA_TOTAL / 4 + 255) / 256, 256>>>(
        sa_w_in, sa_w_out, ca_w_out, ph_sain, ph_saout, ph_caout);
    k_ln<<<BB * TT, 256>>>(in_q, lnq_g, lnq_b, ph_ln, nullptr);
    k_hg_act<<<dim3(3 * HH / 128, BB * TT / 128), 256, SMEMH128>>>(
        ph_ln, HH, ph_sain, HH, sa_b_in, ph_qkv, 3 * HH, BB * TT, 3 * HH, HH);
    k_transp<<<dim3(TT / 32, 2, BB * NHH), dim3(32, 8)>>>(
        ph_qkv + 2 * HH, 3 * HH, ph_vt, TT);
    k_flash<<<dim3(TT / 128, 1, BB * NHH), 256, FL_SMEM>>>(
        ph_qkv, 3 * HH, TT * 3 * HH, ph_qkv + HH, 3 * HH, TT * 3 * HH,
        ph_vt, ph_attn, TT, TT);
    k_hg_proj<<<dim3(HH / 128, BB * TT / 128), 256, SMEMH128>>>(
        ph_attn, HH, ph_saout, HH, sa_b_out, in_q, p_q, HH, BB * TT, HH, HH);

    k_ln<<<BB * TT, 256>>>(p_q, lnc_g, lnc_b, ph_ln, nullptr);
    cudaStreamWaitEvent(0, evKV, 0);
    k_hg_act<<<dim3(HH / 128, BB * TT / 128), 256, SMEMH128>>>(
        ph_ln, HH, ph_cain, HH, ca_b_in, ph_cq, HH, BB * TT, HH, HH);
    k_flash<<<dim3(TT / 128, 1, BB * NHH), 256, FL_SMEM>>>(
        ph_cq, HH, TT * HH, ph_kv, 2 * HH, VV * 2 * HH,
        ph_vt2, ph_attn, TT, VV);
    k_hg_proj<<<dim3(HH / 128, BB * TT / 128), 256, SMEMH128>>>(
        ph_attn, HH, ph_caout, HH, ca_b_out, p_q, p_q, HH, BB * TT, HH, HH);

    cudaStreamWaitEvent(0, evG, 0);
    k_gate_s<<<(BB * TT + 7) / 8, 256>>>(
        p_q, gate_txt_w, p_gb_txt, p_probs_t, p_cnt_t, nullptr, TT, BB * TT);
    k_topk_s<<<(BB * EE + 7) / 8, 256>>>(
        p_probs_t, p_sel_t, p_cnt_t, TT, KSEL_T);
    k_ln<<<BB * TT, 256>>>(p_q, lnf_g, lnf_b, ph_ln, p_acc_t);
    k_hg_moe1s<<<dim3(II / 128, 1, BB * EE), 192, SMEMH96>>>(
        ph_ln, ph_e1, e_b1, p_sel_t, ph_ht, TT, KSEL_T);
    k_hg_moe2s<<<dim3(HH / 128, 1, BB * EE), 192, SMEMH96>>>(
        ph_ht, ph_e2, e_b2, p_sel_t, p_acc_t, TT, KSEL_T);
    k_combine_s<<<(BB * TT * HH + 255) / 256, 256>>>(
        p_q, p_acc_t, p_cnt_t, out_q, BB * TT * HH);

    // ---- join ----
    cudaStreamWaitEvent(0, evEnd, 0);
}

// round 14
// speedup vs baseline: 2.0922x; 1.0435x over previous
#include <cuda_runtime.h>
#include <cuda_fp16.h>
#include <math.h>
#include <stdint.h>

// ---------------- problem constants ----------------
#define BB   4
#define TT   512
#define VV   576
#define LL   256
#define HH   1024
#define NHH  16
#define HDD  64
#define II   4096
#define EE   8
#define KSEL_T 80
#define KSEL_V 90
#define SELCAP 96
#define LN_EPS 1e-5f

#define BKH  64
#define ROWH 72

// ---------------- fp32 scratch ----------------
__device__ float g_q     [BB*TT*HH];
__device__ float g_acc_t [BB*TT*HH];
__device__ float g_acc_i [BB*VV*HH];
__device__ float g_ctx_img[BB*HH];
__device__ float g_ctx_txt[BB*HH];
__device__ float g_gb_img[BB*EE];
__device__ float g_gb_txt[BB*EE];
__device__ float g_probs_t[BB*TT*EE];
__device__ float g_probs_i[BB*VV*EE];
__device__ int   g_sel_t[BB*EE*SELCAP];
__device__ int   g_sel_i[BB*EE*SELCAP];
__device__ int   g_cnt_t[BB*TT];
__device__ int   g_cnt_i[BB*VV];

// ---------------- fp16 scratch ----------------
__device__ __half h_w_sain [3*HH*HH];
__device__ __half h_w_saout[HH*HH];
__device__ __half h_w_cain [3*HH*HH];
__device__ __half h_w_caout[HH*HH];
__device__ __half h_w_e1   [EE*II*HH];
__device__ __half h_w_e2   [EE*HH*II];
__device__ __half h_img    [BB*VV*HH];
__device__ __half h_ln     [BB*TT*HH];
__device__ __half h_qkv    [BB*TT*3*HH];
__device__ __half h_cq     [BB*TT*HH];
__device__ __half h_kv     [BB*VV*2*HH];
__device__ __half h_vt     [BB*NHH*HDD*VV];
__device__ __half h_vt2    [BB*NHH*HDD*VV];
__device__ __half h_attn   [BB*TT*HH];
__device__ __half h_ht     [BB*EE*SELCAP*II];
__device__ __half h_hi     [BB*EE*SELCAP*II];

// ---------------- helpers ----------------
__device__ __forceinline__ float gelu_f(float x) {
    float x3 = x * x * x;
    return 0.5f * x * (1.0f + tanhf(0.7978845608028654f * (x + 0.044715f * x3)));
}
__device__ __forceinline__ void mma_f16(float c[4],
    uint32_t a0, uint32_t a1, uint32_t a2, uint32_t a3,
    uint32_t b0, uint32_t b1)
{
    asm volatile(
        "mma.sync.aligned.m16n8k16.row.col.f32.f16.f16.f32 "
        "{%0,%1,%2,%3}, {%4,%5,%6,%7}, {%8,%9}, {%0,%1,%2,%3};"
        : "+f"(c[0]), "+f"(c[1]), "+f"(c[2]), "+f"(c[3])
        : "r"(a0), "r"(a1), "r"(a2), "r"(a3), "r"(b0), "r"(b1));
}
__device__ __forceinline__ void cpa16h(__half* dst, const __half* src, bool valid) {
    uint32_t d = (uint32_t)__cvta_generic_to_shared(dst);
    asm volatile("cp.async.cg.shared.global [%0], [%1], 16, %2;"
                 :: "r"(d), "l"(src), "r"(valid ? 16 : 0));
}

// ---------------- fp16 GEMM (unchanged core) ----------------
template<int BMT, int THREADS, bool GELU_E, bool ATOMIC, bool RES, bool OUT16, bool OUT32>
__device__ __forceinline__ void hgemm(
    __half* smem,
    const __half* __restrict__ A, int lda, const int* __restrict__ arow,
    const __half* __restrict__ Bp, int ldb,
    const float* __restrict__ bias, const float* __restrict__ res,
    float* __restrict__ C32, __half* __restrict__ C16,
    int ldc, const int* __restrict__ crow,
    int M, int N, int K)
{
    constexpr int BN  = 128;
    constexpr int NJ  = 8;
    constexpr int RP  = THREADS / 8;
    constexpr int AP  = BMT / RP;
    constexpr int BP  = (BN + RP - 1) / RP;
    constexpr int NWM = THREADS / 64;
    constexpr int STH = (BMT + BN) * ROWH;
    __half* As[3] = { smem, smem + STH, smem + 2 * STH };
    __half* Bs[3] = { smem + BMT * ROWH, smem + STH + BMT * ROWH,
                      smem + 2 * STH + BMT * ROWH };

    const int tid  = threadIdx.x;
    const int lane = tid & 31, warp = tid >> 5;
    const int wm = (warp % NWM) * 32;
    const int wn = (warp / NWM) * 64;
    const int m0 = blockIdx.y * BMT, n0 = blockIdx.x * BN;

    const int sr = tid >> 3;
    const int ch = tid & 7;
    int rowA[AP]; bool valA[AP];
#pragma unroll
    for (int p = 0; p < AP; p++) {
        int gm = m0 + sr + p * RP;
        valA[p] = gm < M;
        rowA[p] = valA[p] ? (arow ? arow[gm] : gm) : 0;
    }
    int rowB[BP]; bool valB[BP];
#pragma unroll
    for (int p = 0; p < BP; p++) {
        int r = sr + p * RP;
        int gn = n0 + r;
        valB[p] = (r < BN) && (gn < N);
        rowB[p] = valB[p] ? gn : 0;
    }

    float c[2][NJ][4];
#pragma unroll
    for (int i = 0; i < 2; i++)
#pragma unroll
        for (int j = 0; j < NJ; j++)
#pragma unroll
            for (int q = 0; q < 4; q++) c[i][j][q] = 0.0f;

    const int KT = K / BKH;

    auto load_tile = [&](int st, int k0) {
        __half* Ad = As[st];
        __half* Bd = Bs[st];
#pragma unroll
        for (int p = 0; p < AP; p++)
            cpa16h(Ad + (sr + p * RP) * ROWH + ch * 8,
                   A + (size_t)rowA[p] * lda + k0 + ch * 8, valA[p]);
#pragma unroll
        for (int p = 0; p < BP; p++) {
            int r = sr + p * RP;
            if (r < BN)
                cpa16h(Bd + r * ROWH + ch * 8,
                       Bp + (size_t)rowB[p] * ldb + k0 + ch * 8, valB[p]);
        }
    };

    load_tile(0, 0);
    asm volatile("cp.async.commit_group;");
    if (KT > 1) load_tile(1, BKH);
    asm volatile("cp.async.commit_group;");

    for (int kt = 0; kt < KT; kt++) {
        asm volatile("cp.async.wait_group 1;");
        __syncthreads();
        const int st = kt % 3;
        if (kt + 2 < KT) load_tile((kt + 2) % 3, (kt + 2) * BKH);
        asm volatile("cp.async.commit_group;");

        const __half* Ab = As[st];
        const __half* Bb = Bs[st];
#pragma unroll
        for (int ks = 0; ks < 4; ks++) {
            const int cc = ks * 16 + 2 * (lane & 3);
            uint32_t a[2][4];
#pragma unroll
            for (int i = 0; i < 2; i++) {
                const int r = wm + i * 16 + (lane >> 2);
                a[i][0] = *(const uint32_t*)&Ab[r * ROWH + cc];
                a[i][1] = *(const uint32_t*)&Ab[(r + 8) * ROWH + cc];
                a[i][2] = *(const uint32_t*)&Ab[r * ROWH + cc + 8];
                a[i][3] = *(const uint32_t*)&Ab[(r + 8) * ROWH + cc + 8];
            }
            uint32_t b[NJ][2];
#pragma unroll
            for (int j = 0; j < NJ; j++) {
                const int bc = wn + j * 8 + (lane >> 2);
                b[j][0] = *(const uint32_t*)&Bb[bc * ROWH + cc];
                b[j][1] = *(const uint32_t*)&Bb[bc * ROWH + cc + 8];
            }
#pragma unroll
            for (int i = 0; i < 2; i++)
#pragma unroll
                for (int j = 0; j < NJ; j++)
                    mma_f16(c[i][j], a[i][0], a[i][1], a[i][2], a[i][3],
                            b[j][0], b[j][1]);
        }
    }

#pragma unroll
    for (int i = 0; i < 2; i++) {
        int rm = m0 + wm + i * 16 + (lane >> 2);
#pragma unroll
        for (int j = 0; j < NJ; j++) {
            int cn = n0 + wn + j * 8 + 2 * (lane & 3);
#pragma unroll
            for (int rr = 0; rr < 2; rr++) {
                int gm = rm + rr * 8;
                if (gm >= M) continue;
                int orow = crow ? crow[gm] : gm;
#pragma unroll
                for (int qq = 0; qq < 2; qq++) {
                    int gn = cn + qq;
                    if (gn >= N) continue;
                    float v = c[i][j][rr * 2 + qq];
                    if (bias) v += bias[gn];
                    if (RES)  v += res[(size_t)gm * ldc + gn];
                    if (GELU_E) v = gelu_f(v);
                    if (ATOMIC) {
                        atomicAdd(&C32[(size_t)orow * ldc + gn], v);
                    } else {
                        if (OUT32) C32[(size_t)orow * ldc + gn] = v;
                        if (OUT16) C16[(size_t)orow * ldc + gn] = __float2half_rn(v);
                    }
                }
            }
        }
    }
}

__global__ __launch_bounds__(256, 2) void k_hg_act(
    const __half* A, int lda, const __half* W, int ldw,
    const float* bias, __half* C16, int ldc, int M, int N, int K)
{
    extern __shared__ __half smh[];
    hgemm<128, 256, false, false, false, true, false>(smh, A, lda, nullptr, W, ldw,
        bias, nullptr, nullptr, C16, ldc, nullptr, M, N, K);
}

__global__ __launch_bounds__(256, 2) void k_hg_proj(
    const __half* A, int lda, const __half* W, int ldw,
    const float* bias, const float* res, float* C32, int ldc, int M, int N, int K)
{
    extern __shared__ __half smh[];
    hgemm<128, 256, false, false, true, false, true>(smh, A, lda, nullptr, W, ldw,
        bias, res, C32, nullptr, ldc, nullptr, M, N, K);
}

__global__ __launch_bounds__(192, 2) void k_hg_moe1s(
    const __half* X0, const __half* w1, const float* b1,
    const int* sel0, __half* H0, int S, int ksel)
{
    extern __shared__ __half smh[];
    int g = blockIdx.z;
    int b = g / EE, e = g % EE;
    const __half* X = X0 + (size_t)b * S * HH;
    const int* sel = sel0 + g * SELCAP;
    __half* H = H0 + (size_t)g * SELCAP * II;
    hgemm<96, 192, true, false, false, true, false>(smh, X, HH, sel,
        w1 + (size_t)e * II * HH, HH, b1 + (size_t)e * II, nullptr,
        nullptr, H, II, nullptr, ksel, II, HH);
}

__global__ __launch_bounds__(192, 2) void k_hg_moe2s(
    const __half* H0, const __half* w2, const float* b2,
    const int* sel0, float* Acc0, int S, int ksel)
{
    extern __shared__ __half smh[];
    int g = blockIdx.z;
    int b = g / EE, e = g % EE;
    const __half* H = H0 + (size_t)g * SELCAP * II;
    const int* sel = sel0 + g * SELCAP;
    float* Acc = Acc0 + (size_t)b * S * HH;
    hgemm<96, 192, false, true, false, false, false>(smh, H, II, nullptr,
        w2 + (size_t)e * HH * II, II, b2 + (size_t)e * HH, nullptr,
        Acc, nullptr, HH, sel, ksel, HH, II);
}

// ---------------- fused flash attention (2 CTAs/SM) ----------------
#define FL_SMEM ((128 * ROWH + 4 * 64 * ROWH) * 2)

__global__ __launch_bounds__(256, 2) void k_flash(
    const __half* __restrict__ Qp, int qld, int qbs,
    const __half* __restrict__ Kp, int kld, int kbs,
    const __half* __restrict__ Vt,
    __half* __restrict__ O, int Tq, int Skv)
{
    extern __shared__ __half sm[];
    __half* Qs = sm;
    __half* Ks[2] = { sm + 128 * ROWH, sm + 128 * ROWH + 64 * ROWH };
    __half* Vs[2] = { sm + 128 * ROWH + 2 * 64 * ROWH,
                      sm + 128 * ROWH + 3 * 64 * ROWH };

    const int z = blockIdx.z, b = z / NHH, h = z % NHH;
    const __half* Qb = Qp + (size_t)b * qbs + h * HDD;
    const __half* Kb = Kp + (size_t)b * kbs + h * HDD;
    const __half* Vb = Vt + (size_t)z * HDD * Skv;
    __half* Ob = O + (size_t)b * Tq * HH + h * HDD;

    const int tid = threadIdx.x, lane = tid & 31, warp = tid >> 5;
    const int m0 = blockIdx.x * 128;
    const int sr = tid >> 3, ch = tid & 7;

    auto loadKV = [&](int buf, int s0) {
#pragma unroll
        for (int p = 0; p < 2; p++)
            cpa16h(Ks[buf] + (sr + p * 32) * ROWH + ch * 8,
                   Kb + (size_t)(s0 + sr + p * 32) * kld + ch * 8, true);
#pragma unroll
        for (int p = 0; p < 2; p++)
            cpa16h(Vs[buf] + (sr + p * 32) * ROWH + ch * 8,
                   Vb + (size_t)(sr + p * 32) * Skv + s0 + ch * 8, true);
    };

#pragma unroll
    for (int p = 0; p < 4; p++)
        cpa16h(Qs + (sr + p * 32) * ROWH + ch * 8,
               Qb + (size_t)(m0 + sr + p * 32) * qld + ch * 8, true);
    loadKV(0, 0);
    asm volatile("cp.async.commit_group;");

    uint32_t qa[4][4];
    float o[8][4];
#pragma unroll
    for (int j = 0; j < 8; j++)
#pragma unroll
        for (int q = 0; q < 4; q++) o[j][q] = 0.0f;
    float m0v = -1.0e30f, m1v = -1.0e30f, l0 = 0.0f, l1 = 0.0f;

    const int nchunks = Skv / 64;
    for (int s = 0; s < nchunks; s++) {
        asm volatile("cp.async.wait_group 0;");
        __syncthreads();
        const int buf = s & 1;
        if (s == 0) {
            const int r = warp * 16 + (lane >> 2);
#pragma unroll
            for (int ks = 0; ks < 4; ks++) {
                const int cc = ks * 16 + 2 * (lane & 3);
                qa[ks][0] = *(const uint32_t*)&Qs[r * ROWH + cc];
                qa[ks][1] = *(const uint32_t*)&Qs[(r + 8) * ROWH + cc];
                qa[ks][2] = *(const uint32_t*)&Qs[r * ROWH + cc + 8];
                qa[ks][3] = *(const uint32_t*)&Qs[(r + 8) * ROWH + cc + 8];
            }
        }
        if (s + 1 < nchunks) loadKV(buf ^ 1, (s + 1) * 64);
        asm volatile("cp.async.commit_group;");

        float sc[8][4];
#pragma unroll
        for (int j = 0; j < 8; j++)
#pragma unroll
            for (int q = 0; q < 4; q++) sc[j][q] = 0.0f;
        const __half* Kc = Ks[buf];
#pragma unroll
        for (int ks = 0; ks < 4; ks++) {
            const int cc = ks * 16 + 2 * (lane & 3);
#pragma unroll
            for (int j = 0; j < 8; j++) {
                const int bc = j * 8 + (lane >> 2);
                uint32_t b0 = *(const uint32_t*)&Kc[bc * ROWH + cc];
                uint32_t b1 = *(const uint32_t*)&Kc[bc * ROWH + cc + 8];
                mma_f16(sc[j], qa[ks][0], qa[ks][1], qa[ks][2], qa[ks][3], b0, b1);
            }
        }
        float rm0 = -1.0e30f, rm1 = -1.0e30f;
#pragma unroll
        for (int j = 0; j < 8; j++) {
#pragma unroll
            for (int q = 0; q < 4; q++) sc[j][q] *= 0.125f;
            rm0 = fmaxf(rm0, fmaxf(sc[j][0], sc[j][1]));
            rm1 = fmaxf(rm1, fmaxf(sc[j][2], sc[j][3]));
        }
#pragma unroll
        for (int off = 1; off <= 2; off <<= 1) {
            rm0 = fmaxf(rm0, __shfl_xor_sync(0xffffffffu, rm0, off));
            rm1 = fmaxf(rm1, __shfl_xor_sync(0xffffffffu, rm1, off));
        }
        float nm0 = fmaxf(m0v, rm0), nm1 = fmaxf(m1v, rm1);
        float cr0 = __expf(m0v - nm0), cr1 = __expf(m1v - nm1);
        m0v = nm0; m1v = nm1;
        float rs0 = 0.0f, rs1 = 0.0f;
#pragma unroll
        for (int j = 0; j < 8; j++) {
            sc[j][0] = __expf(sc[j][0] - nm0);
            sc[j][1] = __expf(sc[j][1] - nm0);
            sc[j][2] = __expf(sc[j][2] - nm1);
            sc[j][3] = __expf(sc[j][3] - nm1);
            rs0 += sc[j][0] + sc[j][1];
            rs1 += sc[j][2] + sc[j][3];
        }
#pragma unroll
        for (int off = 1; off <= 2; off <<= 1) {
            rs0 += __shfl_xor_sync(0xffffffffu, rs0, off);
            rs1 += __shfl_xor_sync(0xffffffffu, rs1, off);
        }
        l0 = l0 * cr0 + rs0;
        l1 = l1 * cr1 + rs1;
#pragma unroll
        for (int j = 0; j < 8; j++) {
            o[j][0] *= cr0; o[j][1] *= cr0;
            o[j][2] *= cr1; o[j][3] *= cr1;
        }
        const __half* Vc = Vs[buf];
#pragma unroll
        for (int ks = 0; ks < 4; ks++) {
            uint32_t a0, a1, a2, a3;
            {
                __half2 t;
                t = __floats2half2_rn(sc[2 * ks][0], sc[2 * ks][1]);     a0 = *(uint32_t*)&t;
                t = __floats2half2_rn(sc[2 * ks][2], sc[2 * ks][3]);     a1 = *(uint32_t*)&t;
                t = __floats2half2_rn(sc[2 * ks + 1][0], sc[2 * ks + 1][1]); a2 = *(uint32_t*)&t;
                t = __floats2half2_rn(sc[2 * ks + 1][2], sc[2 * ks + 1][3]); a3 = *(uint32_t*)&t;
            }
            const int cc = ks * 16 + 2 * (lane & 3);
#pragma unroll
            for (int jd = 0; jd < 8; jd++) {
                const int bc = jd * 8 + (lane >> 2);
                uint32_t b0 = *(const uint32_t*)&Vc[bc * ROWH + cc];
                uint32_t b1 = *(const uint32_t*)&Vc[bc * ROWH + cc + 8];
                mma_f16(o[jd], a0, a1, a2, a3, b0, b1);
            }
        }
    }

    const float iv0 = 1.0f / l0, iv1 = 1.0f / l1;
    const int r0 = m0 + warp * 16 + (lane >> 2);
#pragma unroll
    for (int jd = 0; jd < 8; jd++) {
        const int col = jd * 8 + 2 * (lane & 3);
        Ob[(size_t)r0 * HH + col]       = __float2half_rn(o[jd][0] * iv0);
        Ob[(size_t)r0 * HH + col + 1]   = __float2half_rn(o[jd][1] * iv0);
        Ob[(size_t)(r0 + 8) * HH + col]     = __float2half_rn(o[jd][2] * iv1);
        Ob[(size_t)(r0 + 8) * HH + col + 1] = __float2half_rn(o[jd][3] * iv1);
    }
}

// ---------------- split fp32->fp16 conversions ----------------
#define A0 (3*HH*HH)
#define A1 (HH*HH)
#define A2 (HH*HH)
#define F2HA_TOTAL (A0+A1+A2)
__global__ void k_f2h_a(const float* s0, const float* s1, const float* s2,
                        __half* d0, __half* d1, __half* d2)
{
    int i = (blockIdx.x * 256 + threadIdx.x) * 4;
    if (i >= F2HA_TOTAL) return;
    const float* src; __half* dst; int off;
    if      (i < A0)      { src = s0; dst = d0; off = i; }
    else if (i < A0+A1)   { src = s1; dst = d1; off = i - A0; }
    else                  { src = s2; dst = d2; off = i - A0 - A1; }
    float4 v = *(const float4*)(src + off);
    *(__half2*)(dst + off)     = __floats2half2_rn(v.x, v.y);
    *(__half2*)(dst + off + 2) = __floats2half2_rn(v.z, v.w);
}

#define B0 (3*HH*HH)
#define B1 (BB*VV*HH)
#define B2 (EE*II*HH)
#define B3 (EE*HH*II)
#define F2HB_TOTAL (B0+B1+B2+B3)
__global__ void k_f2h_b(const float* s0, const float* s1, const float* s2,
                        const float* s3,
                        __half* d0, __half* d1, __half* d2, __half* d3)
{
    int i = (blockIdx.x * 256 + threadIdx.x) * 4;
    if (i >= F2HB_TOTAL) return;
    const float* src; __half* dst; int off;
    if      (i < B0)          { src = s0; dst = d0; off = i; }
    else if (i < B0+B1)       { src = s1; dst = d1; off = i - B0; }
    else if (i < B0+B1+B2)    { src = s2; dst = d2; off = i - B0 - B1; }
    else                      { src = s3; dst = d3; off = i - B0 - B1 - B2; }
    float4 v = *(const float4*)(src + off);
    *(__half2*)(dst + off)     = __floats2half2_rn(v.x, v.y);
    *(__half2*)(dst + off + 2) = __floats2half2_rn(v.z, v.w);
}

// ---------------- V transpose (fp16) ----------------
__global__ void k_transp(const __half* __restrict__ X, int ldx,
                         __half* __restrict__ Y, int S)
{
    __shared__ float t[32][33];
    int z = blockIdx.z; int b = z >> 4, h = z & 15;
    int t0 = blockIdx.x * 32, d0 = blockIdx.y * 32;
    const __half* src = X + ((size_t)b * S) * ldx + h * HDD;
#pragma unroll
    for (int k2 = 0; k2 < 4; k2++) {
        int tt = t0 + threadIdx.y + k2 * 8;
        t[threadIdx.y + k2 * 8][threadIdx.x] =
            __half2float(src[(size_t)tt * ldx + d0 + threadIdx.x]);
    }
    __syncthreads();
    __half* dst = Y + ((size_t)z * HDD) * S;
#pragma unroll
    for (int k2 = 0; k2 < 4; k2++) {
        int d = d0 + threadIdx.y + k2 * 8;
        dst[(size_t)d * S + t0 + threadIdx.x] =
            __float2half_rn(t[threadIdx.x][threadIdx.y + k2 * 8]);
    }
}

// ---------------- layernorm ----------------
__global__ void k_ln(const float* X, const float* gg, const float* bb,
                     __half* Y, float* accz)
{
    int r = blockIdx.x;
    const float* x = X + (size_t)r * HH;
    __half* y = Y + (size_t)r * HH;
    int tid = threadIdx.x;
    if (accz) {
        float* az = accz + (size_t)r * HH;
        for (int i = tid; i < HH; i += 256) az[i] = 0.0f;
    }
    float s = 0.0f, s2 = 0.0f;
    for (int i = tid; i < HH; i += 256) { float v = x[i]; s += v; s2 += v * v; }
    __shared__ float r1[256], r2[256];
    r1[tid] = s; r2[tid] = s2; __syncthreads();
    for (int st = 128; st; st >>= 1) {
        if (tid < st) { r1[tid] += r1[tid + st]; r2[tid] += r2[tid + st]; }
        __syncthreads();
    }
    float mean = r1[0] * (1.0f / HH);
    float var  = r2[0] * (1.0f / HH) - mean * mean;
    float rstd = rsqrtf(var + LN_EPS);
    for (int i = tid; i < HH; i += 256)
        y[i] = __float2half_rn((x[i] - mean) * rstd * gg[i] + bb[i]);
}

// ---------------- means (MLP=4) + ctxbias ----------------
__global__ void k_mean2(const float* Xi, const float* Xt,
                        float* ctx_i, float* ctx_t)
{
    int b = blockIdx.y;
    int c = blockIdx.x * 256 + threadIdx.x;
    if (blockIdx.z == 0) {
        const float* base = Xi + (size_t)b * VV * HH + c;
        float s0 = 0.0f, s1 = 0.0f, s2 = 0.0f, s3 = 0.0f;
        for (int j = 0; j < VV; j += 4) {
            s0 += base[(size_t)j * HH];
            s1 += base[(size_t)(j + 1) * HH];
            s2 += base[(size_t)(j + 2) * HH];
            s3 += base[(size_t)(j + 3) * HH];
        }
        ctx_i[b * HH + c] = (s0 + s1 + s2 + s3) / (float)VV;
    } else {
        const float* base = Xt + (size_t)b * LL * HH + c;
        float s0 = 0.0f, s1 = 0.0f, s2 = 0.0f, s3 = 0.0f;
        for (int j = 0; j < LL; j += 4) {
            s0 += base[(size_t)j * HH];
            s1 += base[(size_t)(j + 1) * HH];
            s2 += base[(size_t)(j + 2) * HH];
            s3 += base[(size_t)(j + 3) * HH];
        }
        ctx_t[b * HH + c] = (s0 + s1 + s2 + s3) / (float)LL;
    }
}

__global__ void k_ctxbias2(const float* ctx_t, const float* ctx_i,
                           const float* gw_i, const float* gb_i,
                           const float* gw_t, const float* gb_t,
                           float* out_i, float* out_t)
{
    int w = blockIdx.x * 8 + (threadIdx.x >> 5);
    int lane = threadIdx.x & 31;
    if (w >= 2 * BB * EE) return;
    bool first = w < BB * EE;
    int g = first ? w : w - BB * EE;
    int b = g / EE, e = g % EE;
    const float* ctx = first ? ctx_t : ctx_i;
    const float* gw  = first ? gw_i : gw_t;
    const float* gb  = first ? gb_i : gb_t;
    float* outp      = first ? out_i : out_t;
    float s = 0.0f;
    for (int c = lane; c < HH; c += 32)
        s += ctx[b * HH + c] * gw[(size_t)e * 2 * HH + HH + c];
#pragma unroll
    for (int o = 16; o; o >>= 1) s += __shfl_xor_sync(0xffffffffu, s, o);
    if (lane == 0) outp[g] = s + gb[e];
}

// ---------------- warp-per-token gate ----------------
__global__ __launch_bounds__(256) void k_gate_s(
    const float* __restrict__ X,
    const float* __restrict__ gw, const float* __restrict__ cb,
    float* __restrict__ probs, int* __restrict__ cnt,
    float* __restrict__ accz, int S, int ntok)
{
    int w = blockIdx.x * 8 + (threadIdx.x >> 5);
    int lane = threadIdx.x & 31;
    if (w >= ntok) return;
    int t = w;
    int b = t / S;
    const float* x = X + (size_t)t * HH;
    if (lane == 0) cnt[t] = 0;
    if (accz) {
        float* az = accz + (size_t)t * HH;
        for (int i = lane; i < HH; i += 32) az[i] = 0.0f;
    }
    float acc[EE];
#pragma unroll
    for (int e = 0; e < EE; e++) acc[e] = 0.0f;
    for (int c = lane; c < HH; c += 32) {
        float xv = x[c];
#pragma unroll
        for (int e = 0; e < EE; e++) acc[e] += xv * gw[(size_t)e * 2 * HH + c];
    }
#pragma unroll
    for (int e = 0; e < EE; e++) {
#pragma unroll
        for (int o = 16; o; o >>= 1)
            acc[e] += __shfl_xor_sync(0xffffffffu, acc[e], o);
    }
    if (lane == 0) {
        float lg[EE];
#pragma unroll
        for (int e = 0; e < EE; e++) lg[e] = acc[e] + cb[b * EE + e];
        float mx = lg[0];
#pragma unroll
        for (int e = 1; e < EE; e++) mx = fmaxf(mx, lg[e]);
        float sum = 0.0f, ex[EE];
#pragma unroll
        for (int e = 0; e < EE; e++) { ex[e] = expf(lg[e] - mx); sum += ex[e]; }
        float inv = 1.0f / sum;
#pragma unroll
        for (int e = 0; e < EE; e++) probs[(size_t)t * EE + e] = ex[e] * inv;
    }
}

// ---------------- rank-select top-k: block per group, O(S^2) parallel ------
__global__ __launch_bounds__(256) void k_topk_r(
    const float* __restrict__ probs, int* __restrict__ sel0,
    int* __restrict__ cnt0, int S, int ksel)
{
    __shared__ float v[VV];
    int g = blockIdx.x;
    int b = g / EE, e = g % EE;
    int tid = threadIdx.x;
    for (int i = tid; i < S; i += 256)
        v[i] = probs[(size_t)(b * S + i) * EE + e];
    __syncthreads();
    int* sel = sel0 + g * SELCAP;
    int* cnt = cnt0 + b * S;
    for (int i = tid; i < S; i += 256) {
        float vi = v[i];
        int rank = 0;
        for (int j = 0; j < S; j += 4) {
            rank += (v[j]     > vi) || (v[j]     == vi && j     < i);
            rank += (v[j + 1] > vi) || (v[j + 1] == vi && j + 1 < i);
            rank += (v[j + 2] > vi) || (v[j + 2] == vi && j + 2 < i);
            rank += (v[j + 3] > vi) || (v[j + 3] == vi && j + 3 < i);
        }
        if (rank < ksel) {
            sel[rank] = i;
            atomicAdd(&cnt[i], 1);
        }
    }
}

// ---------------- per-stream combine ----------------
__global__ void k_combine_s(
    const float* base, const float* acc, const int* cnt, float* outp, int n)
{
    int i = blockIdx.x * 256 + threadIdx.x;
    if (i < n) {
        int tok = i / HH;
        outp[i] = base[i] + acc[i] / fmaxf((float)cnt[tok], 1.0f);
    }
}

// ---------------- launch ----------------
#define SMEMH128 (3 * (128 + 128) * ROWH * 2)
#define SMEMH96  (3 * (96 + 128) * ROWH * 2)

extern "C" void kernel_launch(void* const* d_in, const int* in_sizes, int n_in,
                              void* d_out, int out_size)
{
    (void)in_sizes; (void)n_in; (void)out_size;
    const float* in_q      = (const float*)d_in[0];
    const float* in_img    = (const float*)d_in[1];
    const float* in_txt    = (const float*)d_in[2];
    const float* sa_w_in   = (const float*)d_in[3];
    const float* sa_b_in   = (const float*)d_in[4];
    const float* sa_w_out  = (const float*)d_in[5];
    const float* sa_b_out  = (const float*)d_in[6];
    const float* ca_w_in   = (const float*)d_in[7];
    const float* ca_b_in   = (const float*)d_in[8];
    const float* ca_w_out  = (const float*)d_in[9];
    const float* ca_b_out  = (const float*)d_in[10];
    const float* gate_img_w= (const float*)d_in[11];
    const float* gate_img_b= (const float*)d_in[12];
    const float* gate_txt_w= (const float*)d_in[13];
    const float* gate_txt_b= (const float*)d_in[14];
    const float* e_w1      = (const float*)d_in[15];
    const float* e_b1      = (const float*)d_in[16];
    const float* e_w2      = (const float*)d_in[17];
    const float* e_b2      = (const float*)d_in[18];
    const float* lnq_g     = (const float*)d_in[19];
    const float* lnq_b     = (const float*)d_in[20];
    const float* lnc_g     = (const float*)d_in[21];
    const float* lnc_b     = (const float*)d_in[22];
    const float* lnf_g     = (const float*)d_in[23];
    const float* lnf_b     = (const float*)d_in[24];
    float* out_q   = (float*)d_out;
    float* out_img = out_q + (size_t)BB * TT * HH;

    float *p_q, *p_acc_t, *p_acc_i;
    float *p_ctx_img, *p_ctx_txt, *p_gb_img, *p_gb_txt, *p_probs_t, *p_probs_i;
    int *p_sel_t, *p_sel_i, *p_cnt_t, *p_cnt_i;
    __half *ph_sain, *ph_saout, *ph_cain, *ph_caout, *ph_e1, *ph_e2;
    __half *ph_img, *ph_ln, *ph_qkv, *ph_cq, *ph_kv, *ph_vt, *ph_vt2, *ph_attn;
    __half *ph_ht, *ph_hi;
    cudaGetSymbolAddress((void**)&p_q, g_q);
    cudaGetSymbolAddress((void**)&p_acc_t, g_acc_t);
    cudaGetSymbolAddress((void**)&p_acc_i, g_acc_i);
    cudaGetSymbolAddress((void**)&p_ctx_img, g_ctx_img);
    cudaGetSymbolAddress((void**)&p_ctx_txt, g_ctx_txt);
    cudaGetSymbolAddress((void**)&p_gb_img, g_gb_img);
    cudaGetSymbolAddress((void**)&p_gb_txt, g_gb_txt);
    cudaGetSymbolAddress((void**)&p_probs_t, g_probs_t);
    cudaGetSymbolAddress((void**)&p_probs_i, g_probs_i);
    cudaGetSymbolAddress((void**)&p_sel_t, g_sel_t);
    cudaGetSymbolAddress((void**)&p_sel_i, g_sel_i);
    cudaGetSymbolAddress((void**)&p_cnt_t, g_cnt_t);
    cudaGetSymbolAddress((void**)&p_cnt_i, g_cnt_i);
    cudaGetSymbolAddress((void**)&ph_sain, h_w_sain);
    cudaGetSymbolAddress((void**)&ph_saout, h_w_saout);
    cudaGetSymbolAddress((void**)&ph_cain, h_w_cain);
    cudaGetSymbolAddress((void**)&ph_caout, h_w_caout);
    cudaGetSymbolAddress((void**)&ph_e1, h_w_e1);
    cudaGetSymbolAddress((void**)&ph_e2, h_w_e2);
    cudaGetSymbolAddress((void**)&ph_img, h_img);
    cudaGetSymbolAddress((void**)&ph_ln, h_ln);
    cudaGetSymbolAddress((void**)&ph_qkv, h_qkv);
    cudaGetSymbolAddress((void**)&ph_cq, h_cq);
    cudaGetSymbolAddress((void**)&ph_kv, h_kv);
    cudaGetSymbolAddress((void**)&ph_vt, h_vt);
    cudaGetSymbolAddress((void**)&ph_vt2, h_vt2);
    cudaGetSymbolAddress((void**)&ph_attn, h_attn);
    cudaGetSymbolAddress((void**)&ph_ht, h_ht);
    cudaGetSymbolAddress((void**)&ph_hi, h_hi);

    cudaFuncSetAttribute(k_hg_act,   cudaFuncAttributeMaxDynamicSharedMemorySize, SMEMH128);
    cudaFuncSetAttribute(k_hg_proj,  cudaFuncAttributeMaxDynamicSharedMemorySize, SMEMH128);
    cudaFuncSetAttribute(k_hg_moe1s, cudaFuncAttributeMaxDynamicSharedMemorySize, SMEMH96);
    cudaFuncSetAttribute(k_hg_moe2s, cudaFuncAttributeMaxDynamicSharedMemorySize, SMEMH96);
    cudaFuncSetAttribute(k_flash,    cudaFuncAttributeMaxDynamicSharedMemorySize, FL_SMEM);

    // ---- fork stream B off the (captured) default stream ----
    cudaStream_t sB;
    cudaStreamCreateWithFlags(&sB, cudaStreamNonBlocking);
    cudaEvent_t ev0, evKV, evG, evEnd;
    cudaEventCreateWithFlags(&ev0,   cudaEventDisableTiming);
    cudaEventCreateWithFlags(&evKV,  cudaEventDisableTiming);
    cudaEventCreateWithFlags(&evG,   cudaEventDisableTiming);
    cudaEventCreateWithFlags(&evEnd, cudaEventDisableTiming);

    cudaEventRecord(ev0, 0);
    cudaStreamWaitEvent(sB, ev0, 0);

    // ======== stream B: image branch ========
    k_mean2<<<dim3(HH / 256, BB, 2), 256, 0, sB>>>(in_img, in_txt,
                                                   p_ctx_img, p_ctx_txt);
    k_ctxbias2<<<(2 * BB * EE + 7) / 8, 256, 0, sB>>>(
        p_ctx_txt, p_ctx_img, gate_img_w, gate_img_b, gate_txt_w, gate_txt_b,
        p_gb_img, p_gb_txt);
    cudaEventRecord(evG, sB);

    k_gate_s<<<(BB * VV + 7) / 8, 256, 0, sB>>>(
        in_img, gate_img_w, p_gb_img, p_probs_i, p_cnt_i, p_acc_i, VV, BB * VV);
    k_topk_r<<<BB * EE, 256, 0, sB>>>(p_probs_i, p_sel_i, p_cnt_i, VV, KSEL_V);

    k_f2h_b<<<(F2HB_TOTAL / 4 + 255) / 256, 256, 0, sB>>>(
        ca_w_in, in_img, e_w1, e_w2, ph_cain, ph_img, ph_e1, ph_e2);
    k_hg_act<<<dim3(2 * HH / 128, BB * VV / 128), 256, SMEMH128, sB>>>(
        ph_img, HH, ph_cain + (size_t)HH * HH, HH, ca_b_in + HH,
        ph_kv, 2 * HH, BB * VV, 2 * HH, HH);
    k_transp<<<dim3(VV / 32, 2, BB * NHH), dim3(32, 8), 0, sB>>>(
        ph_kv + HH, 2 * HH, ph_vt2, VV);
    cudaEventRecord(evKV, sB);

    k_hg_moe1s<<<dim3(II / 128, 1, BB * EE), 192, SMEMH96, sB>>>(
        ph_img, ph_e1, e_b1, p_sel_i, ph_hi, VV, KSEL_V);
    k_hg_moe2s<<<dim3(HH / 128, 1, BB * EE), 192, SMEMH96, sB>>>(
        ph_hi, ph_e2, e_b2, p_sel_i, p_acc_i, VV, KSEL_V);
    k_combine_s<<<(BB * VV * HH + 255) / 256, 256, 0, sB>>>(
        in_img, p_acc_i, p_cnt_i, out_img, BB * VV * HH);
    cudaEventRecord(evEnd, sB);

    // ======== stream A (default): text chain ========
    k_f2h_a<<<(F2HA_TOTAL / 4 + 255) / 256, 256>>>(
        sa_w_in, sa_w_out, ca_w_out, ph_sain, ph_saout, ph_caout);
    k_ln<<<BB * TT, 256>>>(in_q, lnq_g, lnq_b, ph_ln, nullptr);
    k_hg_act<<<dim3(3 * HH / 128, BB * TT / 128), 256, SMEMH128>>>(
        ph_ln, HH, ph_sain, HH, sa_b_in, ph_qkv, 3 * HH, BB * TT, 3 * HH, HH);
    k_transp<<<dim3(TT / 32, 2, BB * NHH), dim3(32, 8)>>>(
        ph_qkv + 2 * HH, 3 * HH, ph_vt, TT);
    k_flash<<<dim3(TT / 128, 1, BB * NHH), 256, FL_SMEM>>>(
        ph_qkv, 3 * HH, TT * 3 * HH, ph_qkv + HH, 3 * HH, TT * 3 * HH,
        ph_vt, ph_attn, TT, TT);
    k_hg_proj<<<dim3(HH / 128, BB * TT / 128), 256, SMEMH128>>>(
        ph_attn, HH, ph_saout, HH, sa_b_out, in_q, p_q, HH, BB * TT, HH, HH);

    k_ln<<<BB * TT, 256>>>(p_q, lnc_g, lnc_b, ph_ln, nullptr);
    cudaStreamWaitEvent(0, evKV, 0);
    k_hg_act<<<dim3(HH / 128, BB * TT / 128), 256, SMEMH128>>>(
        ph_ln, HH, ph_cain, HH, ca_b_in, ph_cq, HH, BB * TT, HH, HH);
    k_flash<<<dim3(TT / 128, 1, BB * NHH), 256, FL_SMEM>>>(
        ph_cq, HH, TT * HH, ph_kv, 2 * HH, VV * 2 * HH,
        ph_vt2, ph_attn, TT, VV);
    k_hg_proj<<<dim3(HH / 128, BB * TT / 128), 256, SMEMH128>>>(
        ph_attn, HH, ph_caout, HH, ca_b_out, p_q, p_q, HH, BB * TT, HH, HH);

    cudaStreamWaitEvent(0, evG, 0);
    k_gate_s<<<(BB * TT + 7) / 8, 256>>>(
        p_q, gate_txt_w, p_gb_txt, p_probs_t, p_cnt_t, nullptr, TT, BB * TT);
    k_topk_r<<<BB * EE, 256>>>(p_probs_t, p_sel_t, p_cnt_t, TT, KSEL_T);
    k_ln<<<BB * TT, 256>>>(p_q, lnf_g, lnf_b, ph_ln, p_acc_t);
    k_hg_moe1s<<<dim3(II / 128, 1, BB * EE), 192, SMEMH96>>>(
        ph_ln, ph_e1, e_b1, p_sel_t, ph_ht, TT, KSEL_T);
    k_hg_moe2s<<<dim3(HH / 128, 1, BB * EE), 192, SMEMH96>>>(
        ph_ht, ph_e2, e_b2, p_sel_t, p_acc_t, TT, KSEL_T);
    k_combine_s<<<(BB * TT * HH + 255) / 256, 256>>>(
        p_q, p_acc_t, p_cnt_t, out_q, BB * TT * HH);

    // ---- join ----
    cudaStreamWaitEvent(0, evEnd, 0);
}